// round 1
// baseline (speedup 1.0000x reference)
#include <cuda_runtime.h>
#include <cuda_bf16.h>
#include <math.h>

// Problem constants
#define BB      4
#define TT      2048
#define DM      1024
#define NH      16
#define DH      64
#define BT      (BB * TT)        // 8192 rows
#define NQKV    (3 * DM)         // 3072

// Scratch (alloc-free rule: __device__ globals)
__device__ float g_qkv[(size_t)BT * NQKV];   // 100.7 MB : [b*T + t][3*1024] layout (q|k|v, each h*64+d)
__device__ float g_ao [(size_t)BT * DM];     //  33.6 MB : attention output [b*T + t][h*64+d]

// ---------------------------------------------------------------------------
// SGEMM: C[M,N] = A[M,K] * B[K,N], all row-major, M%128==0, N%128==0, K%8==0
// BM=BN=128, BK=8, TM=TN=8, 256 threads
// ---------------------------------------------------------------------------
__global__ __launch_bounds__(256) void sgemm128(
    const float* __restrict__ A, const float* __restrict__ Bm,
    float* __restrict__ C, int M, int N, int K)
{
    constexpr int BM = 128, BN = 128, BK = 8, TM = 8, TN = 8;
    __shared__ float As[BK][BM];
    __shared__ float Bs[BK][BN];

    const int bx = blockIdx.x, by = blockIdx.y;
    const int tid = threadIdx.x;

    const int tx = tid % (BN / TN);   // 0..15
    const int ty = tid / (BN / TN);   // 0..15

    // Load maps
    const int a_row  = tid >> 1;            // 0..127
    const int a_col  = (tid & 1) * 4;       // 0 or 4
    const int b_row  = tid >> 5;            // 0..7
    const int b_col  = (tid & 31) * 4;      // 0..124

    const float* Ab = A + (size_t)(by * BM) * K;
    const float* Bb = Bm + bx * BN;

    float acc[TM][TN];
    #pragma unroll
    for (int i = 0; i < TM; i++)
        #pragma unroll
        for (int j = 0; j < TN; j++) acc[i][j] = 0.f;

    for (int k0 = 0; k0 < K; k0 += BK) {
        float4 av = *(const float4*)(Ab + (size_t)a_row * K + k0 + a_col);
        As[a_col + 0][a_row] = av.x;
        As[a_col + 1][a_row] = av.y;
        As[a_col + 2][a_row] = av.z;
        As[a_col + 3][a_row] = av.w;
        float4 bv = *(const float4*)(Bb + (size_t)(k0 + b_row) * N + b_col);
        *(float4*)&Bs[b_row][b_col] = bv;
        __syncthreads();

        #pragma unroll
        for (int kk = 0; kk < BK; kk++) {
            float ar[TM], br[TN];
            #pragma unroll
            for (int i = 0; i < TM; i += 4)
                *(float4*)&ar[i] = *(const float4*)&As[kk][ty * TM + i];
            #pragma unroll
            for (int j = 0; j < TN; j += 4)
                *(float4*)&br[j] = *(const float4*)&Bs[kk][tx * TN + j];
            #pragma unroll
            for (int i = 0; i < TM; i++)
                #pragma unroll
                for (int j = 0; j < TN; j++)
                    acc[i][j] += ar[i] * br[j];
        }
        __syncthreads();
    }

    #pragma unroll
    for (int i = 0; i < TM; i++) {
        const size_t row = (size_t)(by * BM + ty * TM + i);
        #pragma unroll
        for (int j = 0; j < TN; j += 4) {
            float4 v = make_float4(acc[i][j], acc[i][j+1], acc[i][j+2], acc[i][j+3]);
            *(float4*)(C + row * N + bx * BN + tx * TN + j) = v;
        }
    }
}

// ---------------------------------------------------------------------------
// Flash attention (causal), fp32.
// grid: (T/64, B*NH), block: 64 threads. 1 thread = 1 query row.
// qkv layout: [b*T + t][3072]  (q at +0, k at +1024, v at +2048; head h at h*64)
// ---------------------------------------------------------------------------
__global__ __launch_bounds__(64) void flash_attn(
    const float* __restrict__ qkv, float* __restrict__ ao)
{
    const int qb  = (gridDim.x - 1) - blockIdx.x;   // reverse order: heavy blocks launch first
    const int bh  = blockIdx.y;
    const int b   = bh / NH;
    const int h   = bh % NH;
    const int tid = threadIdx.x;
    const int qi  = qb * 64 + tid;                  // query index in [0, T)

    __shared__ float Ks[64][64];
    __shared__ float Vs[64][64];
    __shared__ float Ss[64][64];   // Ss[j][tid]  (conflict-free: lanes hit consecutive banks)

    const float scale = 0.125f;    // 1/sqrt(64)
    float q[DH];
    {
        const float* qptr = qkv + ((size_t)(b * TT + qi)) * NQKV + h * DH;
        #pragma unroll
        for (int d = 0; d < DH; d += 4) {
            float4 v = *(const float4*)(qptr + d);
            q[d] = v.x * scale; q[d+1] = v.y * scale; q[d+2] = v.z * scale; q[d+3] = v.w * scale;
        }
    }

    float o[DH];
    #pragma unroll
    for (int d = 0; d < DH; d++) o[d] = 0.f;
    float m = -INFINITY, l = 0.f;

    for (int kb = 0; kb <= qb; kb++) {
        const int j0 = kb * 64;
        const float* kbase = qkv + ((size_t)(b * TT + j0)) * NQKV + DM + h * DH;  // K
        // load K and V tiles: 1024 float4 each, 16 per thread
        #pragma unroll
        for (int r = 0; r < 16; r++) {
            int f4 = r * 64 + tid;          // 0..1023
            int row = f4 >> 4;
            int col = (f4 & 15) * 4;
            *(float4*)&Ks[row][col] = *(const float4*)(kbase + (size_t)row * NQKV + col);
            *(float4*)&Vs[row][col] = *(const float4*)(kbase + (size_t)row * NQKV + DM + col);
        }
        __syncthreads();

        const int jmax = (kb == qb) ? (tid + 1) : 64;

        // Pass 1: scores + tile max
        float mt = m;
        for (int j = 0; j < jmax; j++) {
            float s0 = 0.f, s1 = 0.f, s2 = 0.f, s3 = 0.f;
            #pragma unroll
            for (int d = 0; d < DH; d += 4) {
                float4 kv = *(const float4*)&Ks[j][d];
                s0 += q[d]   * kv.x;
                s1 += q[d+1] * kv.y;
                s2 += q[d+2] * kv.z;
                s3 += q[d+3] * kv.w;
            }
            float s = (s0 + s1) + (s2 + s3);
            Ss[j][tid] = s;
            mt = fmaxf(mt, s);
        }

        // Rescale running state
        const float alpha = __expf(m - mt);
        m = mt;
        l *= alpha;
        #pragma unroll
        for (int d = 0; d < DH; d++) o[d] *= alpha;

        // Pass 2: exp + accumulate P @ V
        for (int j = 0; j < jmax; j++) {
            float p = __expf(Ss[j][tid] - m);
            l += p;
            #pragma unroll
            for (int d = 0; d < DH; d += 4) {
                float4 vv = *(const float4*)&Vs[j][d];
                o[d]   += p * vv.x;
                o[d+1] += p * vv.y;
                o[d+2] += p * vv.z;
                o[d+3] += p * vv.w;
            }
        }
        __syncthreads();
    }

    const float inv = 1.f / l;
    float* optr = ao + ((size_t)(b * TT + qi)) * DM + h * DH;
    #pragma unroll
    for (int d = 0; d < DH; d += 4) {
        float4 v = make_float4(o[d] * inv, o[d+1] * inv, o[d+2] * inv, o[d+3] * inv);
        *(float4*)(optr + d) = v;
    }
}

// ---------------------------------------------------------------------------
extern "C" void kernel_launch(void* const* d_in, const int* in_sizes, int n_in,
                              void* d_out, int out_size)
{
    const float* x    = (const float*)d_in[0];   // [B,T,1024] fp32
    const float* Wqkv = (const float*)d_in[1];   // [1024,3072] fp32
    const float* Wout = (const float*)d_in[2];   // [1024,1024] fp32
    // d_in[3] = mask (int32) — causal, hardcoded in flash_attn
    float* out = (float*)d_out;                  // [B,T,1024] fp32

    float *qkv, *ao;
    cudaGetSymbolAddress((void**)&qkv, g_qkv);
    cudaGetSymbolAddress((void**)&ao,  g_ao);

    // 1) QKV projection: [8192,1024] x [1024,3072]
    sgemm128<<<dim3(NQKV / 128, BT / 128), 256>>>(x, Wqkv, qkv, BT, NQKV, DM);

    // 2) Causal flash attention per (b, h)
    flash_attn<<<dim3(TT / 64, BB * NH), 64>>>(qkv, ao);

    // 3) Output projection: [8192,1024] x [1024,1024]
    sgemm128<<<dim3(DM / 128, BT / 128), 256>>>(ao, Wout, out, BT, DM, DM);
}

// round 3
// speedup vs baseline: 1.5924x; 1.5924x over previous
#include <cuda_runtime.h>
#include <cuda_bf16.h>
#include <math.h>
#include <stdint.h>

// Problem constants
#define BB      4
#define TT      2048
#define DM      1024
#define NH      16
#define DH      64
#define BT      (BB * TT)        // 8192 rows
#define NQKV    (3 * DM)         // 3072

// Scratch (alloc-free rule: __device__ globals)
__device__ float g_qkv[(size_t)BT * NQKV];   // 100.7 MB
__device__ float g_ao [(size_t)BT * DM];     //  33.6 MB
__device__ float g_xr [(size_t)BT * DM];     //  33.6 MB (x rounded to tf32)
__device__ float g_wtq[(size_t)NQKV * DM];   //  12.6 MB (Wqkv^T, tf32-rounded)
__device__ float g_wto[(size_t)DM * DM];     //   4.2 MB (Wout^T, tf32-rounded)

// ---------------------------------------------------------------------------
// Helpers
// ---------------------------------------------------------------------------
__device__ __forceinline__ uint32_t smem_u32(const void* p) {
    uint32_t a;
    asm("{ .reg .u64 t; cvta.to.shared.u64 t, %1; cvt.u32.u64 %0, t; }" : "=r"(a) : "l"(p));
    return a;
}
__device__ __forceinline__ float to_tf32(float v) {
    uint32_t r;
    asm("cvt.rna.tf32.f32 %0, %1;" : "=r"(r) : "f"(v));
    return __uint_as_float(r);
}

#define CP16(dst, src)  asm volatile("cp.async.cg.shared.global [%0], [%1], 16;" :: "r"(dst), "l"(src))
#define CP_COMMIT()     asm volatile("cp.async.commit_group;")
#define CP_WAIT(n)      asm volatile("cp.async.wait_group %0;" :: "n"(n))

// m16n8k8 tf32 mma: D += A*B  (A row-major m16k8, B col-major k8n8)
__device__ __forceinline__ void mma8(float* d, const uint32_t* a, uint32_t b0, uint32_t b1) {
    asm volatile(
        "mma.sync.aligned.m16n8k8.row.col.f32.tf32.tf32.f32 "
        "{%0,%1,%2,%3}, {%4,%5,%6,%7}, {%8,%9}, {%0,%1,%2,%3};"
        : "+f"(d[0]), "+f"(d[1]), "+f"(d[2]), "+f"(d[3])
        : "r"(a[0]), "r"(a[1]), "r"(a[2]), "r"(a[3]), "r"(b0), "r"(b1));
}

// ---------------------------------------------------------------------------
// Tensor-core tf32 GEMM: C[M,N] = A[M,K] * Bt[N,K]^T  (A, Bt row-major,
// values pre-rounded to tf32). BM=BN=128, BK=16, 256 threads (8 warps),
// warp tile 32x64, double-buffered cp.async.
// Smem row stride 20 floats -> conflict-free fragment loads.
// ---------------------------------------------------------------------------
#define LDSR 20
__global__ __launch_bounds__(256, 2) void gemm_mma(
    const float* __restrict__ A, const float* __restrict__ Bt, float* __restrict__ C,
    int M, int N, int K)
{
    __shared__ float As[2][128 * LDSR];
    __shared__ float Bs[2][128 * LDSR];

    const int tid  = threadIdx.x;
    const int lane = tid & 31;
    const int wid  = tid >> 5;
    const int wm   = (wid >> 1) * 32;   // warp row offset (0,32,64,96)
    const int wn   = (wid & 1) * 64;    // warp col offset (0,64)
    const int g    = lane >> 2;         // 0..7
    const int tg   = lane & 3;          // 0..3

    const int bx = blockIdx.x, by = blockIdx.y;

    // load map: tile = 512 float4; thread does 2 for A, 2 for B
    const int f0 = tid, f1 = tid + 256;
    const int r0 = f0 >> 2, q0 = (f0 & 3) * 4;
    const int r1 = f1 >> 2, q1 = (f1 & 3) * 4;
    const float* gA = A  + (size_t)(by * 128) * K;
    const float* gB = Bt + (size_t)(bx * 128) * K;

    const uint32_t sA0 = smem_u32(&As[0][0]);
    const uint32_t sB0 = smem_u32(&Bs[0][0]);

    float acc[2][8][4];
    #pragma unroll
    for (int i = 0; i < 2; i++)
        #pragma unroll
        for (int j = 0; j < 8; j++)
            #pragma unroll
            for (int q = 0; q < 4; q++) acc[i][j][q] = 0.f;

    const int NC = K / 16;

    // prologue: stage 0
    {
        CP16(sA0 + (r0 * LDSR + q0) * 4, gA + (size_t)r0 * K + q0);
        CP16(sA0 + (r1 * LDSR + q1) * 4, gA + (size_t)r1 * K + q1);
        CP16(sB0 + (r0 * LDSR + q0) * 4, gB + (size_t)r0 * K + q0);
        CP16(sB0 + (r1 * LDSR + q1) * 4, gB + (size_t)r1 * K + q1);
        CP_COMMIT();
    }

    for (int c = 0; c < NC; c++) {
        const int s = c & 1;
        if (c + 1 < NC) {
            const int ns = (c + 1) & 1;
            const int k0 = (c + 1) * 16;
            const uint32_t dA = sA0 + ns * 128 * LDSR * 4;
            const uint32_t dB = sB0 + ns * 128 * LDSR * 4;
            CP16(dA + (r0 * LDSR + q0) * 4, gA + (size_t)r0 * K + k0 + q0);
            CP16(dA + (r1 * LDSR + q1) * 4, gA + (size_t)r1 * K + k0 + q1);
            CP16(dB + (r0 * LDSR + q0) * 4, gB + (size_t)r0 * K + k0 + q0);
            CP16(dB + (r1 * LDSR + q1) * 4, gB + (size_t)r1 * K + k0 + q1);
            CP_COMMIT();
            CP_WAIT(1);
        } else {
            CP_WAIT(0);
        }
        __syncthreads();

        const float* as = &As[s][0];
        const float* bs = &Bs[s][0];
        #pragma unroll
        for (int ks = 0; ks < 2; ks++) {
            const int kb = ks * 8;
            uint32_t a[2][4];
            #pragma unroll
            for (int mt = 0; mt < 2; mt++) {
                const int row = wm + mt * 16;
                a[mt][0] = __float_as_uint(as[(row + g)     * LDSR + kb + tg]);
                a[mt][1] = __float_as_uint(as[(row + g + 8) * LDSR + kb + tg]);
                a[mt][2] = __float_as_uint(as[(row + g)     * LDSR + kb + tg + 4]);
                a[mt][3] = __float_as_uint(as[(row + g + 8) * LDSR + kb + tg + 4]);
            }
            #pragma unroll
            for (int nt = 0; nt < 8; nt++) {
                const int col = wn + nt * 8;
                uint32_t b0 = __float_as_uint(bs[(col + g) * LDSR + kb + tg]);
                uint32_t b1 = __float_as_uint(bs[(col + g) * LDSR + kb + tg + 4]);
                mma8(acc[0][nt], a[0], b0, b1);
                mma8(acc[1][nt], a[1], b0, b1);
            }
        }
        __syncthreads();
    }

    // epilogue
    #pragma unroll
    for (int mt = 0; mt < 2; mt++) {
        const size_t rowA = (size_t)(by * 128 + wm + mt * 16 + g);
        #pragma unroll
        for (int nt = 0; nt < 8; nt++) {
            const int col = bx * 128 + wn + nt * 8 + 2 * tg;
            *(float2*)(C + rowA * N + col)       = make_float2(acc[mt][nt][0], acc[mt][nt][1]);
            *(float2*)(C + (rowA + 8) * N + col) = make_float2(acc[mt][nt][2], acc[mt][nt][3]);
        }
    }
}

// ---------------------------------------------------------------------------
// Transpose [rows,cols] -> [cols,rows], rounding values to tf32 (RN)
// ---------------------------------------------------------------------------
__global__ void transpose32(const float* __restrict__ in, float* __restrict__ out,
                            int rows, int cols)
{
    __shared__ float t[32][33];
    const int bx = blockIdx.x * 32, by = blockIdx.y * 32;
    #pragma unroll
    for (int i = threadIdx.y; i < 32; i += 8)
        t[i][threadIdx.x] = in[(size_t)(by + i) * cols + bx + threadIdx.x];
    __syncthreads();
    #pragma unroll
    for (int i = threadIdx.y; i < 32; i += 8)
        out[(size_t)(bx + i) * rows + by + threadIdx.x] = to_tf32(t[threadIdx.x][i]);
}

// Round fp32 array to tf32 (RN), vectorized
__global__ void round_tf32_vec(const float* __restrict__ in, float* __restrict__ out, int n4)
{
    int i = blockIdx.x * blockDim.x + threadIdx.x;
    if (i < n4) {
        float4 v = ((const float4*)in)[i];
        v.x = to_tf32(v.x); v.y = to_tf32(v.y); v.z = to_tf32(v.z); v.w = to_tf32(v.w);
        ((float4*)out)[i] = v;
    }
}

// ---------------------------------------------------------------------------
// Flash attention (causal), fp32. grid: (T/64, B*NH), block: 64 threads.
// Output rounded to tf32 (feeds the tf32 out-projection GEMM).
// ---------------------------------------------------------------------------
__global__ __launch_bounds__(64) void flash_attn(
    const float* __restrict__ qkv, float* __restrict__ ao)
{
    const int qb  = (gridDim.x - 1) - blockIdx.x;
    const int bh  = blockIdx.y;
    const int b   = bh / NH;
    const int h   = bh % NH;
    const int tid = threadIdx.x;
    const int qi  = qb * 64 + tid;

    __shared__ float Ks[64][64];
    __shared__ float Vs[64][64];
    __shared__ float Ss[64][64];

    const float scale = 0.125f;
    float q[DH];
    {
        const float* qptr = qkv + ((size_t)(b * TT + qi)) * NQKV + h * DH;
        #pragma unroll
        for (int d = 0; d < DH; d += 4) {
            float4 v = *(const float4*)(qptr + d);
            q[d] = v.x * scale; q[d+1] = v.y * scale; q[d+2] = v.z * scale; q[d+3] = v.w * scale;
        }
    }

    float o[DH];
    #pragma unroll
    for (int d = 0; d < DH; d++) o[d] = 0.f;
    float m = -INFINITY, l = 0.f;

    for (int kb = 0; kb <= qb; kb++) {
        const int j0 = kb * 64;
        const float* kbase = qkv + ((size_t)(b * TT + j0)) * NQKV + DM + h * DH;
        #pragma unroll
        for (int r = 0; r < 16; r++) {
            int f4 = r * 64 + tid;
            int row = f4 >> 4;
            int col = (f4 & 15) * 4;
            *(float4*)&Ks[row][col] = *(const float4*)(kbase + (size_t)row * NQKV + col);
            *(float4*)&Vs[row][col] = *(const float4*)(kbase + (size_t)row * NQKV + DM + col);
        }
        __syncthreads();

        const int jmax = (kb == qb) ? (tid + 1) : 64;

        float mt = m;
        for (int j = 0; j < jmax; j++) {
            float s0 = 0.f, s1 = 0.f, s2 = 0.f, s3 = 0.f;
            #pragma unroll
            for (int d = 0; d < DH; d += 4) {
                float4 kv = *(const float4*)&Ks[j][d];
                s0 += q[d]   * kv.x;
                s1 += q[d+1] * kv.y;
                s2 += q[d+2] * kv.z;
                s3 += q[d+3] * kv.w;
            }
            float s = (s0 + s1) + (s2 + s3);
            Ss[j][tid] = s;
            mt = fmaxf(mt, s);
        }

        const float alpha = __expf(m - mt);
        m = mt;
        l *= alpha;
        #pragma unroll
        for (int d = 0; d < DH; d++) o[d] *= alpha;

        for (int j = 0; j < jmax; j++) {
            float p = __expf(Ss[j][tid] - m);
            l += p;
            #pragma unroll
            for (int d = 0; d < DH; d += 4) {
                float4 vv = *(const float4*)&Vs[j][d];
                o[d]   += p * vv.x;
                o[d+1] += p * vv.y;
                o[d+2] += p * vv.z;
                o[d+3] += p * vv.w;
            }
        }
        __syncthreads();
    }

    const float inv = 1.f / l;
    float* optr = ao + ((size_t)(b * TT + qi)) * DM + h * DH;
    #pragma unroll
    for (int d = 0; d < DH; d += 4) {
        float4 v = make_float4(to_tf32(o[d] * inv),   to_tf32(o[d+1] * inv),
                               to_tf32(o[d+2] * inv), to_tf32(o[d+3] * inv));
        *(float4*)(optr + d) = v;
    }
}

// ---------------------------------------------------------------------------
extern "C" void kernel_launch(void* const* d_in, const int* in_sizes, int n_in,
                              void* d_out, int out_size)
{
    const float* x    = (const float*)d_in[0];   // [B,T,1024]
    const float* Wqkv = (const float*)d_in[1];   // [1024,3072]
    const float* Wout = (const float*)d_in[2];   // [1024,1024]
    float* out = (float*)d_out;

    float *qkv, *ao, *xr, *wtq, *wto;
    cudaGetSymbolAddress((void**)&qkv, g_qkv);
    cudaGetSymbolAddress((void**)&ao,  g_ao);
    cudaGetSymbolAddress((void**)&xr,  g_xr);
    cudaGetSymbolAddress((void**)&wtq, g_wtq);
    cudaGetSymbolAddress((void**)&wto, g_wto);

    // Pre-round / pre-transpose GEMM operands to tf32
    round_tf32_vec<<<(BT * DM / 4 + 255) / 256, 256>>>(x, xr, BT * DM / 4);
    transpose32<<<dim3(NQKV / 32, DM / 32), dim3(32, 8)>>>(Wqkv, wtq, DM, NQKV);
    transpose32<<<dim3(DM / 32, DM / 32), dim3(32, 8)>>>(Wout, wto, DM, DM);

    // 1) QKV projection (tensor-core tf32)
    gemm_mma<<<dim3(NQKV / 128, BT / 128), 256>>>(xr, wtq, qkv, BT, NQKV, DM);

    // 2) Causal flash attention
    flash_attn<<<dim3(TT / 64, BB * NH), 64>>>(qkv, ao);

    // 3) Output projection (tensor-core tf32)
    gemm_mma<<<dim3(DM / 128, BT / 128), 256>>>(ao, wto, out, BT, DM, DM);
}

// round 5
// speedup vs baseline: 2.5689x; 1.6133x over previous
#include <cuda_runtime.h>
#include <cuda_bf16.h>
#include <math.h>
#include <stdint.h>

// Problem constants
#define BB      4
#define TT      2048
#define DM      1024
#define NH      16
#define DH      64
#define BT      (BB * TT)        // 8192 rows
#define NQKV    (3 * DM)         // 3072

// Scratch (alloc-free rule: __device__ globals)
__device__ float g_qkv[(size_t)BT * NQKV];   // 100.7 MB
__device__ float g_ao [(size_t)BT * DM];     //  33.6 MB
__device__ float g_xr [(size_t)BT * DM];     //  33.6 MB (x rounded to tf32)
__device__ float g_wtq[(size_t)NQKV * DM];   //  12.6 MB (Wqkv^T, tf32-rounded)
__device__ float g_wto[(size_t)DM * DM];     //   4.2 MB (Wout^T, tf32-rounded)

// ---------------------------------------------------------------------------
// Helpers
// ---------------------------------------------------------------------------
__device__ __forceinline__ uint32_t smem_u32(const void* p) {
    uint32_t a;
    asm("{ .reg .u64 t; cvta.to.shared.u64 t, %1; cvt.u32.u64 %0, t; }" : "=r"(a) : "l"(p));
    return a;
}
__device__ __forceinline__ float to_tf32(float v) {
    uint32_t r;
    asm("cvt.rna.tf32.f32 %0, %1;" : "=r"(r) : "f"(v));
    return __uint_as_float(r);
}

#define CP16(dst, src)  asm volatile("cp.async.cg.shared.global [%0], [%1], 16;" :: "r"(dst), "l"(src))
#define CP_COMMIT()     asm volatile("cp.async.commit_group;")
#define CP_WAIT(n)      asm volatile("cp.async.wait_group %0;" :: "n"(n))

// m16n8k8 tf32 mma: D += A*B  (A row-major m16k8, B col-major k8n8)
__device__ __forceinline__ void mma8(float* d, const uint32_t* a, uint32_t b0, uint32_t b1) {
    asm volatile(
        "mma.sync.aligned.m16n8k8.row.col.f32.tf32.tf32.f32 "
        "{%0,%1,%2,%3}, {%4,%5,%6,%7}, {%8,%9}, {%0,%1,%2,%3};"
        : "+f"(d[0]), "+f"(d[1]), "+f"(d[2]), "+f"(d[3])
        : "r"(a[0]), "r"(a[1]), "r"(a[2]), "r"(a[3]), "r"(b0), "r"(b1));
}
__device__ __forceinline__ void mma8f(float* d, const float* a, float b0, float b1) {
    asm volatile(
        "mma.sync.aligned.m16n8k8.row.col.f32.tf32.tf32.f32 "
        "{%0,%1,%2,%3}, {%4,%5,%6,%7}, {%8,%9}, {%0,%1,%2,%3};"
        : "+f"(d[0]), "+f"(d[1]), "+f"(d[2]), "+f"(d[3])
        : "r"(__float_as_uint(a[0])), "r"(__float_as_uint(a[1])),
          "r"(__float_as_uint(a[2])), "r"(__float_as_uint(a[3])),
          "r"(__float_as_uint(b0)),  "r"(__float_as_uint(b1)));
}

// ---------------------------------------------------------------------------
// Tensor-core tf32 GEMM (unchanged from R3 — passing)
// ---------------------------------------------------------------------------
#define LDSR 20
__global__ __launch_bounds__(256, 2) void gemm_mma(
    const float* __restrict__ A, const float* __restrict__ Bt, float* __restrict__ C,
    int M, int N, int K)
{
    __shared__ float As[2][128 * LDSR];
    __shared__ float Bs[2][128 * LDSR];

    const int tid  = threadIdx.x;
    const int lane = tid & 31;
    const int wid  = tid >> 5;
    const int wm   = (wid >> 1) * 32;
    const int wn   = (wid & 1) * 64;
    const int g    = lane >> 2;
    const int tg   = lane & 3;

    const int bx = blockIdx.x, by = blockIdx.y;

    const int f0 = tid, f1 = tid + 256;
    const int r0 = f0 >> 2, q0 = (f0 & 3) * 4;
    const int r1 = f1 >> 2, q1 = (f1 & 3) * 4;
    const float* gA = A  + (size_t)(by * 128) * K;
    const float* gB = Bt + (size_t)(bx * 128) * K;

    const uint32_t sA0 = smem_u32(&As[0][0]);
    const uint32_t sB0 = smem_u32(&Bs[0][0]);

    float acc[2][8][4];
    #pragma unroll
    for (int i = 0; i < 2; i++)
        #pragma unroll
        for (int j = 0; j < 8; j++)
            #pragma unroll
            for (int q = 0; q < 4; q++) acc[i][j][q] = 0.f;

    const int NC = K / 16;

    {
        CP16(sA0 + (r0 * LDSR + q0) * 4, gA + (size_t)r0 * K + q0);
        CP16(sA0 + (r1 * LDSR + q1) * 4, gA + (size_t)r1 * K + q1);
        CP16(sB0 + (r0 * LDSR + q0) * 4, gB + (size_t)r0 * K + q0);
        CP16(sB0 + (r1 * LDSR + q1) * 4, gB + (size_t)r1 * K + q1);
        CP_COMMIT();
    }

    for (int c = 0; c < NC; c++) {
        const int s = c & 1;
        if (c + 1 < NC) {
            const int ns = (c + 1) & 1;
            const int k0 = (c + 1) * 16;
            const uint32_t dA = sA0 + ns * 128 * LDSR * 4;
            const uint32_t dB = sB0 + ns * 128 * LDSR * 4;
            CP16(dA + (r0 * LDSR + q0) * 4, gA + (size_t)r0 * K + k0 + q0);
            CP16(dA + (r1 * LDSR + q1) * 4, gA + (size_t)r1 * K + k0 + q1);
            CP16(dB + (r0 * LDSR + q0) * 4, gB + (size_t)r0 * K + k0 + q0);
            CP16(dB + (r1 * LDSR + q1) * 4, gB + (size_t)r1 * K + k0 + q1);
            CP_COMMIT();
            CP_WAIT(1);
        } else {
            CP_WAIT(0);
        }
        __syncthreads();

        const float* as = &As[s][0];
        const float* bs = &Bs[s][0];
        #pragma unroll
        for (int ks = 0; ks < 2; ks++) {
            const int kb = ks * 8;
            uint32_t a[2][4];
            #pragma unroll
            for (int mt = 0; mt < 2; mt++) {
                const int row = wm + mt * 16;
                a[mt][0] = __float_as_uint(as[(row + g)     * LDSR + kb + tg]);
                a[mt][1] = __float_as_uint(as[(row + g + 8) * LDSR + kb + tg]);
                a[mt][2] = __float_as_uint(as[(row + g)     * LDSR + kb + tg + 4]);
                a[mt][3] = __float_as_uint(as[(row + g + 8) * LDSR + kb + tg + 4]);
            }
            #pragma unroll
            for (int nt = 0; nt < 8; nt++) {
                const int col = wn + nt * 8;
                uint32_t b0 = __float_as_uint(bs[(col + g) * LDSR + kb + tg]);
                uint32_t b1 = __float_as_uint(bs[(col + g) * LDSR + kb + tg + 4]);
                mma8(acc[0][nt], a[0], b0, b1);
                mma8(acc[1][nt], a[1], b0, b1);
            }
        }
        __syncthreads();
    }

    #pragma unroll
    for (int mt = 0; mt < 2; mt++) {
        const size_t rowA = (size_t)(by * 128 + wm + mt * 16 + g);
        #pragma unroll
        for (int nt = 0; nt < 8; nt++) {
            const int col = bx * 128 + wn + nt * 8 + 2 * tg;
            *(float2*)(C + rowA * N + col)       = make_float2(acc[mt][nt][0], acc[mt][nt][1]);
            *(float2*)(C + (rowA + 8) * N + col) = make_float2(acc[mt][nt][2], acc[mt][nt][3]);
        }
    }
}

// ---------------------------------------------------------------------------
// Transpose + tf32 rounding prologue kernels (unchanged)
// ---------------------------------------------------------------------------
__global__ void transpose32(const float* __restrict__ in, float* __restrict__ out,
                            int rows, int cols)
{
    __shared__ float t[32][33];
    const int bx = blockIdx.x * 32, by = blockIdx.y * 32;
    #pragma unroll
    for (int i = threadIdx.y; i < 32; i += 8)
        t[i][threadIdx.x] = in[(size_t)(by + i) * cols + bx + threadIdx.x];
    __syncthreads();
    #pragma unroll
    for (int i = threadIdx.y; i < 32; i += 8)
        out[(size_t)(bx + i) * rows + by + threadIdx.x] = to_tf32(t[threadIdx.x][i]);
}

__global__ void round_tf32_vec(const float* __restrict__ in, float* __restrict__ out, int n4)
{
    int i = blockIdx.x * blockDim.x + threadIdx.x;
    if (i < n4) {
        float4 v = ((const float4*)in)[i];
        v.x = to_tf32(v.x); v.y = to_tf32(v.y); v.z = to_tf32(v.z); v.w = to_tf32(v.w);
        ((float4*)out)[i] = v;
    }
}

// ---------------------------------------------------------------------------
// Tensor-core flash attention (causal), 3x-tf32 split => ~fp32 accuracy.
// grid: (T/64, B*NH), block 128 (4 warps). Warp w handles query rows
// [qb*64 + 16w, +16). K/V tiles 64x64 double-buffered in smem via cp.async.
//
// m16n8k8 fragment layouts (verified by passing gemm_mma):
//   A: a0=(g,tg) a1=(g+8,tg) a2=(g,tg+4) a3=(g+8,tg+4)   g=lane>>2, tg=lane&3
//   B: b0=(k=tg,n=g) b1=(k=tg+4,n=g)
//   C: c0=(g,2tg) c1=(g,2tg+1) c2=(g+8,2tg) c3=(g+8,2tg+1)
// ---------------------------------------------------------------------------
#define PADK 68
#define PADV 72
#define FA_KS_BYTES (64 * PADK * 4)            // 17408
#define FA_VS_BYTES (64 * PADV * 4)            // 18432
#define FA_SMEM (2 * FA_KS_BYTES + 2 * FA_VS_BYTES + FA_KS_BYTES)  // 89088

__global__ __launch_bounds__(128) void flash_attn_mma(
    const float* __restrict__ qkv, float* __restrict__ ao)
{
    extern __shared__ char sm[];
    float* KsBase = (float*)sm;                                  // [2][64][PADK]
    float* VsBase = (float*)(sm + 2 * FA_KS_BYTES);              // [2][64][PADV]
    float* Ps     = (float*)(sm + 2 * FA_KS_BYTES + 2 * FA_VS_BYTES); // [64][PADK]

    const int qb   = (gridDim.x - 1) - blockIdx.x;  // heavy blocks first
    const int bh   = blockIdx.y;
    const int b    = bh >> 4;
    const int h    = bh & 15;
    const int tid  = threadIdx.x;
    const int lane = tid & 31;
    const int wid  = tid >> 5;
    const int g    = lane >> 2;
    const int tg   = lane & 3;
    const int r0   = wid * 16;                      // warp's row base within tile

    const uint32_t ksb = smem_u32(KsBase);
    const uint32_t vsb = smem_u32(VsBase);

    // ---- issue cp.async for K/V tile 0 into buffer 0 ----
    const size_t rowbase = (size_t)(b * TT);
    {
        const float* kb0 = qkv + (rowbase + 0) * NQKV + DM + h * DH;
        #pragma unroll
        for (int i = 0; i < 8; i++) {
            int f4 = tid + i * 128;
            int row = f4 >> 4;
            int col = (f4 & 15) * 4;
            CP16(ksb + (uint32_t)(row * PADK + col) * 4, kb0 + (size_t)row * NQKV + col);
            CP16(vsb + (uint32_t)(row * PADV + col) * 4, kb0 + (size_t)row * NQKV + DM + col);
        }
        CP_COMMIT();
    }

    // ---- load Q fragments into registers, split hi/lo (overlaps cp.async) ----
    float qh[8][4], ql[8][4];
    {
        const float* qp = qkv + (rowbase + (size_t)(qb * 64 + r0)) * NQKV + h * DH;
        #pragma unroll
        for (int kc = 0; kc < 8; kc++) {
            #pragma unroll
            for (int e = 0; e < 4; e++) {
                int dr = (e & 1) * 8;          // a0,a2 -> row g ; a1,a3 -> row g+8
                int dc = (e >> 1) * 4;         // a0,a1 -> k tg ; a2,a3 -> k tg+4
                float v = qp[(size_t)(g + dr) * NQKV + kc * 8 + tg + dc] * 0.125f;
                float hi = to_tf32(v);
                qh[kc][e] = hi;
                ql[kc][e] = v - hi;
            }
        }
    }

    float O[8][4];
    #pragma unroll
    for (int nc = 0; nc < 8; nc++)
        #pragma unroll
        for (int e = 0; e < 4; e++) O[nc][e] = 0.f;
    float m0 = -1e30f, m1 = -1e30f, l0 = 0.f, l1 = 0.f;

    for (int kb = 0; kb <= qb; kb++) {
        const int buf = kb & 1;
        // prefetch next tile
        if (kb < qb) {
            const int nbuf = buf ^ 1;
            const float* kbn = qkv + (rowbase + (size_t)((kb + 1) * 64)) * NQKV + DM + h * DH;
            const uint32_t kd = ksb + (uint32_t)nbuf * FA_KS_BYTES;
            const uint32_t vd = vsb + (uint32_t)nbuf * FA_VS_BYTES;
            #pragma unroll
            for (int i = 0; i < 8; i++) {
                int f4 = tid + i * 128;
                int row = f4 >> 4;
                int col = (f4 & 15) * 4;
                CP16(kd + (uint32_t)(row * PADK + col) * 4, kbn + (size_t)row * NQKV + col);
                CP16(vd + (uint32_t)(row * PADV + col) * 4, kbn + (size_t)row * NQKV + DM + col);
            }
            CP_COMMIT();
            CP_WAIT(1);   // tile kb complete (next still in flight)
        } else {
            CP_WAIT(0);
        }
        __syncthreads();

        const float* Ks = KsBase + buf * (64 * PADK);
        const float* Vs = VsBase + buf * (64 * PADV);

        // ---- S = (Q*scale) K^T via 3x tf32 split ----
        float Sc[8][4];
        #pragma unroll
        for (int nc = 0; nc < 8; nc++)
            #pragma unroll
            for (int e = 0; e < 4; e++) Sc[nc][e] = 0.f;

        #pragma unroll
        for (int kc = 0; kc < 8; kc++) {
            #pragma unroll
            for (int nc = 0; nc < 8; nc++) {
                float kv0 = Ks[(nc * 8 + g) * PADK + kc * 8 + tg];
                float kv1 = Ks[(nc * 8 + g) * PADK + kc * 8 + tg + 4];
                float kh0 = to_tf32(kv0), kl0 = kv0 - kh0;
                float kh1 = to_tf32(kv1), kl1 = kv1 - kh1;
                mma8f(Sc[nc], qh[kc], kh0, kh1);
                mma8f(Sc[nc], ql[kc], kh0, kh1);
                mma8f(Sc[nc], qh[kc], kl0, kl1);
            }
        }

        // ---- causal mask on diagonal tile ----
        if (kb == qb) {
            const int i0 = r0 + g, i1 = r0 + g + 8;
            #pragma unroll
            for (int nc = 0; nc < 8; nc++) {
                int j = nc * 8 + 2 * tg;
                if (j     > i0) Sc[nc][0] = -1e30f;
                if (j + 1 > i0) Sc[nc][1] = -1e30f;
                if (j     > i1) Sc[nc][2] = -1e30f;
                if (j + 1 > i1) Sc[nc][3] = -1e30f;
            }
        }

        // ---- online softmax ----
        float rx0 = -1e30f, rx1 = -1e30f;
        #pragma unroll
        for (int nc = 0; nc < 8; nc++) {
            rx0 = fmaxf(rx0, fmaxf(Sc[nc][0], Sc[nc][1]));
            rx1 = fmaxf(rx1, fmaxf(Sc[nc][2], Sc[nc][3]));
        }
        rx0 = fmaxf(rx0, __shfl_xor_sync(0xFFFFFFFF, rx0, 1));
        rx0 = fmaxf(rx0, __shfl_xor_sync(0xFFFFFFFF, rx0, 2));
        rx1 = fmaxf(rx1, __shfl_xor_sync(0xFFFFFFFF, rx1, 1));
        rx1 = fmaxf(rx1, __shfl_xor_sync(0xFFFFFFFF, rx1, 2));

        const float mn0 = fmaxf(m0, rx0);
        const float mn1 = fmaxf(m1, rx1);
        const float a0 = __expf(m0 - mn0);
        const float a1 = __expf(m1 - mn1);
        m0 = mn0; m1 = mn1;

        float s0 = 0.f, s1 = 0.f;
        #pragma unroll
        for (int nc = 0; nc < 8; nc++) {
            Sc[nc][0] = __expf(Sc[nc][0] - mn0);
            Sc[nc][1] = __expf(Sc[nc][1] - mn0);
            Sc[nc][2] = __expf(Sc[nc][2] - mn1);
            Sc[nc][3] = __expf(Sc[nc][3] - mn1);
            s0 += Sc[nc][0] + Sc[nc][1];
            s1 += Sc[nc][2] + Sc[nc][3];
        }
        s0 += __shfl_xor_sync(0xFFFFFFFF, s0, 1);
        s0 += __shfl_xor_sync(0xFFFFFFFF, s0, 2);
        s1 += __shfl_xor_sync(0xFFFFFFFF, s1, 1);
        s1 += __shfl_xor_sync(0xFFFFFFFF, s1, 2);
        l0 = l0 * a0 + s0;
        l1 = l1 * a1 + s1;

        #pragma unroll
        for (int nc = 0; nc < 8; nc++) {
            O[nc][0] *= a0; O[nc][1] *= a0;
            O[nc][2] *= a1; O[nc][3] *= a1;
        }

        // ---- P -> smem (per-warp region), then PV via 3x split ----
        #pragma unroll
        for (int nc = 0; nc < 8; nc++) {
            *(float2*)&Ps[(r0 + g)     * PADK + nc * 8 + 2 * tg] = make_float2(Sc[nc][0], Sc[nc][1]);
            *(float2*)&Ps[(r0 + g + 8) * PADK + nc * 8 + 2 * tg] = make_float2(Sc[nc][2], Sc[nc][3]);
        }
        __syncwarp();

        #pragma unroll
        for (int kc = 0; kc < 8; kc++) {
            float ph[4], pl[4];
            #pragma unroll
            for (int e = 0; e < 4; e++) {
                int dr = (e & 1) * 8;
                int dc = (e >> 1) * 4;
                float v = Ps[(r0 + g + dr) * PADK + kc * 8 + tg + dc];
                float hi = to_tf32(v);
                ph[e] = hi;
                pl[e] = v - hi;
            }
            #pragma unroll
            for (int nc = 0; nc < 8; nc++) {
                float vv0 = Vs[(kc * 8 + tg)     * PADV + nc * 8 + g];
                float vv1 = Vs[(kc * 8 + tg + 4) * PADV + nc * 8 + g];
                float vh0 = to_tf32(vv0), vl0 = vv0 - vh0;
                float vh1 = to_tf32(vv1), vl1 = vv1 - vh1;
                mma8f(O[nc], ph, vh0, vh1);
                mma8f(O[nc], pl, vh0, vh1);
                mma8f(O[nc], ph, vl0, vl1);
            }
        }
        __syncwarp();
        __syncthreads();   // all warps done with this K/V buffer
    }

    // ---- normalize + write (tf32-rounded, feeds tf32 out-proj) ----
    const float inv0 = 1.f / l0;
    const float inv1 = 1.f / l1;
    float* op0 = ao + (rowbase + (size_t)(qb * 64 + r0 + g))     * DM + h * DH;
    float* op1 = ao + (rowbase + (size_t)(qb * 64 + r0 + g + 8)) * DM + h * DH;
    #pragma unroll
    for (int nc = 0; nc < 8; nc++) {
        *(float2*)(op0 + nc * 8 + 2 * tg) =
            make_float2(to_tf32(O[nc][0] * inv0), to_tf32(O[nc][1] * inv0));
        *(float2*)(op1 + nc * 8 + 2 * tg) =
            make_float2(to_tf32(O[nc][2] * inv1), to_tf32(O[nc][3] * inv1));
    }
}

// ---------------------------------------------------------------------------
extern "C" void kernel_launch(void* const* d_in, const int* in_sizes, int n_in,
                              void* d_out, int out_size)
{
    const float* x    = (const float*)d_in[0];   // [B,T,1024]
    const float* Wqkv = (const float*)d_in[1];   // [1024,3072]
    const float* Wout = (const float*)d_in[2];   // [1024,1024]
    float* out = (float*)d_out;

    float *qkv, *ao, *xr, *wtq, *wto;
    cudaGetSymbolAddress((void**)&qkv, g_qkv);
    cudaGetSymbolAddress((void**)&ao,  g_ao);
    cudaGetSymbolAddress((void**)&xr,  g_xr);
    cudaGetSymbolAddress((void**)&wtq, g_wtq);
    cudaGetSymbolAddress((void**)&wto, g_wto);

    cudaFuncSetAttribute(flash_attn_mma, cudaFuncAttributeMaxDynamicSharedMemorySize, FA_SMEM);

    // Pre-round / pre-transpose GEMM operands to tf32
    round_tf32_vec<<<(BT * DM / 4 + 255) / 256, 256>>>(x, xr, BT * DM / 4);
    transpose32<<<dim3(NQKV / 32, DM / 32), dim3(32, 8)>>>(Wqkv, wtq, DM, NQKV);
    transpose32<<<dim3(DM / 32, DM / 32), dim3(32, 8)>>>(Wout, wto, DM, DM);

    // 1) QKV projection (tensor-core tf32)
    gemm_mma<<<dim3(NQKV / 128, BT / 128), 256>>>(xr, wtq, qkv, BT, NQKV, DM);

    // 2) Causal flash attention (tensor-core, 3x-tf32 split)
    flash_attn_mma<<<dim3(TT / 64, BB * NH), 128, FA_SMEM>>>(qkv, ao);

    // 3) Output projection (tensor-core tf32)
    gemm_mma<<<dim3(DM / 128, BT / 128), 256>>>(ao, wto, out, BT, DM, DM);
}

// round 6
// speedup vs baseline: 3.7078x; 1.4434x over previous
#include <cuda_runtime.h>
#include <cuda_bf16.h>
#include <math.h>
#include <stdint.h>

// Problem constants
#define BB      4
#define TT      2048
#define DM      1024
#define NH      16
#define DH      64
#define BT      (BB * TT)        // 8192 rows
#define NQKV    (3 * DM)         // 3072

// Scratch (alloc-free rule: __device__ globals)
__device__ float g_qkv[(size_t)BT * NQKV];   // 100.7 MB
__device__ float g_ao [(size_t)BT * DM];     //  33.6 MB
__device__ float g_xr [(size_t)BT * DM];     //  33.6 MB (x rounded to tf32)
__device__ float g_wtq[(size_t)NQKV * DM];   //  12.6 MB (Wqkv^T, tf32-rounded)
__device__ float g_wto[(size_t)DM * DM];     //   4.2 MB (Wout^T, tf32-rounded)

// ---------------------------------------------------------------------------
// Helpers
// ---------------------------------------------------------------------------
__device__ __forceinline__ uint32_t smem_u32(const void* p) {
    uint32_t a;
    asm("{ .reg .u64 t; cvta.to.shared.u64 t, %1; cvt.u32.u64 %0, t; }" : "=r"(a) : "l"(p));
    return a;
}
__device__ __forceinline__ float to_tf32(float v) {
    uint32_t r;
    asm("cvt.rna.tf32.f32 %0, %1;" : "=r"(r) : "f"(v));
    return __uint_as_float(r);
}

#define CP16(dst, src)  asm volatile("cp.async.cg.shared.global [%0], [%1], 16;" :: "r"(dst), "l"(src))
#define CP_COMMIT()     asm volatile("cp.async.commit_group;")
#define CP_WAIT(n)      asm volatile("cp.async.wait_group %0;" :: "n"(n))

// m16n8k8 tf32 mma: D += A*B  (A row-major m16k8, B col-major k8n8)
__device__ __forceinline__ void mma8(float* d, const uint32_t* a, uint32_t b0, uint32_t b1) {
    asm volatile(
        "mma.sync.aligned.m16n8k8.row.col.f32.tf32.tf32.f32 "
        "{%0,%1,%2,%3}, {%4,%5,%6,%7}, {%8,%9}, {%0,%1,%2,%3};"
        : "+f"(d[0]), "+f"(d[1]), "+f"(d[2]), "+f"(d[3])
        : "r"(a[0]), "r"(a[1]), "r"(a[2]), "r"(a[3]), "r"(b0), "r"(b1));
}
__device__ __forceinline__ void mma8f(float* d, const float* a, float b0, float b1) {
    asm volatile(
        "mma.sync.aligned.m16n8k8.row.col.f32.tf32.tf32.f32 "
        "{%0,%1,%2,%3}, {%4,%5,%6,%7}, {%8,%9}, {%0,%1,%2,%3};"
        : "+f"(d[0]), "+f"(d[1]), "+f"(d[2]), "+f"(d[3])
        : "r"(__float_as_uint(a[0])), "r"(__float_as_uint(a[1])),
          "r"(__float_as_uint(a[2])), "r"(__float_as_uint(a[3])),
          "r"(__float_as_uint(b0)),  "r"(__float_as_uint(b1)));
}

// ---------------------------------------------------------------------------
// Tensor-core tf32 GEMM. New: output columns >= roundFrom*128 are written
// tf32-rounded (used to pre-round K,V for the attention kernel for free).
// ---------------------------------------------------------------------------
#define LDSR 20
__global__ __launch_bounds__(256, 2) void gemm_mma(
    const float* __restrict__ A, const float* __restrict__ Bt, float* __restrict__ C,
    int M, int N, int K, int roundFrom)
{
    __shared__ float As[2][128 * LDSR];
    __shared__ float Bs[2][128 * LDSR];

    const int tid  = threadIdx.x;
    const int lane = tid & 31;
    const int wid  = tid >> 5;
    const int wm   = (wid >> 1) * 32;
    const int wn   = (wid & 1) * 64;
    const int g    = lane >> 2;
    const int tg   = lane & 3;

    const int bx = blockIdx.x, by = blockIdx.y;

    const int f0 = tid, f1 = tid + 256;
    const int r0 = f0 >> 2, q0 = (f0 & 3) * 4;
    const int r1 = f1 >> 2, q1 = (f1 & 3) * 4;
    const float* gA = A  + (size_t)(by * 128) * K;
    const float* gB = Bt + (size_t)(bx * 128) * K;

    const uint32_t sA0 = smem_u32(&As[0][0]);
    const uint32_t sB0 = smem_u32(&Bs[0][0]);

    float acc[2][8][4];
    #pragma unroll
    for (int i = 0; i < 2; i++)
        #pragma unroll
        for (int j = 0; j < 8; j++)
            #pragma unroll
            for (int q = 0; q < 4; q++) acc[i][j][q] = 0.f;

    const int NC = K / 16;

    {
        CP16(sA0 + (r0 * LDSR + q0) * 4, gA + (size_t)r0 * K + q0);
        CP16(sA0 + (r1 * LDSR + q1) * 4, gA + (size_t)r1 * K + q1);
        CP16(sB0 + (r0 * LDSR + q0) * 4, gB + (size_t)r0 * K + q0);
        CP16(sB0 + (r1 * LDSR + q1) * 4, gB + (size_t)r1 * K + q1);
        CP_COMMIT();
    }

    for (int c = 0; c < NC; c++) {
        const int s = c & 1;
        if (c + 1 < NC) {
            const int ns = (c + 1) & 1;
            const int k0 = (c + 1) * 16;
            const uint32_t dA = sA0 + ns * 128 * LDSR * 4;
            const uint32_t dB = sB0 + ns * 128 * LDSR * 4;
            CP16(dA + (r0 * LDSR + q0) * 4, gA + (size_t)r0 * K + k0 + q0);
            CP16(dA + (r1 * LDSR + q1) * 4, gA + (size_t)r1 * K + k0 + q1);
            CP16(dB + (r0 * LDSR + q0) * 4, gB + (size_t)r0 * K + k0 + q0);
            CP16(dB + (r1 * LDSR + q1) * 4, gB + (size_t)r1 * K + k0 + q1);
            CP_COMMIT();
            CP_WAIT(1);
        } else {
            CP_WAIT(0);
        }
        __syncthreads();

        const float* as = &As[s][0];
        const float* bs = &Bs[s][0];
        #pragma unroll
        for (int ks = 0; ks < 2; ks++) {
            const int kb = ks * 8;
            uint32_t a[2][4];
            #pragma unroll
            for (int mt = 0; mt < 2; mt++) {
                const int row = wm + mt * 16;
                a[mt][0] = __float_as_uint(as[(row + g)     * LDSR + kb + tg]);
                a[mt][1] = __float_as_uint(as[(row + g + 8) * LDSR + kb + tg]);
                a[mt][2] = __float_as_uint(as[(row + g)     * LDSR + kb + tg + 4]);
                a[mt][3] = __float_as_uint(as[(row + g + 8) * LDSR + kb + tg + 4]);
            }
            #pragma unroll
            for (int nt = 0; nt < 8; nt++) {
                const int col = wn + nt * 8;
                uint32_t b0 = __float_as_uint(bs[(col + g) * LDSR + kb + tg]);
                uint32_t b1 = __float_as_uint(bs[(col + g) * LDSR + kb + tg + 4]);
                mma8(acc[0][nt], a[0], b0, b1);
                mma8(acc[1][nt], a[1], b0, b1);
            }
        }
        __syncthreads();
    }

    const bool doRound = (bx >= roundFrom);
    #pragma unroll
    for (int mt = 0; mt < 2; mt++) {
        const size_t rowA = (size_t)(by * 128 + wm + mt * 16 + g);
        #pragma unroll
        for (int nt = 0; nt < 8; nt++) {
            const int col = bx * 128 + wn + nt * 8 + 2 * tg;
            float v0 = acc[mt][nt][0], v1 = acc[mt][nt][1];
            float v2 = acc[mt][nt][2], v3 = acc[mt][nt][3];
            if (doRound) {
                v0 = to_tf32(v0); v1 = to_tf32(v1);
                v2 = to_tf32(v2); v3 = to_tf32(v3);
            }
            *(float2*)(C + rowA * N + col)       = make_float2(v0, v1);
            *(float2*)(C + (rowA + 8) * N + col) = make_float2(v2, v3);
        }
    }
}

// ---------------------------------------------------------------------------
// Transpose + tf32 rounding prologue kernels (unchanged)
// ---------------------------------------------------------------------------
__global__ void transpose32(const float* __restrict__ in, float* __restrict__ out,
                            int rows, int cols)
{
    __shared__ float t[32][33];
    const int bx = blockIdx.x * 32, by = blockIdx.y * 32;
    #pragma unroll
    for (int i = threadIdx.y; i < 32; i += 8)
        t[i][threadIdx.x] = in[(size_t)(by + i) * cols + bx + threadIdx.x];
    __syncthreads();
    #pragma unroll
    for (int i = threadIdx.y; i < 32; i += 8)
        out[(size_t)(bx + i) * rows + by + threadIdx.x] = to_tf32(t[threadIdx.x][i]);
}

__global__ void round_tf32_vec(const float* __restrict__ in, float* __restrict__ out, int n4)
{
    int i = blockIdx.x * blockDim.x + threadIdx.x;
    if (i < n4) {
        float4 v = ((const float4*)in)[i];
        v.x = to_tf32(v.x); v.y = to_tf32(v.y); v.z = to_tf32(v.z); v.w = to_tf32(v.w);
        ((float4*)out)[i] = v;
    }
}

// ---------------------------------------------------------------------------
// Tensor-core flash attention (causal).
// K,V arrive tf32-pre-rounded (QKV gemm epilogue). Q exact, split hi/lo:
//   S = qh*K + ql*K            (2 mma, err ~= K rounding 2.8e-4)
//   P rounded to tf32; O += P*V (1 mma, err ~= P,V rounding ~4e-4)
// grid: (T/64, B*NH), block 128 (4 warps), warp = 16 query rows.
// ---------------------------------------------------------------------------
#define PADK 68
#define PADV 72
#define FA_KS_BYTES (64 * PADK * 4)            // 17408
#define FA_VS_BYTES (64 * PADV * 4)            // 18432
#define FA_SMEM (2 * FA_KS_BYTES + 2 * FA_VS_BYTES + FA_KS_BYTES)  // 89088

__global__ __launch_bounds__(128) void flash_attn_mma(
    const float* __restrict__ qkv, float* __restrict__ ao)
{
    extern __shared__ char sm[];
    float* KsBase = (float*)sm;                                  // [2][64][PADK]
    float* VsBase = (float*)(sm + 2 * FA_KS_BYTES);              // [2][64][PADV]
    float* Ps     = (float*)(sm + 2 * FA_KS_BYTES + 2 * FA_VS_BYTES); // [64][PADK]

    const int qb   = (gridDim.x - 1) - blockIdx.x;  // heavy blocks first
    const int bh   = blockIdx.y;
    const int b    = bh >> 4;
    const int h    = bh & 15;
    const int tid  = threadIdx.x;
    const int lane = tid & 31;
    const int wid  = tid >> 5;
    const int g    = lane >> 2;
    const int tg   = lane & 3;
    const int r0   = wid * 16;                      // warp's row base within tile

    const uint32_t ksb = smem_u32(KsBase);
    const uint32_t vsb = smem_u32(VsBase);

    // ---- issue cp.async for K/V tile 0 into buffer 0 ----
    const size_t rowbase = (size_t)(b * TT);
    {
        const float* kb0 = qkv + (rowbase + 0) * NQKV + DM + h * DH;
        #pragma unroll
        for (int i = 0; i < 8; i++) {
            int f4 = tid + i * 128;
            int row = f4 >> 4;
            int col = (f4 & 15) * 4;
            CP16(ksb + (uint32_t)(row * PADK + col) * 4, kb0 + (size_t)row * NQKV + col);
            CP16(vsb + (uint32_t)(row * PADV + col) * 4, kb0 + (size_t)row * NQKV + DM + col);
        }
        CP_COMMIT();
    }

    // ---- load Q fragments into registers, split hi/lo (overlaps cp.async) ----
    float qh[8][4], ql[8][4];
    {
        const float* qp = qkv + (rowbase + (size_t)(qb * 64 + r0)) * NQKV + h * DH;
        #pragma unroll
        for (int kc = 0; kc < 8; kc++) {
            #pragma unroll
            for (int e = 0; e < 4; e++) {
                int dr = (e & 1) * 8;          // a0,a2 -> row g ; a1,a3 -> row g+8
                int dc = (e >> 1) * 4;         // a0,a1 -> k tg ; a2,a3 -> k tg+4
                float v = qp[(size_t)(g + dr) * NQKV + kc * 8 + tg + dc] * 0.125f;
                float hi = to_tf32(v);
                qh[kc][e] = hi;
                ql[kc][e] = v - hi;
            }
        }
    }

    float O[8][4];
    #pragma unroll
    for (int nc = 0; nc < 8; nc++)
        #pragma unroll
        for (int e = 0; e < 4; e++) O[nc][e] = 0.f;
    float m0 = -1e30f, m1 = -1e30f, l0 = 0.f, l1 = 0.f;  // l0,l1 thread-partial

    for (int kb = 0; kb <= qb; kb++) {
        const int buf = kb & 1;
        // prefetch next tile
        if (kb < qb) {
            const int nbuf = buf ^ 1;
            const float* kbn = qkv + (rowbase + (size_t)((kb + 1) * 64)) * NQKV + DM + h * DH;
            const uint32_t kd = ksb + (uint32_t)nbuf * FA_KS_BYTES;
            const uint32_t vd = vsb + (uint32_t)nbuf * FA_VS_BYTES;
            #pragma unroll
            for (int i = 0; i < 8; i++) {
                int f4 = tid + i * 128;
                int row = f4 >> 4;
                int col = (f4 & 15) * 4;
                CP16(kd + (uint32_t)(row * PADK + col) * 4, kbn + (size_t)row * NQKV + col);
                CP16(vd + (uint32_t)(row * PADV + col) * 4, kbn + (size_t)row * NQKV + DM + col);
            }
            CP_COMMIT();
            CP_WAIT(1);   // tile kb complete (next still in flight)
        } else {
            CP_WAIT(0);
        }
        __syncthreads();

        const float* Ks = KsBase + buf * (64 * PADK);
        const float* Vs = VsBase + buf * (64 * PADV);

        // ---- S = (Q*scale) K^T : 2-term (Q exact via split, K pre-rounded) ----
        float Sc[8][4];
        #pragma unroll
        for (int nc = 0; nc < 8; nc++)
            #pragma unroll
            for (int e = 0; e < 4; e++) Sc[nc][e] = 0.f;

        #pragma unroll
        for (int kc = 0; kc < 8; kc++) {
            #pragma unroll
            for (int nc = 0; nc < 8; nc++) {
                float kv0 = Ks[(nc * 8 + g) * PADK + kc * 8 + tg];
                float kv1 = Ks[(nc * 8 + g) * PADK + kc * 8 + tg + 4];
                mma8f(Sc[nc], qh[kc], kv0, kv1);
                mma8f(Sc[nc], ql[kc], kv0, kv1);
            }
        }

        // ---- causal mask on diagonal tile ----
        if (kb == qb) {
            const int i0 = r0 + g, i1 = r0 + g + 8;
            #pragma unroll
            for (int nc = 0; nc < 8; nc++) {
                int j = nc * 8 + 2 * tg;
                if (j     > i0) Sc[nc][0] = -1e30f;
                if (j + 1 > i0) Sc[nc][1] = -1e30f;
                if (j     > i1) Sc[nc][2] = -1e30f;
                if (j + 1 > i1) Sc[nc][3] = -1e30f;
            }
        }

        // ---- online softmax (row max via quad shfl; l kept thread-partial) ----
        float rx0 = -1e30f, rx1 = -1e30f;
        #pragma unroll
        for (int nc = 0; nc < 8; nc++) {
            rx0 = fmaxf(rx0, fmaxf(Sc[nc][0], Sc[nc][1]));
            rx1 = fmaxf(rx1, fmaxf(Sc[nc][2], Sc[nc][3]));
        }
        rx0 = fmaxf(rx0, __shfl_xor_sync(0xFFFFFFFF, rx0, 1));
        rx0 = fmaxf(rx0, __shfl_xor_sync(0xFFFFFFFF, rx0, 2));
        rx1 = fmaxf(rx1, __shfl_xor_sync(0xFFFFFFFF, rx1, 1));
        rx1 = fmaxf(rx1, __shfl_xor_sync(0xFFFFFFFF, rx1, 2));

        const float mn0 = fmaxf(m0, rx0);
        const float mn1 = fmaxf(m1, rx1);
        const float a0 = __expf(m0 - mn0);
        const float a1 = __expf(m1 - mn1);
        m0 = mn0; m1 = mn1;

        // exp, round P to tf32 (consistent: l sums the rounded values)
        float s0 = 0.f, s1 = 0.f;
        #pragma unroll
        for (int nc = 0; nc < 8; nc++) {
            Sc[nc][0] = to_tf32(__expf(Sc[nc][0] - mn0));
            Sc[nc][1] = to_tf32(__expf(Sc[nc][1] - mn0));
            Sc[nc][2] = to_tf32(__expf(Sc[nc][2] - mn1));
            Sc[nc][3] = to_tf32(__expf(Sc[nc][3] - mn1));
            s0 += Sc[nc][0] + Sc[nc][1];
            s1 += Sc[nc][2] + Sc[nc][3];
        }
        l0 = l0 * a0 + s0;
        l1 = l1 * a1 + s1;

        #pragma unroll
        for (int nc = 0; nc < 8; nc++) {
            O[nc][0] *= a0; O[nc][1] *= a0;
            O[nc][2] *= a1; O[nc][3] *= a1;
        }

        // ---- P -> smem (per-warp region), then O += P V (1 mma, both rounded) ----
        #pragma unroll
        for (int nc = 0; nc < 8; nc++) {
            *(float2*)&Ps[(r0 + g)     * PADK + nc * 8 + 2 * tg] = make_float2(Sc[nc][0], Sc[nc][1]);
            *(float2*)&Ps[(r0 + g + 8) * PADK + nc * 8 + 2 * tg] = make_float2(Sc[nc][2], Sc[nc][3]);
        }
        __syncwarp();

        #pragma unroll
        for (int kc = 0; kc < 8; kc++) {
            float pf[4];
            #pragma unroll
            for (int e = 0; e < 4; e++) {
                int dr = (e & 1) * 8;
                int dc = (e >> 1) * 4;
                pf[e] = Ps[(r0 + g + dr) * PADK + kc * 8 + tg + dc];
            }
            #pragma unroll
            for (int nc = 0; nc < 8; nc++) {
                float vv0 = Vs[(kc * 8 + tg)     * PADV + nc * 8 + g];
                float vv1 = Vs[(kc * 8 + tg + 4) * PADV + nc * 8 + g];
                mma8f(O[nc], pf, vv0, vv1);
            }
        }
        __syncwarp();
        __syncthreads();   // all warps done with this K/V buffer
    }

    // ---- final l reduction across quad, normalize + write (tf32-rounded) ----
    l0 += __shfl_xor_sync(0xFFFFFFFF, l0, 1);
    l0 += __shfl_xor_sync(0xFFFFFFFF, l0, 2);
    l1 += __shfl_xor_sync(0xFFFFFFFF, l1, 1);
    l1 += __shfl_xor_sync(0xFFFFFFFF, l1, 2);
    const float inv0 = 1.f / l0;
    const float inv1 = 1.f / l1;
    float* op0 = ao + (rowbase + (size_t)(qb * 64 + r0 + g))     * DM + h * DH;
    float* op1 = ao + (rowbase + (size_t)(qb * 64 + r0 + g + 8)) * DM + h * DH;
    #pragma unroll
    for (int nc = 0; nc < 8; nc++) {
        *(float2*)(op0 + nc * 8 + 2 * tg) =
            make_float2(to_tf32(O[nc][0] * inv0), to_tf32(O[nc][1] * inv0));
        *(float2*)(op1 + nc * 8 + 2 * tg) =
            make_float2(to_tf32(O[nc][2] * inv1), to_tf32(O[nc][3] * inv1));
    }
}

// ---------------------------------------------------------------------------
extern "C" void kernel_launch(void* const* d_in, const int* in_sizes, int n_in,
                              void* d_out, int out_size)
{
    const float* x    = (const float*)d_in[0];   // [B,T,1024]
    const float* Wqkv = (const float*)d_in[1];   // [1024,3072]
    const float* Wout = (const float*)d_in[2];   // [1024,1024]
    float* out = (float*)d_out;

    float *qkv, *ao, *xr, *wtq, *wto;
    cudaGetSymbolAddress((void**)&qkv, g_qkv);
    cudaGetSymbolAddress((void**)&ao,  g_ao);
    cudaGetSymbolAddress((void**)&xr,  g_xr);
    cudaGetSymbolAddress((void**)&wtq, g_wtq);
    cudaGetSymbolAddress((void**)&wto, g_wto);

    cudaFuncSetAttribute(flash_attn_mma, cudaFuncAttributeMaxDynamicSharedMemorySize, FA_SMEM);

    // Pre-round / pre-transpose GEMM operands to tf32
    round_tf32_vec<<<(BT * DM / 4 + 255) / 256, 256>>>(x, xr, BT * DM / 4);
    transpose32<<<dim3(NQKV / 32, DM / 32), dim3(32, 8)>>>(Wqkv, wtq, DM, NQKV);
    transpose32<<<dim3(DM / 32, DM / 32), dim3(32, 8)>>>(Wout, wto, DM, DM);

    // 1) QKV projection; K,V output columns (bx>=8 <=> col>=1024) tf32-rounded
    gemm_mma<<<dim3(NQKV / 128, BT / 128), 256>>>(xr, wtq, qkv, BT, NQKV, DM, 8);

    // 2) Causal flash attention (tensor-core, reduced-mma path)
    flash_attn_mma<<<dim3(TT / 64, BB * NH), 128, FA_SMEM>>>(qkv, ao);

    // 3) Output projection (no rounding of final output)
    gemm_mma<<<dim3(DM / 128, BT / 128), 256>>>(ao, wto, out, BT, DM, DM, 1 << 30);
}

// round 7
// speedup vs baseline: 3.9404x; 1.0627x over previous
#include <cuda_runtime.h>
#include <cuda_bf16.h>
#include <math.h>
#include <stdint.h>

// Problem constants
#define BB      4
#define TT      2048
#define DM      1024
#define NH      16
#define DH      64
#define BT      (BB * TT)        // 8192 rows
#define NQKV    (3 * DM)         // 3072

// Scratch (alloc-free rule: __device__ globals)
__device__ float g_qkv[(size_t)BT * NQKV];   // 100.7 MB
__device__ float g_ao [(size_t)BT * DM];     //  33.6 MB
__device__ float g_xr [(size_t)BT * DM];     //  33.6 MB (x rounded to tf32)
__device__ float g_wtq[(size_t)NQKV * DM];   //  12.6 MB (Wqkv^T, tf32-rounded)
__device__ float g_wto[(size_t)DM * DM];     //   4.2 MB (Wout^T, tf32-rounded)

// ---------------------------------------------------------------------------
// Helpers
// ---------------------------------------------------------------------------
__device__ __forceinline__ uint32_t smem_u32(const void* p) {
    uint32_t a;
    asm("{ .reg .u64 t; cvta.to.shared.u64 t, %1; cvt.u32.u64 %0, t; }" : "=r"(a) : "l"(p));
    return a;
}
__device__ __forceinline__ float to_tf32(float v) {
    uint32_t r;
    asm("cvt.rna.tf32.f32 %0, %1;" : "=r"(r) : "f"(v));
    return __uint_as_float(r);
}

#define CP16(dst, src)  asm volatile("cp.async.cg.shared.global [%0], [%1], 16;" :: "r"(dst), "l"(src))
#define CP_COMMIT()     asm volatile("cp.async.commit_group;")
#define CP_WAIT(n)      asm volatile("cp.async.wait_group %0;" :: "n"(n))

// m16n8k8 tf32 mma: D += A*B  (A row-major m16k8, B col-major k8n8)
__device__ __forceinline__ void mma8(float* d, const uint32_t* a, uint32_t b0, uint32_t b1) {
    asm volatile(
        "mma.sync.aligned.m16n8k8.row.col.f32.tf32.tf32.f32 "
        "{%0,%1,%2,%3}, {%4,%5,%6,%7}, {%8,%9}, {%0,%1,%2,%3};"
        : "+f"(d[0]), "+f"(d[1]), "+f"(d[2]), "+f"(d[3])
        : "r"(a[0]), "r"(a[1]), "r"(a[2]), "r"(a[3]), "r"(b0), "r"(b1));
}
__device__ __forceinline__ void mma8f(float* d, const float* a, float b0, float b1) {
    asm volatile(
        "mma.sync.aligned.m16n8k8.row.col.f32.tf32.tf32.f32 "
        "{%0,%1,%2,%3}, {%4,%5,%6,%7}, {%8,%9}, {%0,%1,%2,%3};"
        : "+f"(d[0]), "+f"(d[1]), "+f"(d[2]), "+f"(d[3])
        : "r"(__float_as_uint(a[0])), "r"(__float_as_uint(a[1])),
          "r"(__float_as_uint(a[2])), "r"(__float_as_uint(a[3])),
          "r"(__float_as_uint(b0)),  "r"(__float_as_uint(b1)));
}

// ---------------------------------------------------------------------------
// Tensor-core tf32 GEMM (97.5% of mma.sync issue floor — DO NOT TOUCH).
// Output columns >= roundFrom*128 are written tf32-rounded.
// ---------------------------------------------------------------------------
#define LDSR 20
__global__ __launch_bounds__(256, 2) void gemm_mma(
    const float* __restrict__ A, const float* __restrict__ Bt, float* __restrict__ C,
    int M, int N, int K, int roundFrom)
{
    __shared__ float As[2][128 * LDSR];
    __shared__ float Bs[2][128 * LDSR];

    const int tid  = threadIdx.x;
    const int lane = tid & 31;
    const int wid  = tid >> 5;
    const int wm   = (wid >> 1) * 32;
    const int wn   = (wid & 1) * 64;
    const int g    = lane >> 2;
    const int tg   = lane & 3;

    const int bx = blockIdx.x, by = blockIdx.y;

    const int f0 = tid, f1 = tid + 256;
    const int r0 = f0 >> 2, q0 = (f0 & 3) * 4;
    const int r1 = f1 >> 2, q1 = (f1 & 3) * 4;
    const float* gA = A  + (size_t)(by * 128) * K;
    const float* gB = Bt + (size_t)(bx * 128) * K;

    const uint32_t sA0 = smem_u32(&As[0][0]);
    const uint32_t sB0 = smem_u32(&Bs[0][0]);

    float acc[2][8][4];
    #pragma unroll
    for (int i = 0; i < 2; i++)
        #pragma unroll
        for (int j = 0; j < 8; j++)
            #pragma unroll
            for (int q = 0; q < 4; q++) acc[i][j][q] = 0.f;

    const int NC = K / 16;

    {
        CP16(sA0 + (r0 * LDSR + q0) * 4, gA + (size_t)r0 * K + q0);
        CP16(sA0 + (r1 * LDSR + q1) * 4, gA + (size_t)r1 * K + q1);
        CP16(sB0 + (r0 * LDSR + q0) * 4, gB + (size_t)r0 * K + q0);
        CP16(sB0 + (r1 * LDSR + q1) * 4, gB + (size_t)r1 * K + q1);
        CP_COMMIT();
    }

    for (int c = 0; c < NC; c++) {
        const int s = c & 1;
        if (c + 1 < NC) {
            const int ns = (c + 1) & 1;
            const int k0 = (c + 1) * 16;
            const uint32_t dA = sA0 + ns * 128 * LDSR * 4;
            const uint32_t dB = sB0 + ns * 128 * LDSR * 4;
            CP16(dA + (r0 * LDSR + q0) * 4, gA + (size_t)r0 * K + k0 + q0);
            CP16(dA + (r1 * LDSR + q1) * 4, gA + (size_t)r1 * K + k0 + q1);
            CP16(dB + (r0 * LDSR + q0) * 4, gB + (size_t)r0 * K + k0 + q0);
            CP16(dB + (r1 * LDSR + q1) * 4, gB + (size_t)r1 * K + k0 + q1);
            CP_COMMIT();
            CP_WAIT(1);
        } else {
            CP_WAIT(0);
        }
        __syncthreads();

        const float* as = &As[s][0];
        const float* bs = &Bs[s][0];
        #pragma unroll
        for (int ks = 0; ks < 2; ks++) {
            const int kb = ks * 8;
            uint32_t a[2][4];
            #pragma unroll
            for (int mt = 0; mt < 2; mt++) {
                const int row = wm + mt * 16;
                a[mt][0] = __float_as_uint(as[(row + g)     * LDSR + kb + tg]);
                a[mt][1] = __float_as_uint(as[(row + g + 8) * LDSR + kb + tg]);
                a[mt][2] = __float_as_uint(as[(row + g)     * LDSR + kb + tg + 4]);
                a[mt][3] = __float_as_uint(as[(row + g + 8) * LDSR + kb + tg + 4]);
            }
            #pragma unroll
            for (int nt = 0; nt < 8; nt++) {
                const int col = wn + nt * 8;
                uint32_t b0 = __float_as_uint(bs[(col + g) * LDSR + kb + tg]);
                uint32_t b1 = __float_as_uint(bs[(col + g) * LDSR + kb + tg + 4]);
                mma8(acc[0][nt], a[0], b0, b1);
                mma8(acc[1][nt], a[1], b0, b1);
            }
        }
        __syncthreads();
    }

    const bool doRound = (bx >= roundFrom);
    #pragma unroll
    for (int mt = 0; mt < 2; mt++) {
        const size_t rowA = (size_t)(by * 128 + wm + mt * 16 + g);
        #pragma unroll
        for (int nt = 0; nt < 8; nt++) {
            const int col = bx * 128 + wn + nt * 8 + 2 * tg;
            float v0 = acc[mt][nt][0], v1 = acc[mt][nt][1];
            float v2 = acc[mt][nt][2], v3 = acc[mt][nt][3];
            if (doRound) {
                v0 = to_tf32(v0); v1 = to_tf32(v1);
                v2 = to_tf32(v2); v3 = to_tf32(v3);
            }
            *(float2*)(C + rowA * N + col)       = make_float2(v0, v1);
            *(float2*)(C + (rowA + 8) * N + col) = make_float2(v2, v3);
        }
    }
}

// ---------------------------------------------------------------------------
// Transpose + tf32 rounding prologue kernels (unchanged)
// ---------------------------------------------------------------------------
__global__ void transpose32(const float* __restrict__ in, float* __restrict__ out,
                            int rows, int cols)
{
    __shared__ float t[32][33];
    const int bx = blockIdx.x * 32, by = blockIdx.y * 32;
    #pragma unroll
    for (int i = threadIdx.y; i < 32; i += 8)
        t[i][threadIdx.x] = in[(size_t)(by + i) * cols + bx + threadIdx.x];
    __syncthreads();
    #pragma unroll
    for (int i = threadIdx.y; i < 32; i += 8)
        out[(size_t)(bx + i) * rows + by + threadIdx.x] = to_tf32(t[threadIdx.x][i]);
}

__global__ void round_tf32_vec(const float* __restrict__ in, float* __restrict__ out, int n4)
{
    int i = blockIdx.x * blockDim.x + threadIdx.x;
    if (i < n4) {
        float4 v = ((const float4*)in)[i];
        v.x = to_tf32(v.x); v.y = to_tf32(v.y); v.z = to_tf32(v.z); v.w = to_tf32(v.w);
        ((float4*)out)[i] = v;
    }
}

// ---------------------------------------------------------------------------
// Tensor-core flash attention (causal).
// Q,K,V all arrive tf32-pre-rounded (QKV gemm epilogue, roundFrom=0):
//   S = Q K^T             (1 mma per 16x8 block)
//   P rounded to tf32; O += P V (1 mma)
// grid: (T/64, B*NH), block 128 (4 warps), warp = 16 query rows.
// ---------------------------------------------------------------------------
#define PADK 68
#define PADV 72
#define FA_KS_BYTES (64 * PADK * 4)            // 17408
#define FA_VS_BYTES (64 * PADV * 4)            // 18432
#define FA_SMEM (2 * FA_KS_BYTES + 2 * FA_VS_BYTES + FA_KS_BYTES)  // 89088

__global__ __launch_bounds__(128) void flash_attn_mma(
    const float* __restrict__ qkv, float* __restrict__ ao)
{
    extern __shared__ char sm[];
    float* KsBase = (float*)sm;                                  // [2][64][PADK]
    float* VsBase = (float*)(sm + 2 * FA_KS_BYTES);              // [2][64][PADV]
    float* Ps     = (float*)(sm + 2 * FA_KS_BYTES + 2 * FA_VS_BYTES); // [64][PADK]

    const int qb   = (gridDim.x - 1) - blockIdx.x;  // heavy blocks first
    const int bh   = blockIdx.y;
    const int b    = bh >> 4;
    const int h    = bh & 15;
    const int tid  = threadIdx.x;
    const int lane = tid & 31;
    const int wid  = tid >> 5;
    const int g    = lane >> 2;
    const int tg   = lane & 3;
    const int r0   = wid * 16;                      // warp's row base within tile

    const uint32_t ksb = smem_u32(KsBase);
    const uint32_t vsb = smem_u32(VsBase);

    // ---- issue cp.async for K/V tile 0 into buffer 0 ----
    const size_t rowbase = (size_t)(b * TT);
    {
        const float* kb0 = qkv + (rowbase + 0) * NQKV + DM + h * DH;
        #pragma unroll
        for (int i = 0; i < 8; i++) {
            int f4 = tid + i * 128;
            int row = f4 >> 4;
            int col = (f4 & 15) * 4;
            CP16(ksb + (uint32_t)(row * PADK + col) * 4, kb0 + (size_t)row * NQKV + col);
            CP16(vsb + (uint32_t)(row * PADV + col) * 4, kb0 + (size_t)row * NQKV + DM + col);
        }
        CP_COMMIT();
    }

    // ---- load Q fragments (already tf32; *0.125 is exact) ----
    float qf[8][4];
    {
        const float* qp = qkv + (rowbase + (size_t)(qb * 64 + r0)) * NQKV + h * DH;
        #pragma unroll
        for (int kc = 0; kc < 8; kc++) {
            #pragma unroll
            for (int e = 0; e < 4; e++) {
                int dr = (e & 1) * 8;          // a0,a2 -> row g ; a1,a3 -> row g+8
                int dc = (e >> 1) * 4;         // a0,a1 -> k tg ; a2,a3 -> k tg+4
                qf[kc][e] = qp[(size_t)(g + dr) * NQKV + kc * 8 + tg + dc] * 0.125f;
            }
        }
    }

    float O[8][4];
    #pragma unroll
    for (int nc = 0; nc < 8; nc++)
        #pragma unroll
        for (int e = 0; e < 4; e++) O[nc][e] = 0.f;
    float m0 = -1e30f, m1 = -1e30f, l0 = 0.f, l1 = 0.f;  // l thread-partial

    for (int kb = 0; kb <= qb; kb++) {
        const int buf = kb & 1;
        // prefetch next tile
        if (kb < qb) {
            const int nbuf = buf ^ 1;
            const float* kbn = qkv + (rowbase + (size_t)((kb + 1) * 64)) * NQKV + DM + h * DH;
            const uint32_t kd = ksb + (uint32_t)nbuf * FA_KS_BYTES;
            const uint32_t vd = vsb + (uint32_t)nbuf * FA_VS_BYTES;
            #pragma unroll
            for (int i = 0; i < 8; i++) {
                int f4 = tid + i * 128;
                int row = f4 >> 4;
                int col = (f4 & 15) * 4;
                CP16(kd + (uint32_t)(row * PADK + col) * 4, kbn + (size_t)row * NQKV + col);
                CP16(vd + (uint32_t)(row * PADV + col) * 4, kbn + (size_t)row * NQKV + DM + col);
            }
            CP_COMMIT();
            CP_WAIT(1);   // tile kb complete (next still in flight)
        } else {
            CP_WAIT(0);
        }
        __syncthreads();

        const float* Ks = KsBase + buf * (64 * PADK);
        const float* Vs = VsBase + buf * (64 * PADV);

        // ---- S = (Q*scale) K^T : 1 mma (both operands tf32-pre-rounded) ----
        float Sc[8][4];
        #pragma unroll
        for (int nc = 0; nc < 8; nc++)
            #pragma unroll
            for (int e = 0; e < 4; e++) Sc[nc][e] = 0.f;

        #pragma unroll
        for (int kc = 0; kc < 8; kc++) {
            #pragma unroll
            for (int nc = 0; nc < 8; nc++) {
                float kv0 = Ks[(nc * 8 + g) * PADK + kc * 8 + tg];
                float kv1 = Ks[(nc * 8 + g) * PADK + kc * 8 + tg + 4];
                mma8f(Sc[nc], qf[kc], kv0, kv1);
            }
        }

        // ---- causal mask on diagonal tile ----
        if (kb == qb) {
            const int i0 = r0 + g, i1 = r0 + g + 8;
            #pragma unroll
            for (int nc = 0; nc < 8; nc++) {
                int j = nc * 8 + 2 * tg;
                if (j     > i0) Sc[nc][0] = -1e30f;
                if (j + 1 > i0) Sc[nc][1] = -1e30f;
                if (j     > i1) Sc[nc][2] = -1e30f;
                if (j + 1 > i1) Sc[nc][3] = -1e30f;
            }
        }

        // ---- online softmax (row max via quad shfl; l kept thread-partial) ----
        float rx0 = -1e30f, rx1 = -1e30f;
        #pragma unroll
        for (int nc = 0; nc < 8; nc++) {
            rx0 = fmaxf(rx0, fmaxf(Sc[nc][0], Sc[nc][1]));
            rx1 = fmaxf(rx1, fmaxf(Sc[nc][2], Sc[nc][3]));
        }
        rx0 = fmaxf(rx0, __shfl_xor_sync(0xFFFFFFFF, rx0, 1));
        rx0 = fmaxf(rx0, __shfl_xor_sync(0xFFFFFFFF, rx0, 2));
        rx1 = fmaxf(rx1, __shfl_xor_sync(0xFFFFFFFF, rx1, 1));
        rx1 = fmaxf(rx1, __shfl_xor_sync(0xFFFFFFFF, rx1, 2));

        const float mn0 = fmaxf(m0, rx0);
        const float mn1 = fmaxf(m1, rx1);
        const float a0 = __expf(m0 - mn0);
        const float a1 = __expf(m1 - mn1);
        m0 = mn0; m1 = mn1;

        // exp, round P to tf32 (consistent: l sums the rounded values)
        float s0 = 0.f, s1 = 0.f;
        #pragma unroll
        for (int nc = 0; nc < 8; nc++) {
            Sc[nc][0] = to_tf32(__expf(Sc[nc][0] - mn0));
            Sc[nc][1] = to_tf32(__expf(Sc[nc][1] - mn0));
            Sc[nc][2] = to_tf32(__expf(Sc[nc][2] - mn1));
            Sc[nc][3] = to_tf32(__expf(Sc[nc][3] - mn1));
            s0 += Sc[nc][0] + Sc[nc][1];
            s1 += Sc[nc][2] + Sc[nc][3];
        }
        l0 = l0 * a0 + s0;
        l1 = l1 * a1 + s1;

        #pragma unroll
        for (int nc = 0; nc < 8; nc++) {
            O[nc][0] *= a0; O[nc][1] *= a0;
            O[nc][2] *= a1; O[nc][3] *= a1;
        }

        // ---- P -> smem (per-warp region), then O += P V (1 mma, both rounded) ----
        #pragma unroll
        for (int nc = 0; nc < 8; nc++) {
            *(float2*)&Ps[(r0 + g)     * PADK + nc * 8 + 2 * tg] = make_float2(Sc[nc][0], Sc[nc][1]);
            *(float2*)&Ps[(r0 + g + 8) * PADK + nc * 8 + 2 * tg] = make_float2(Sc[nc][2], Sc[nc][3]);
        }
        __syncwarp();

        #pragma unroll
        for (int kc = 0; kc < 8; kc++) {
            float pf[4];
            #pragma unroll
            for (int e = 0; e < 4; e++) {
                int dr = (e & 1) * 8;
                int dc = (e >> 1) * 4;
                pf[e] = Ps[(r0 + g + dr) * PADK + kc * 8 + tg + dc];
            }
            #pragma unroll
            for (int nc = 0; nc < 8; nc++) {
                float vv0 = Vs[(kc * 8 + tg)     * PADV + nc * 8 + g];
                float vv1 = Vs[(kc * 8 + tg + 4) * PADV + nc * 8 + g];
                mma8f(O[nc], pf, vv0, vv1);
            }
        }
        __syncwarp();
        __syncthreads();   // all warps done with this K/V buffer
    }

    // ---- final l reduction across quad, normalize + write (tf32-rounded) ----
    l0 += __shfl_xor_sync(0xFFFFFFFF, l0, 1);
    l0 += __shfl_xor_sync(0xFFFFFFFF, l0, 2);
    l1 += __shfl_xor_sync(0xFFFFFFFF, l1, 1);
    l1 += __shfl_xor_sync(0xFFFFFFFF, l1, 2);
    const float inv0 = 1.f / l0;
    const float inv1 = 1.f / l1;
    float* op0 = ao + (rowbase + (size_t)(qb * 64 + r0 + g))     * DM + h * DH;
    float* op1 = ao + (rowbase + (size_t)(qb * 64 + r0 + g + 8)) * DM + h * DH;
    #pragma unroll
    for (int nc = 0; nc < 8; nc++) {
        *(float2*)(op0 + nc * 8 + 2 * tg) =
            make_float2(to_tf32(O[nc][0] * inv0), to_tf32(O[nc][1] * inv0));
        *(float2*)(op1 + nc * 8 + 2 * tg) =
            make_float2(to_tf32(O[nc][2] * inv1), to_tf32(O[nc][3] * inv1));
    }
}

// ---------------------------------------------------------------------------
extern "C" void kernel_launch(void* const* d_in, const int* in_sizes, int n_in,
                              void* d_out, int out_size)
{
    const float* x    = (const float*)d_in[0];   // [B,T,1024]
    const float* Wqkv = (const float*)d_in[1];   // [1024,3072]
    const float* Wout = (const float*)d_in[2];   // [1024,1024]
    float* out = (float*)d_out;

    float *qkv, *ao, *xr, *wtq, *wto;
    cudaGetSymbolAddress((void**)&qkv, g_qkv);
    cudaGetSymbolAddress((void**)&ao,  g_ao);
    cudaGetSymbolAddress((void**)&xr,  g_xr);
    cudaGetSymbolAddress((void**)&wtq, g_wtq);
    cudaGetSymbolAddress((void**)&wto, g_wto);

    cudaFuncSetAttribute(flash_attn_mma, cudaFuncAttributeMaxDynamicSharedMemorySize, FA_SMEM);

    // Pre-round / pre-transpose GEMM operands to tf32
    round_tf32_vec<<<(BT * DM / 4 + 255) / 256, 256>>>(x, xr, BT * DM / 4);
    transpose32<<<dim3(NQKV / 32, DM / 32), dim3(32, 8)>>>(Wqkv, wtq, DM, NQKV);
    transpose32<<<dim3(DM / 32, DM / 32), dim3(32, 8)>>>(Wout, wto, DM, DM);

    // 1) QKV projection; ALL outputs (Q,K,V) tf32-rounded in epilogue
    gemm_mma<<<dim3(NQKV / 128, BT / 128), 256>>>(xr, wtq, qkv, BT, NQKV, DM, 0);

    // 2) Causal flash attention (tensor-core, 1-term S + 1-term PV)
    flash_attn_mma<<<dim3(TT / 64, BB * NH), 128, FA_SMEM>>>(qkv, ao);

    // 3) Output projection (no rounding of final output)
    gemm_mma<<<dim3(DM / 128, BT / 128), 256>>>(ao, wto, out, BT, DM, DM, 1 << 30);
}

// round 8
// speedup vs baseline: 6.9741x; 1.7699x over previous
#include <cuda_runtime.h>
#include <cuda_fp16.h>
#include <math.h>
#include <stdint.h>

// Problem constants
#define BB      4
#define TT      2048
#define DM      1024
#define NH      16
#define DH      64
#define BT      (BB * TT)        // 8192 rows
#define NQKV    (3 * DM)         // 3072

// Scratch (alloc-free rule: __device__ globals)
__device__ __half g_qkv[(size_t)BT * NQKV];  // 50.3 MB (fp16)
__device__ __half g_ao [(size_t)BT * DM];    // 16.8 MB (fp16)
__device__ __half g_xh [(size_t)BT * DM];    // 16.8 MB (x in fp16)
__device__ __half g_wtq[(size_t)NQKV * DM];  //  6.3 MB (Wqkv^T fp16)
__device__ __half g_wto[(size_t)DM * DM];    //  2.1 MB (Wout^T fp16)

// ---------------------------------------------------------------------------
// Helpers
// ---------------------------------------------------------------------------
__device__ __forceinline__ uint32_t smem_u32(const void* p) {
    uint32_t a;
    asm("{ .reg .u64 t; cvta.to.shared.u64 t, %1; cvt.u32.u64 %0, t; }" : "=r"(a) : "l"(p));
    return a;
}

#define CP16(dst, src)  asm volatile("cp.async.cg.shared.global [%0], [%1], 16;" :: "r"(dst), "l"(src))
#define CP_COMMIT()     asm volatile("cp.async.commit_group;")
#define CP_WAIT(n)      asm volatile("cp.async.wait_group %0;" :: "n"(n))

// m16n8k16 fp16 mma, fp32 accumulate. A row-major (4 regs), B col-major (2 regs).
__device__ __forceinline__ void mma16h(float* d, const uint32_t* a, uint32_t b0, uint32_t b1) {
    asm volatile(
        "mma.sync.aligned.m16n8k16.row.col.f32.f16.f16.f32 "
        "{%0,%1,%2,%3}, {%4,%5,%6,%7}, {%8,%9}, {%0,%1,%2,%3};"
        : "+f"(d[0]), "+f"(d[1]), "+f"(d[2]), "+f"(d[3])
        : "r"(a[0]), "r"(a[1]), "r"(a[2]), "r"(a[3]), "r"(b0), "r"(b1));
}

// ldmatrix x2 transposed b16 (for V B-fragments)
__device__ __forceinline__ void ldsm_x2_t(uint32_t& r0, uint32_t& r1, uint32_t addr) {
    asm volatile("ldmatrix.sync.aligned.m8n8.x2.trans.shared.b16 {%0,%1}, [%2];"
        : "=r"(r0), "=r"(r1) : "r"(addr));
}

// ---------------------------------------------------------------------------
// fp16 tensor-core GEMM: C[M,N] = A[M,K] * Bt[N,K]^T  (A, Bt fp16 row-major)
// BM=BN=128, BK=32 halves, 256 threads (8 warps), warp tile 32x64,
// double-buffered cp.async. Smem rows padded to 40 halves (conflict-free).
// Output: fp16 (Ch) if Ch != nullptr, else fp32 (Cf).
// ---------------------------------------------------------------------------
#define GPAD 40
__global__ __launch_bounds__(256, 2) void gemm_h(
    const __half* __restrict__ A, const __half* __restrict__ Bt,
    float* __restrict__ Cf, __half* __restrict__ Ch,
    int M, int N, int K)
{
    __shared__ __half As[2][128 * GPAD];
    __shared__ __half Bs[2][128 * GPAD];

    const int tid  = threadIdx.x;
    const int lane = tid & 31;
    const int wid  = tid >> 5;
    const int wm   = (wid >> 1) * 32;
    const int wn   = (wid & 1) * 64;
    const int g    = lane >> 2;
    const int tg   = lane & 3;

    const int bx = blockIdx.x, by = blockIdx.y;

    // load map: 128 rows x 32 halves per operand; thread: row = tid>>1,
    // two cp16 at half-cols colb, colb+8 (colb = (tid&1)*16)
    const int lrow = tid >> 1;
    const int colb = (tid & 1) * 16;

    const __half* gA = A  + (size_t)(by * 128) * K;
    const __half* gB = Bt + (size_t)(bx * 128) * K;

    const uint32_t sA0 = smem_u32(&As[0][0]);
    const uint32_t sB0 = smem_u32(&Bs[0][0]);
    const uint32_t dOffA = (uint32_t)(lrow * GPAD + colb) * 2;

    float acc[2][8][4];
    #pragma unroll
    for (int i = 0; i < 2; i++)
        #pragma unroll
        for (int j = 0; j < 8; j++)
            #pragma unroll
            for (int q = 0; q < 4; q++) acc[i][j][q] = 0.f;

    const int NC = K / 32;

    {   // prologue: chunk 0 -> stage 0
        CP16(sA0 + dOffA,      gA + (size_t)lrow * K + colb);
        CP16(sA0 + dOffA + 16, gA + (size_t)lrow * K + colb + 8);
        CP16(sB0 + dOffA,      gB + (size_t)lrow * K + colb);
        CP16(sB0 + dOffA + 16, gB + (size_t)lrow * K + colb + 8);
        CP_COMMIT();
    }

    for (int c = 0; c < NC; c++) {
        const int s = c & 1;
        if (c + 1 < NC) {
            const int ns = (c + 1) & 1;
            const int k0 = (c + 1) * 32;
            const uint32_t dA = sA0 + (uint32_t)ns * 128 * GPAD * 2 + dOffA;
            const uint32_t dB = sB0 + (uint32_t)ns * 128 * GPAD * 2 + dOffA;
            CP16(dA,      gA + (size_t)lrow * K + k0 + colb);
            CP16(dA + 16, gA + (size_t)lrow * K + k0 + colb + 8);
            CP16(dB,      gB + (size_t)lrow * K + k0 + colb);
            CP16(dB + 16, gB + (size_t)lrow * K + k0 + colb + 8);
            CP_COMMIT();
            CP_WAIT(1);
        } else {
            CP_WAIT(0);
        }
        __syncthreads();

        const __half* as = &As[s][0];
        const __half* bs = &Bs[s][0];
        #pragma unroll
        for (int ks = 0; ks < 2; ks++) {
            const int kb = ks * 16;
            uint32_t a[2][4];
            #pragma unroll
            for (int mt = 0; mt < 2; mt++) {
                const int row = wm + mt * 16;
                a[mt][0] = *(const uint32_t*)&as[(row + g)     * GPAD + kb + 2 * tg];
                a[mt][1] = *(const uint32_t*)&as[(row + g + 8) * GPAD + kb + 2 * tg];
                a[mt][2] = *(const uint32_t*)&as[(row + g)     * GPAD + kb + 8 + 2 * tg];
                a[mt][3] = *(const uint32_t*)&as[(row + g + 8) * GPAD + kb + 8 + 2 * tg];
            }
            #pragma unroll
            for (int nt = 0; nt < 8; nt++) {
                const int col = wn + nt * 8;
                uint32_t b0 = *(const uint32_t*)&bs[(col + g) * GPAD + kb + 2 * tg];
                uint32_t b1 = *(const uint32_t*)&bs[(col + g) * GPAD + kb + 8 + 2 * tg];
                mma16h(acc[0][nt], a[0], b0, b1);
                mma16h(acc[1][nt], a[1], b0, b1);
            }
        }
        __syncthreads();
    }

    // epilogue
    #pragma unroll
    for (int mt = 0; mt < 2; mt++) {
        const size_t r0 = (size_t)(by * 128 + wm + mt * 16 + g);
        #pragma unroll
        for (int nt = 0; nt < 8; nt++) {
            const int col = bx * 128 + wn + nt * 8 + 2 * tg;
            if (Ch) {
                *(__half2*)(Ch + r0 * N + col) =
                    __floats2half2_rn(acc[mt][nt][0], acc[mt][nt][1]);
                *(__half2*)(Ch + (r0 + 8) * N + col) =
                    __floats2half2_rn(acc[mt][nt][2], acc[mt][nt][3]);
            } else {
                *(float2*)(Cf + r0 * N + col)       = make_float2(acc[mt][nt][0], acc[mt][nt][1]);
                *(float2*)(Cf + (r0 + 8) * N + col) = make_float2(acc[mt][nt][2], acc[mt][nt][3]);
            }
        }
    }
}

// ---------------------------------------------------------------------------
// Prologue kernels: fp32 -> fp16 convert, and transpose (fp32 in, fp16 out)
// ---------------------------------------------------------------------------
__global__ void f32_to_f16(const float4* __restrict__ in, __half2* __restrict__ out, int n4)
{
    int i = blockIdx.x * blockDim.x + threadIdx.x;
    if (i < n4) {
        float4 v = in[i];
        out[2 * i]     = __floats2half2_rn(v.x, v.y);
        out[2 * i + 1] = __floats2half2_rn(v.z, v.w);
    }
}

__global__ void transposeH(const float* __restrict__ in, __half* __restrict__ out,
                           int rows, int cols)
{
    __shared__ float t[32][33];
    const int bx = blockIdx.x * 32, by = blockIdx.y * 32;
    #pragma unroll
    for (int i = threadIdx.y; i < 32; i += 8)
        t[i][threadIdx.x] = in[(size_t)(by + i) * cols + bx + threadIdx.x];
    __syncthreads();
    #pragma unroll
    for (int i = threadIdx.y; i < 32; i += 8)
        out[(size_t)(bx + i) * rows + by + threadIdx.x] = __float2half_rn(t[threadIdx.x][i]);
}

// ---------------------------------------------------------------------------
// fp16 tensor-core flash attention (causal), fp32 softmax/accum.
// grid: (T/64, B*NH), block 128 (4 warps), warp = 16 query rows.
// K/V tiles 64x64 halves double-buffered (cp.async); V B-frags via
// ldmatrix.x2.trans; P staged fp16 in per-warp smem.
// ---------------------------------------------------------------------------
#define PADH 72
__global__ __launch_bounds__(128) void flash_attn_h(
    const __half* __restrict__ qkv, __half* __restrict__ ao)
{
    __shared__ __half Kh[2][64 * PADH];
    __shared__ __half Vh[2][64 * PADH];
    __shared__ __half Ph[64 * PADH];

    const int qb   = (gridDim.x - 1) - blockIdx.x;  // heavy blocks first
    const int bh   = blockIdx.y;
    const int b    = bh >> 4;
    const int h    = bh & 15;
    const int tid  = threadIdx.x;
    const int lane = tid & 31;
    const int wid  = tid >> 5;
    const int g    = lane >> 2;
    const int tg   = lane & 3;
    const int r0   = wid * 16;

    const uint32_t ksb = smem_u32(&Kh[0][0]);
    const uint32_t vsb = smem_u32(&Vh[0][0]);
    const size_t rowbase = (size_t)(b * TT);

    // cp.async map: 1024 cp16 per tile pair (512 K + 512 V), 8 per thread
    // f in [0,512): row = f>>3, half-col = (f&7)*8
    {
        const __half* kb0 = qkv + (rowbase + 0) * NQKV + DM + h * DH;
        #pragma unroll
        for (int i = 0; i < 8; i++) {
            int f  = tid + i * 128;
            int kv = f >> 9;               // 0 = K, 1 = V
            int f5 = f & 511;
            int row = f5 >> 3;
            int col = (f5 & 7) * 8;
            uint32_t dst = (kv ? vsb : ksb) + (uint32_t)(row * PADH + col) * 2;
            CP16(dst, kb0 + (size_t)row * NQKV + kv * DM + col);
        }
        CP_COMMIT();
    }

    // Q fragments (scaled by 0.125, exact in fp16)
    uint32_t qa[4][4];
    {
        const __half* qp = qkv + (rowbase + (size_t)(qb * 64 + r0)) * NQKV + h * DH;
        const __half2 sc = __floats2half2_rn(0.125f, 0.125f);
        #pragma unroll
        for (int kc = 0; kc < 4; kc++) {
            #pragma unroll
            for (int e = 0; e < 4; e++) {
                int dr = (e & 1) * 8;
                int dc = (e >> 1) * 8;
                __half2 v = *(const __half2*)(qp + (size_t)(g + dr) * NQKV + kc * 16 + dc + 2 * tg);
                v = __hmul2(v, sc);
                qa[kc][e] = *(const uint32_t*)&v;
            }
        }
    }

    float O[8][4];
    #pragma unroll
    for (int nc = 0; nc < 8; nc++)
        #pragma unroll
        for (int e = 0; e < 4; e++) O[nc][e] = 0.f;
    float m0 = -1e30f, m1 = -1e30f, l0 = 0.f, l1 = 0.f;

    const int vrow = lane & 15;   // ldmatrix row provider

    for (int kb = 0; kb <= qb; kb++) {
        const int buf = kb & 1;
        if (kb < qb) {
            const int nbuf = buf ^ 1;
            const __half* kbn = qkv + (rowbase + (size_t)((kb + 1) * 64)) * NQKV + DM + h * DH;
            const uint32_t kd = ksb + (uint32_t)nbuf * 64 * PADH * 2;
            const uint32_t vd = vsb + (uint32_t)nbuf * 64 * PADH * 2;
            #pragma unroll
            for (int i = 0; i < 8; i++) {
                int f  = tid + i * 128;
                int kv = f >> 9;
                int f5 = f & 511;
                int row = f5 >> 3;
                int col = (f5 & 7) * 8;
                uint32_t dst = (kv ? vd : kd) + (uint32_t)(row * PADH + col) * 2;
                CP16(dst, kbn + (size_t)row * NQKV + kv * DM + col);
            }
            CP_COMMIT();
            CP_WAIT(1);
        } else {
            CP_WAIT(0);
        }
        __syncthreads();

        const __half* Ks = &Kh[buf][0];
        const uint32_t vbase = vsb + (uint32_t)buf * 64 * PADH * 2
                             + (uint32_t)(vrow * PADH) * 2;

        // ---- S = (Q*scale) K^T : 32 fp16 mma ----
        float Sc[8][4];
        #pragma unroll
        for (int nc = 0; nc < 8; nc++)
            #pragma unroll
            for (int e = 0; e < 4; e++) Sc[nc][e] = 0.f;

        #pragma unroll
        for (int kc = 0; kc < 4; kc++) {
            #pragma unroll
            for (int nc = 0; nc < 8; nc++) {
                uint32_t b0 = *(const uint32_t*)&Ks[(nc * 8 + g) * PADH + kc * 16 + 2 * tg];
                uint32_t b1 = *(const uint32_t*)&Ks[(nc * 8 + g) * PADH + kc * 16 + 8 + 2 * tg];
                mma16h(Sc[nc], qa[kc], b0, b1);
            }
        }

        // ---- causal mask on diagonal tile ----
        if (kb == qb) {
            const int i0 = r0 + g, i1 = r0 + g + 8;
            #pragma unroll
            for (int nc = 0; nc < 8; nc++) {
                int j = nc * 8 + 2 * tg;
                if (j     > i0) Sc[nc][0] = -1e30f;
                if (j + 1 > i0) Sc[nc][1] = -1e30f;
                if (j     > i1) Sc[nc][2] = -1e30f;
                if (j + 1 > i1) Sc[nc][3] = -1e30f;
            }
        }

        // ---- online softmax ----
        float rx0 = -1e30f, rx1 = -1e30f;
        #pragma unroll
        for (int nc = 0; nc < 8; nc++) {
            rx0 = fmaxf(rx0, fmaxf(Sc[nc][0], Sc[nc][1]));
            rx1 = fmaxf(rx1, fmaxf(Sc[nc][2], Sc[nc][3]));
        }
        rx0 = fmaxf(rx0, __shfl_xor_sync(0xFFFFFFFF, rx0, 1));
        rx0 = fmaxf(rx0, __shfl_xor_sync(0xFFFFFFFF, rx0, 2));
        rx1 = fmaxf(rx1, __shfl_xor_sync(0xFFFFFFFF, rx1, 1));
        rx1 = fmaxf(rx1, __shfl_xor_sync(0xFFFFFFFF, rx1, 2));

        const float mn0 = fmaxf(m0, rx0);
        const float mn1 = fmaxf(m1, rx1);
        const float a0 = __expf(m0 - mn0);
        const float a1 = __expf(m1 - mn1);
        m0 = mn0; m1 = mn1;

        // exp -> fp16 P (l sums the fp16-rounded values), store to smem
        float s0 = 0.f, s1 = 0.f;
        #pragma unroll
        for (int nc = 0; nc < 8; nc++) {
            __half2 h01 = __floats2half2_rn(__expf(Sc[nc][0] - mn0), __expf(Sc[nc][1] - mn0));
            __half2 h23 = __floats2half2_rn(__expf(Sc[nc][2] - mn1), __expf(Sc[nc][3] - mn1));
            s0 += __low2float(h01) + __high2float(h01);
            s1 += __low2float(h23) + __high2float(h23);
            *(__half2*)&Ph[(r0 + g)     * PADH + nc * 8 + 2 * tg] = h01;
            *(__half2*)&Ph[(r0 + g + 8) * PADH + nc * 8 + 2 * tg] = h23;
        }
        l0 = l0 * a0 + s0;
        l1 = l1 * a1 + s1;

        #pragma unroll
        for (int nc = 0; nc < 8; nc++) {
            O[nc][0] *= a0; O[nc][1] *= a0;
            O[nc][2] *= a1; O[nc][3] *= a1;
        }
        __syncwarp();

        // ---- O += P V : 32 fp16 mma, V frags via ldmatrix.trans ----
        #pragma unroll
        for (int kc = 0; kc < 4; kc++) {
            uint32_t pa[4];
            pa[0] = *(const uint32_t*)&Ph[(r0 + g)     * PADH + kc * 16 + 2 * tg];
            pa[1] = *(const uint32_t*)&Ph[(r0 + g + 8) * PADH + kc * 16 + 2 * tg];
            pa[2] = *(const uint32_t*)&Ph[(r0 + g)     * PADH + kc * 16 + 8 + 2 * tg];
            pa[3] = *(const uint32_t*)&Ph[(r0 + g + 8) * PADH + kc * 16 + 8 + 2 * tg];
            const uint32_t va = vbase + (uint32_t)(kc * 16 * PADH) * 2;
            #pragma unroll
            for (int nc = 0; nc < 8; nc++) {
                uint32_t b0, b1;
                ldsm_x2_t(b0, b1, va + (uint32_t)(nc * 8) * 2);
                mma16h(O[nc], pa, b0, b1);
            }
        }
        __syncwarp();
        __syncthreads();
    }

    // ---- final l reduction, normalize, write fp16 ao ----
    l0 += __shfl_xor_sync(0xFFFFFFFF, l0, 1);
    l0 += __shfl_xor_sync(0xFFFFFFFF, l0, 2);
    l1 += __shfl_xor_sync(0xFFFFFFFF, l1, 1);
    l1 += __shfl_xor_sync(0xFFFFFFFF, l1, 2);
    const float inv0 = 1.f / l0;
    const float inv1 = 1.f / l1;
    __half* op0 = ao + (rowbase + (size_t)(qb * 64 + r0 + g))     * DM + h * DH;
    __half* op1 = ao + (rowbase + (size_t)(qb * 64 + r0 + g + 8)) * DM + h * DH;
    #pragma unroll
    for (int nc = 0; nc < 8; nc++) {
        *(__half2*)(op0 + nc * 8 + 2 * tg) =
            __floats2half2_rn(O[nc][0] * inv0, O[nc][1] * inv0);
        *(__half2*)(op1 + nc * 8 + 2 * tg) =
            __floats2half2_rn(O[nc][2] * inv1, O[nc][3] * inv1);
    }
}

// ---------------------------------------------------------------------------
extern "C" void kernel_launch(void* const* d_in, const int* in_sizes, int n_in,
                              void* d_out, int out_size)
{
    const float* x    = (const float*)d_in[0];   // [B,T,1024]
    const float* Wqkv = (const float*)d_in[1];   // [1024,3072]
    const float* Wout = (const float*)d_in[2];   // [1024,1024]
    float* out = (float*)d_out;

    __half *qkv, *ao, *xh, *wtq, *wto;
    cudaGetSymbolAddress((void**)&qkv, g_qkv);
    cudaGetSymbolAddress((void**)&ao,  g_ao);
    cudaGetSymbolAddress((void**)&xh,  g_xh);
    cudaGetSymbolAddress((void**)&wtq, g_wtq);
    cudaGetSymbolAddress((void**)&wto, g_wto);

    // Prologue: x -> fp16; weights transposed -> fp16
    f32_to_f16<<<(BT * DM / 4 + 255) / 256, 256>>>((const float4*)x, (__half2*)xh, BT * DM / 4);
    transposeH<<<dim3(NQKV / 32, DM / 32), dim3(32, 8)>>>(Wqkv, wtq, DM, NQKV);
    transposeH<<<dim3(DM / 32, DM / 32), dim3(32, 8)>>>(Wout, wto, DM, DM);

    // 1) QKV projection (fp16 mma, fp16 output)
    gemm_h<<<dim3(NQKV / 128, BT / 128), 256>>>(xh, wtq, nullptr, qkv, BT, NQKV, DM);

    // 2) Causal flash attention (fp16 mma)
    flash_attn_h<<<dim3(TT / 64, BB * NH), 128>>>(qkv, ao);

    // 3) Output projection (fp16 mma, fp32 output)
    gemm_h<<<dim3(DM / 128, BT / 128), 256>>>(ao, wto, out, nullptr, BT, DM, DM);
}

// round 13
// speedup vs baseline: 7.8213x; 1.1215x over previous
#include <cuda_runtime.h>
#include <cuda_fp16.h>
#include <math.h>
#include <stdint.h>

// Problem constants
#define BB      4
#define TT      2048
#define DM      1024
#define NH      16
#define DH      64
#define BT      (BB * TT)        // 8192 rows
#define NQKV    (3 * DM)         // 3072

// Scratch (alloc-free rule: __device__ globals)
__device__ __half g_qkv[(size_t)BT * NQKV];  // 50.3 MB (fp16)
__device__ __half g_ao [(size_t)BT * DM];    // 16.8 MB (fp16)
__device__ __half g_xh [(size_t)BT * DM];    // 16.8 MB (x in fp16)
__device__ __half g_wtq[(size_t)NQKV * DM];  //  6.3 MB (Wqkv^T fp16)
__device__ __half g_wto[(size_t)DM * DM];    //  2.1 MB (Wout^T fp16)

// ---------------------------------------------------------------------------
// Helpers
// ---------------------------------------------------------------------------
__device__ __forceinline__ uint32_t smem_u32(const void* p) {
    uint32_t a;
    asm("{ .reg .u64 t; cvta.to.shared.u64 t, %1; cvt.u32.u64 %0, t; }" : "=r"(a) : "l"(p));
    return a;
}

#define CP16(dst, src)  asm volatile("cp.async.cg.shared.global [%0], [%1], 16;" :: "r"(dst), "l"(src))
#define CP_COMMIT()     asm volatile("cp.async.commit_group;")
#define CP_WAIT(n)      asm volatile("cp.async.wait_group %0;" :: "n"(n))

// m16n8k16 fp16 mma, fp32 accumulate.
__device__ __forceinline__ void mma16h(float* d, const uint32_t* a, uint32_t b0, uint32_t b1) {
    asm volatile(
        "mma.sync.aligned.m16n8k16.row.col.f32.f16.f16.f32 "
        "{%0,%1,%2,%3}, {%4,%5,%6,%7}, {%8,%9}, {%0,%1,%2,%3};"
        : "+f"(d[0]), "+f"(d[1]), "+f"(d[2]), "+f"(d[3])
        : "r"(a[0]), "r"(a[1]), "r"(a[2]), "r"(a[3]), "r"(b0), "r"(b1));
}

__device__ __forceinline__ void ldsm_x4(uint32_t& r0, uint32_t& r1, uint32_t& r2, uint32_t& r3,
                                        uint32_t addr) {
    asm volatile("ldmatrix.sync.aligned.m8n8.x4.shared.b16 {%0,%1,%2,%3}, [%4];"
        : "=r"(r0), "=r"(r1), "=r"(r2), "=r"(r3) : "r"(addr));
}
__device__ __forceinline__ void ldsm_x2_t(uint32_t& r0, uint32_t& r1, uint32_t addr) {
    asm volatile("ldmatrix.sync.aligned.m8n8.x2.trans.shared.b16 {%0,%1}, [%2];"
        : "=r"(r0), "=r"(r1) : "r"(addr));
}

// ---------------------------------------------------------------------------
// fp16 tensor-core GEMM: C[M,N] = A[M,K] * Bt[N,K]^T.
// BM=BN=128, BK=32 halves, 256 threads (8 warps), warp tile 32x64.
// 3-stage cp.async ring, ONE __syncthreads per chunk, ldmatrix fragments.
// Smem rows padded to 40 halves (80B stride: ldmatrix conflict-free).
// ---------------------------------------------------------------------------
#define GPAD  40
#define GASZ  (128 * GPAD * 2)          // 10240 B per operand per stage
#define GSTG  (2 * GASZ)                // 20480 B per stage
#define G_SMEM (3 * GSTG)               // 61440 B

__global__ __launch_bounds__(256, 2) void gemm_h(
    const __half* __restrict__ A, const __half* __restrict__ Bt,
    float* __restrict__ Cf, __half* __restrict__ Ch,
    int M, int N, int K)
{
    extern __shared__ char smem_g[];
    const uint32_t sbase = smem_u32(smem_g);

    const int tid  = threadIdx.x;
    const int lane = tid & 31;
    const int wid  = tid >> 5;
    const int wm   = (wid >> 1) * 32;
    const int wn   = (wid & 1) * 64;
    const int g    = lane >> 2;
    const int tg   = lane & 3;

    const int bx = blockIdx.x, by = blockIdx.y;

    // cp.async load map
    const int lrow = tid >> 1;
    const int colb = (tid & 1) * 16;
    const uint32_t dOff = (uint32_t)(lrow * GPAD + colb) * 2;
    const __half* gA = A  + (size_t)(by * 128) * K;
    const __half* gB = Bt + (size_t)(bx * 128) * K;

    // ldmatrix per-lane offsets
    const int mi = lane >> 3, lr = lane & 7;
    const int aRow = lr + ((mi & 1) << 3);
    const int aCol = (mi & 2) << 2;           // 0 or 8
    const int bRow = lr + ((mi >> 1) << 3);
    const int bCol = (mi & 1) << 3;           // 0 or 8

    float acc[2][8][4];
    #pragma unroll
    for (int i = 0; i < 2; i++)
        #pragma unroll
        for (int j = 0; j < 8; j++)
            #pragma unroll
            for (int q = 0; q < 4; q++) acc[i][j][q] = 0.f;

    const int NC = K / 32;

    // prologue: chunks 0,1 -> stages 0,1
    {
        const uint32_t dA0 = sbase + dOff;
        CP16(dA0,              gA + (size_t)lrow * K + colb);
        CP16(dA0 + 16,         gA + (size_t)lrow * K + colb + 8);
        CP16(dA0 + GASZ,       gB + (size_t)lrow * K + colb);
        CP16(dA0 + GASZ + 16,  gB + (size_t)lrow * K + colb + 8);
        CP_COMMIT();
        const uint32_t dA1 = sbase + GSTG + dOff;
        CP16(dA1,              gA + (size_t)lrow * K + 32 + colb);
        CP16(dA1 + 16,         gA + (size_t)lrow * K + 32 + colb + 8);
        CP16(dA1 + GASZ,       gB + (size_t)lrow * K + 32 + colb);
        CP16(dA1 + GASZ + 16,  gB + (size_t)lrow * K + 32 + colb + 8);
        CP_COMMIT();
    }

    for (int c = 0; c < NC; c++) {
        CP_WAIT(1);           // chunk c landed (chunk c+1 may be in flight)
        __syncthreads();      // globally visible; all warps done with chunk c-1
        if (c + 2 < NC) {     // prefetch chunk c+2 into stage (c+2)%3 (= (c-1)%3)
            const int k0 = (c + 2) * 32;
            const uint32_t dA = sbase + (uint32_t)((c + 2) % 3) * GSTG + dOff;
            CP16(dA,             gA + (size_t)lrow * K + k0 + colb);
            CP16(dA + 16,        gA + (size_t)lrow * K + k0 + colb + 8);
            CP16(dA + GASZ,      gB + (size_t)lrow * K + k0 + colb);
            CP16(dA + GASZ + 16, gB + (size_t)lrow * K + k0 + colb + 8);
        }
        CP_COMMIT();          // always commit (empty groups keep accounting fixed)

        const uint32_t aoff = sbase + (uint32_t)(c % 3) * GSTG;
        const uint32_t boff = aoff + GASZ;
        #pragma unroll
        for (int ks = 0; ks < 2; ks++) {
            uint32_t a0[4], a1[4];
            ldsm_x4(a0[0], a0[1], a0[2], a0[3],
                    aoff + (uint32_t)((wm + aRow) * GPAD + ks * 16 + aCol) * 2);
            ldsm_x4(a1[0], a1[1], a1[2], a1[3],
                    aoff + (uint32_t)((wm + 16 + aRow) * GPAD + ks * 16 + aCol) * 2);
            uint32_t bb[8][2];
            #pragma unroll
            for (int ntp = 0; ntp < 4; ntp++) {
                uint32_t r0, r1, r2, r3;
                ldsm_x4(r0, r1, r2, r3,
                        boff + (uint32_t)((wn + ntp * 16 + bRow) * GPAD + ks * 16 + bCol) * 2);
                bb[2 * ntp][0] = r0; bb[2 * ntp][1] = r1;
                bb[2 * ntp + 1][0] = r2; bb[2 * ntp + 1][1] = r3;
            }
            #pragma unroll
            for (int nt = 0; nt < 8; nt++) {
                mma16h(acc[0][nt], a0, bb[nt][0], bb[nt][1]);
                mma16h(acc[1][nt], a1, bb[nt][0], bb[nt][1]);
            }
        }
    }

    // epilogue (registers -> gmem; no barrier needed)
    #pragma unroll
    for (int mt = 0; mt < 2; mt++) {
        const size_t r0 = (size_t)(by * 128 + wm + mt * 16 + g);
        #pragma unroll
        for (int nt = 0; nt < 8; nt++) {
            const int col = bx * 128 + wn + nt * 8 + 2 * tg;
            if (Ch) {
                *(__half2*)(Ch + r0 * N + col) =
                    __floats2half2_rn(acc[mt][nt][0], acc[mt][nt][1]);
                *(__half2*)(Ch + (r0 + 8) * N + col) =
                    __floats2half2_rn(acc[mt][nt][2], acc[mt][nt][3]);
            } else {
                *(float2*)(Cf + r0 * N + col)       = make_float2(acc[mt][nt][0], acc[mt][nt][1]);
                *(float2*)(Cf + (r0 + 8) * N + col) = make_float2(acc[mt][nt][2], acc[mt][nt][3]);
            }
        }
    }
}

// ---------------------------------------------------------------------------
// Prologue kernels
// ---------------------------------------------------------------------------
__global__ void f32_to_f16(const float4* __restrict__ in, __half2* __restrict__ out, int n4)
{
    int i = blockIdx.x * blockDim.x + threadIdx.x;
    if (i < n4) {
        float4 v = in[i];
        out[2 * i]     = __floats2half2_rn(v.x, v.y);
        out[2 * i + 1] = __floats2half2_rn(v.z, v.w);
    }
}

__global__ void transposeH(const float* __restrict__ in, __half* __restrict__ out,
                           int rows, int cols)
{
    __shared__ float t[32][33];
    const int bx = blockIdx.x * 32, by = blockIdx.y * 32;
    #pragma unroll
    for (int i = threadIdx.y; i < 32; i += 8)
        t[i][threadIdx.x] = in[(size_t)(by + i) * cols + bx + threadIdx.x];
    __syncthreads();
    #pragma unroll
    for (int i = threadIdx.y; i < 32; i += 8)
        out[(size_t)(bx + i) * rows + by + threadIdx.x] = __float2half_rn(t[threadIdx.x][i]);
}

// ---------------------------------------------------------------------------
// fp16 tensor-core flash attention (causal), fp32 softmax/accum.
// grid: (T/128, B*NH), block 256 (8 warps), warp = 16 query rows.
// K/V tiles 64x64 halves double-buffered; V B-frags via ldmatrix.x2.trans.
// ---------------------------------------------------------------------------
#define PADH 72
#define FA_KSTG (64 * PADH * 2)               // 9216 B per K (or V) stage
#define FA_SMEM (4 * FA_KSTG + 128 * PADH * 2) // K[2]+V[2]+P[128] = 55296 B

__global__ __launch_bounds__(256, 2) void flash_attn_h(
    const __half* __restrict__ qkv, __half* __restrict__ ao)
{
    extern __shared__ char smf[];
    __half* Ph = (__half*)(smf + 4 * FA_KSTG);
    const uint32_t ksb = smem_u32(smf);
    const uint32_t vsb = ksb + 2 * FA_KSTG;

    const int qb2  = (gridDim.x - 1) - blockIdx.x;  // heavy blocks first
    const int bh   = blockIdx.y;
    const int b    = bh >> 4;
    const int h    = bh & 15;
    const int tid  = threadIdx.x;
    const int lane = tid & 31;
    const int wid  = tid >> 5;
    const int g    = lane >> 2;
    const int tg   = lane & 3;
    const int r0   = wid * 16;                      // warp row base within 128
    const int qRowBase = qb2 * 128 + r0;            // global (within sequence)

    const size_t rowbase = (size_t)(b * TT);

    // cp.async map: 1024 cp16 per tile pair, 4 per thread
    {
        const __half* kb0 = qkv + (rowbase + 0) * NQKV + DM + h * DH;
        #pragma unroll
        for (int i = 0; i < 4; i++) {
            int f  = tid + i * 256;
            int kv = f >> 9;
            int f5 = f & 511;
            int row = f5 >> 3;
            int col = (f5 & 7) * 8;
            uint32_t dst = (kv ? vsb : ksb) + (uint32_t)(row * PADH + col) * 2;
            CP16(dst, kb0 + (size_t)row * NQKV + kv * DM + col);
        }
        CP_COMMIT();
    }

    // Q fragments (x 0.125, exact in fp16)
    uint32_t qa[4][4];
    {
        const __half* qp = qkv + (rowbase + (size_t)qRowBase) * NQKV + h * DH;
        const __half2 sc = __floats2half2_rn(0.125f, 0.125f);
        #pragma unroll
        for (int kc = 0; kc < 4; kc++) {
            #pragma unroll
            for (int e = 0; e < 4; e++) {
                int dr = (e & 1) * 8;
                int dc = (e >> 1) * 8;
                __half2 v = *(const __half2*)(qp + (size_t)(g + dr) * NQKV + kc * 16 + dc + 2 * tg);
                v = __hmul2(v, sc);
                qa[kc][e] = *(const uint32_t*)&v;
            }
        }
    }

    float O[8][4];
    #pragma unroll
    for (int nc = 0; nc < 8; nc++)
        #pragma unroll
        for (int e = 0; e < 4; e++) O[nc][e] = 0.f;
    float m0 = -1e30f, m1 = -1e30f, l0 = 0.f, l1 = 0.f;

    const int vrow = lane & 15;
    const int lastT = 2 * qb2 + 1;

    for (int kb = 0; kb <= lastT; kb++) {
        const int buf = kb & 1;
        if (kb < lastT) {
            const int nbuf = buf ^ 1;
            const __half* kbn = qkv + (rowbase + (size_t)((kb + 1) * 64)) * NQKV + DM + h * DH;
            const uint32_t kd = ksb + (uint32_t)nbuf * FA_KSTG;
            const uint32_t vd = vsb + (uint32_t)nbuf * FA_KSTG;
            #pragma unroll
            for (int i = 0; i < 4; i++) {
                int f  = tid + i * 256;
                int kv = f >> 9;
                int f5 = f & 511;
                int row = f5 >> 3;
                int col = (f5 & 7) * 8;
                uint32_t dst = (kv ? vd : kd) + (uint32_t)(row * PADH + col) * 2;
                CP16(dst, kbn + (size_t)row * NQKV + kv * DM + col);
            }
            CP_COMMIT();
            CP_WAIT(1);
        } else {
            CP_WAIT(0);
        }
        __syncthreads();

        const int iloc = qRowBase - kb * 64;    // warp row base relative to key tile
        if (iloc > -16) {                       // not fully masked for this warp
            const __half* Ks = (const __half*)(smf) + (size_t)buf * (64 * PADH);
            const uint32_t vbase = vsb + (uint32_t)buf * FA_KSTG
                                 + (uint32_t)(vrow * PADH) * 2;

            // ---- S = (Q*scale) K^T : 32 fp16 mma ----
            float Sc[8][4];
            #pragma unroll
            for (int nc = 0; nc < 8; nc++)
                #pragma unroll
                for (int e = 0; e < 4; e++) Sc[nc][e] = 0.f;

            #pragma unroll
            for (int kc = 0; kc < 4; kc++) {
                #pragma unroll
                for (int nc = 0; nc < 8; nc++) {
                    uint32_t b0 = *(const uint32_t*)&Ks[(nc * 8 + g) * PADH + kc * 16 + 2 * tg];
                    uint32_t b1 = *(const uint32_t*)&Ks[(nc * 8 + g) * PADH + kc * 16 + 8 + 2 * tg];
                    mma16h(Sc[nc], qa[kc], b0, b1);
                }
            }

            // ---- causal mask (diagonal-overlapping tiles) ----
            if (iloc < 63) {
                const int i0 = iloc + g, i1 = iloc + g + 8;
                #pragma unroll
                for (int nc = 0; nc < 8; nc++) {
                    int j = nc * 8 + 2 * tg;
                    if (j     > i0) Sc[nc][0] = -1e30f;
                    if (j + 1 > i0) Sc[nc][1] = -1e30f;
                    if (j     > i1) Sc[nc][2] = -1e30f;
                    if (j + 1 > i1) Sc[nc][3] = -1e30f;
                }
            }

            // ---- online softmax ----
            float rx0 = -1e30f, rx1 = -1e30f;
            #pragma unroll
            for (int nc = 0; nc < 8; nc++) {
                rx0 = fmaxf(rx0, fmaxf(Sc[nc][0], Sc[nc][1]));
                rx1 = fmaxf(rx1, fmaxf(Sc[nc][2], Sc[nc][3]));
            }
            rx0 = fmaxf(rx0, __shfl_xor_sync(0xFFFFFFFF, rx0, 1));
            rx0 = fmaxf(rx0, __shfl_xor_sync(0xFFFFFFFF, rx0, 2));
            rx1 = fmaxf(rx1, __shfl_xor_sync(0xFFFFFFFF, rx1, 1));
            rx1 = fmaxf(rx1, __shfl_xor_sync(0xFFFFFFFF, rx1, 2));

            const float mn0 = fmaxf(m0, rx0);
            const float mn1 = fmaxf(m1, rx1);
            const float a0 = __expf(m0 - mn0);
            const float a1 = __expf(m1 - mn1);
            m0 = mn0; m1 = mn1;

            float s0 = 0.f, s1 = 0.f;
            #pragma unroll
            for (int nc = 0; nc < 8; nc++) {
                __half2 h01 = __floats2half2_rn(__expf(Sc[nc][0] - mn0), __expf(Sc[nc][1] - mn0));
                __half2 h23 = __floats2half2_rn(__expf(Sc[nc][2] - mn1), __expf(Sc[nc][3] - mn1));
                s0 += __low2float(h01) + __high2float(h01);
                s1 += __low2float(h23) + __high2float(h23);
                *(__half2*)&Ph[(r0 + g)     * PADH + nc * 8 + 2 * tg] = h01;
                *(__half2*)&Ph[(r0 + g + 8) * PADH + nc * 8 + 2 * tg] = h23;
            }
            l0 = l0 * a0 + s0;
            l1 = l1 * a1 + s1;

            #pragma unroll
            for (int nc = 0; nc < 8; nc++) {
                O[nc][0] *= a0; O[nc][1] *= a0;
                O[nc][2] *= a1; O[nc][3] *= a1;
            }
            __syncwarp();

            // ---- O += P V : 32 fp16 mma, V frags via ldmatrix.trans ----
            #pragma unroll
            for (int kc = 0; kc < 4; kc++) {
                uint32_t pa[4];
                pa[0] = *(const uint32_t*)&Ph[(r0 + g)     * PADH + kc * 16 + 2 * tg];
                pa[1] = *(const uint32_t*)&Ph[(r0 + g + 8) * PADH + kc * 16 + 2 * tg];
                pa[2] = *(const uint32_t*)&Ph[(r0 + g)     * PADH + kc * 16 + 8 + 2 * tg];
                pa[3] = *(const uint32_t*)&Ph[(r0 + g + 8) * PADH + kc * 16 + 8 + 2 * tg];
                const uint32_t va = vbase + (uint32_t)(kc * 16 * PADH) * 2;
                #pragma unroll
                for (int nc = 0; nc < 8; nc++) {
                    uint32_t b0, b1;
                    ldsm_x2_t(b0, b1, va + (uint32_t)(nc * 8) * 2);
                    mma16h(O[nc], pa, b0, b1);
                }
            }
            __syncwarp();
        }
        __syncthreads();
    }

    // ---- final l reduction, normalize, write fp16 ao ----
    l0 += __shfl_xor_sync(0xFFFFFFFF, l0, 1);
    l0 += __shfl_xor_sync(0xFFFFFFFF, l0, 2);
    l1 += __shfl_xor_sync(0xFFFFFFFF, l1, 1);
    l1 += __shfl_xor_sync(0xFFFFFFFF, l1, 2);
    const float inv0 = 1.f / l0;
    const float inv1 = 1.f / l1;
    __half* op0 = ao + (rowbase + (size_t)(qRowBase + g))     * DM + h * DH;
    __half* op1 = ao + (rowbase + (size_t)(qRowBase + g + 8)) * DM + h * DH;
    #pragma unroll
    for (int nc = 0; nc < 8; nc++) {
        *(__half2*)(op0 + nc * 8 + 2 * tg) =
            __floats2half2_rn(O[nc][0] * inv0, O[nc][1] * inv0);
        *(__half2*)(op1 + nc * 8 + 2 * tg) =
            __floats2half2_rn(O[nc][2] * inv1, O[nc][3] * inv1);
    }
}

// ---------------------------------------------------------------------------
extern "C" void kernel_launch(void* const* d_in, const int* in_sizes, int n_in,
                              void* d_out, int out_size)
{
    const float* x    = (const float*)d_in[0];   // [B,T,1024]
    const float* Wqkv = (const float*)d_in[1];   // [1024,3072]
    const float* Wout = (const float*)d_in[2];   // [1024,1024]
    float* out = (float*)d_out;

    __half *qkv, *ao, *xh, *wtq, *wto;
    cudaGetSymbolAddress((void**)&qkv, g_qkv);
    cudaGetSymbolAddress((void**)&ao,  g_ao);
    cudaGetSymbolAddress((void**)&xh,  g_xh);
    cudaGetSymbolAddress((void**)&wtq, g_wtq);
    cudaGetSymbolAddress((void**)&wto, g_wto);

    cudaFuncSetAttribute(gemm_h, cudaFuncAttributeMaxDynamicSharedMemorySize, G_SMEM);
    cudaFuncSetAttribute(flash_attn_h, cudaFuncAttributeMaxDynamicSharedMemorySize, FA_SMEM);

    // Prologue: x -> fp16; weights transposed -> fp16
    f32_to_f16<<<(BT * DM / 4 + 255) / 256, 256>>>((const float4*)x, (__half2*)xh, BT * DM / 4);
    transposeH<<<dim3(NQKV / 32, DM / 32), dim3(32, 8)>>>(Wqkv, wtq, DM, NQKV);
    transposeH<<<dim3(DM / 32, DM / 32), dim3(32, 8)>>>(Wout, wto, DM, DM);

    // 1) QKV projection (fp16 mma, fp16 output)
    gemm_h<<<dim3(NQKV / 128, BT / 128), 256, G_SMEM>>>(xh, wtq, nullptr, qkv, BT, NQKV, DM);

    // 2) Causal flash attention (fp16 mma, 128-row CTAs)
    flash_attn_h<<<dim3(TT / 128, BB * NH), 256, FA_SMEM>>>(qkv, ao);

    // 3) Output projection (fp16 mma, fp32 output)
    gemm_h<<<dim3(DM / 128, BT / 128), 256, G_SMEM>>>(ao, wto, out, nullptr, BT, DM, DM);
}

// round 14
// speedup vs baseline: 7.9303x; 1.0139x over previous
#include <cuda_runtime.h>
#include <cuda_fp16.h>
#include <math.h>
#include <stdint.h>

// Problem constants
#define BB      4
#define TT      2048
#define DM      1024
#define NH      16
#define DH      64
#define BT      (BB * TT)        // 8192 rows
#define NQKV    (3 * DM)         // 3072

// Scratch (alloc-free rule: __device__ globals)
__device__ __half g_qkv[(size_t)BT * NQKV];  // 50.3 MB (fp16)
__device__ __half g_ao [(size_t)BT * DM];    // 16.8 MB (fp16)
__device__ __half g_xh [(size_t)BT * DM];    // 16.8 MB (x in fp16)
__device__ __half g_wtq[(size_t)NQKV * DM];  //  6.3 MB (Wqkv^T fp16)
__device__ __half g_wto[(size_t)DM * DM];    //  2.1 MB (Wout^T fp16)

// ---------------------------------------------------------------------------
// Helpers
// ---------------------------------------------------------------------------
__device__ __forceinline__ uint32_t smem_u32(const void* p) {
    uint32_t a;
    asm("{ .reg .u64 t; cvta.to.shared.u64 t, %1; cvt.u32.u64 %0, t; }" : "=r"(a) : "l"(p));
    return a;
}

#define CP16(dst, src)  asm volatile("cp.async.cg.shared.global [%0], [%1], 16;" :: "r"(dst), "l"(src))
#define CP_COMMIT()     asm volatile("cp.async.commit_group;")
#define CP_WAIT(n)      asm volatile("cp.async.wait_group %0;" :: "n"(n))

#define MBAR_INIT(a, c) asm volatile("mbarrier.init.shared.b64 [%0], %1;" :: "r"(a), "r"(c) : "memory")
#define MBAR_ARRIVE(a)  asm volatile("mbarrier.arrive.shared::cta.b64 _, [%0];" :: "r"(a) : "memory")
#define CP_MBAR_ARR(a)  asm volatile("cp.async.mbarrier.arrive.noinc.shared::cta.b64 [%0];" :: "r"(a) : "memory")
#define MBAR_WAIT(a, ph) do { \
    uint32_t _m = (a), _p = (ph), _d; \
    asm volatile("{ .reg .pred p; mbarrier.try_wait.parity.acquire.cta.shared::cta.b64 p, [%1], %2; selp.b32 %0,1,0,p; }" \
        : "=r"(_d) : "r"(_m), "r"(_p) : "memory"); \
    if (!_d) { \
        asm volatile("{ .reg .pred P1;\nW%=:\nmbarrier.try_wait.parity.acquire.cta.shared::cta.b64 P1, [%0], %1, 0x989680;\n@P1 bra.uni D%=;\nbra.uni W%=;\nD%=:\n}" \
            :: "r"(_m), "r"(_p) : "memory"); \
    } } while (0)

// m16n8k16 fp16 mma, fp32 accumulate.
__device__ __forceinline__ void mma16h(float* d, const uint32_t* a, uint32_t b0, uint32_t b1) {
    asm volatile(
        "mma.sync.aligned.m16n8k16.row.col.f32.f16.f16.f32 "
        "{%0,%1,%2,%3}, {%4,%5,%6,%7}, {%8,%9}, {%0,%1,%2,%3};"
        : "+f"(d[0]), "+f"(d[1]), "+f"(d[2]), "+f"(d[3])
        : "r"(a[0]), "r"(a[1]), "r"(a[2]), "r"(a[3]), "r"(b0), "r"(b1));
}

__device__ __forceinline__ void ldsm_x4(uint32_t& r0, uint32_t& r1, uint32_t& r2, uint32_t& r3,
                                        uint32_t addr) {
    asm volatile("ldmatrix.sync.aligned.m8n8.x4.shared.b16 {%0,%1,%2,%3}, [%4];"
        : "=r"(r0), "=r"(r1), "=r"(r2), "=r"(r3) : "r"(addr));
}
__device__ __forceinline__ void ldsm_x2_t(uint32_t& r0, uint32_t& r1, uint32_t addr) {
    asm volatile("ldmatrix.sync.aligned.m8n8.x2.trans.shared.b16 {%0,%1}, [%2];"
        : "=r"(r0), "=r"(r1) : "r"(addr));
}

// ---------------------------------------------------------------------------
// fp16 tensor-core GEMM (93% of mma.sync issue floor — unchanged from R13)
// ---------------------------------------------------------------------------
#define GPAD  40
#define GASZ  (128 * GPAD * 2)
#define GSTG  (2 * GASZ)
#define G_SMEM (3 * GSTG)

__global__ __launch_bounds__(256, 2) void gemm_h(
    const __half* __restrict__ A, const __half* __restrict__ Bt,
    float* __restrict__ Cf, __half* __restrict__ Ch,
    int M, int N, int K)
{
    extern __shared__ char smem_g[];
    const uint32_t sbase = smem_u32(smem_g);

    const int tid  = threadIdx.x;
    const int lane = tid & 31;
    const int wid  = tid >> 5;
    const int wm   = (wid >> 1) * 32;
    const int wn   = (wid & 1) * 64;
    const int g    = lane >> 2;
    const int tg   = lane & 3;

    const int bx = blockIdx.x, by = blockIdx.y;

    const int lrow = tid >> 1;
    const int colb = (tid & 1) * 16;
    const uint32_t dOff = (uint32_t)(lrow * GPAD + colb) * 2;
    const __half* gA = A  + (size_t)(by * 128) * K;
    const __half* gB = Bt + (size_t)(bx * 128) * K;

    const int mi = lane >> 3, lr = lane & 7;
    const int aRow = lr + ((mi & 1) << 3);
    const int aCol = (mi & 2) << 2;
    const int bRow = lr + ((mi >> 1) << 3);
    const int bCol = (mi & 1) << 3;

    float acc[2][8][4];
    #pragma unroll
    for (int i = 0; i < 2; i++)
        #pragma unroll
        for (int j = 0; j < 8; j++)
            #pragma unroll
            for (int q = 0; q < 4; q++) acc[i][j][q] = 0.f;

    const int NC = K / 32;

    {
        const uint32_t dA0 = sbase + dOff;
        CP16(dA0,              gA + (size_t)lrow * K + colb);
        CP16(dA0 + 16,         gA + (size_t)lrow * K + colb + 8);
        CP16(dA0 + GASZ,       gB + (size_t)lrow * K + colb);
        CP16(dA0 + GASZ + 16,  gB + (size_t)lrow * K + colb + 8);
        CP_COMMIT();
        const uint32_t dA1 = sbase + GSTG + dOff;
        CP16(dA1,              gA + (size_t)lrow * K + 32 + colb);
        CP16(dA1 + 16,         gA + (size_t)lrow * K + 32 + colb + 8);
        CP16(dA1 + GASZ,       gB + (size_t)lrow * K + 32 + colb);
        CP16(dA1 + GASZ + 16,  gB + (size_t)lrow * K + 32 + colb + 8);
        CP_COMMIT();
    }

    for (int c = 0; c < NC; c++) {
        CP_WAIT(1);
        __syncthreads();
        if (c + 2 < NC) {
            const int k0 = (c + 2) * 32;
            const uint32_t dA = sbase + (uint32_t)((c + 2) % 3) * GSTG + dOff;
            CP16(dA,             gA + (size_t)lrow * K + k0 + colb);
            CP16(dA + 16,        gA + (size_t)lrow * K + k0 + colb + 8);
            CP16(dA + GASZ,      gB + (size_t)lrow * K + k0 + colb);
            CP16(dA + GASZ + 16, gB + (size_t)lrow * K + k0 + colb + 8);
        }
        CP_COMMIT();

        const uint32_t aoff = sbase + (uint32_t)(c % 3) * GSTG;
        const uint32_t boff = aoff + GASZ;
        #pragma unroll
        for (int ks = 0; ks < 2; ks++) {
            uint32_t a0[4], a1[4];
            ldsm_x4(a0[0], a0[1], a0[2], a0[3],
                    aoff + (uint32_t)((wm + aRow) * GPAD + ks * 16 + aCol) * 2);
            ldsm_x4(a1[0], a1[1], a1[2], a1[3],
                    aoff + (uint32_t)((wm + 16 + aRow) * GPAD + ks * 16 + aCol) * 2);
            uint32_t bb[8][2];
            #pragma unroll
            for (int ntp = 0; ntp < 4; ntp++) {
                uint32_t r0, r1, r2, r3;
                ldsm_x4(r0, r1, r2, r3,
                        boff + (uint32_t)((wn + ntp * 16 + bRow) * GPAD + ks * 16 + bCol) * 2);
                bb[2 * ntp][0] = r0; bb[2 * ntp][1] = r1;
                bb[2 * ntp + 1][0] = r2; bb[2 * ntp + 1][1] = r3;
            }
            #pragma unroll
            for (int nt = 0; nt < 8; nt++) {
                mma16h(acc[0][nt], a0, bb[nt][0], bb[nt][1]);
                mma16h(acc[1][nt], a1, bb[nt][0], bb[nt][1]);
            }
        }
    }

    #pragma unroll
    for (int mt = 0; mt < 2; mt++) {
        const size_t r0 = (size_t)(by * 128 + wm + mt * 16 + g);
        #pragma unroll
        for (int nt = 0; nt < 8; nt++) {
            const int col = bx * 128 + wn + nt * 8 + 2 * tg;
            if (Ch) {
                *(__half2*)(Ch + r0 * N + col) =
                    __floats2half2_rn(acc[mt][nt][0], acc[mt][nt][1]);
                *(__half2*)(Ch + (r0 + 8) * N + col) =
                    __floats2half2_rn(acc[mt][nt][2], acc[mt][nt][3]);
            } else {
                *(float2*)(Cf + r0 * N + col)       = make_float2(acc[mt][nt][0], acc[mt][nt][1]);
                *(float2*)(Cf + (r0 + 8) * N + col) = make_float2(acc[mt][nt][2], acc[mt][nt][3]);
            }
        }
    }
}

// ---------------------------------------------------------------------------
// Prologue kernels
// ---------------------------------------------------------------------------
__global__ void f32_to_f16(const float4* __restrict__ in, __half2* __restrict__ out, int n4)
{
    int i = blockIdx.x * blockDim.x + threadIdx.x;
    if (i < n4) {
        float4 v = in[i];
        out[2 * i]     = __floats2half2_rn(v.x, v.y);
        out[2 * i + 1] = __floats2half2_rn(v.z, v.w);
    }
}

__global__ void transposeH(const float* __restrict__ in, __half* __restrict__ out,
                           int rows, int cols)
{
    __shared__ float t[32][33];
    const int bx = blockIdx.x * 32, by = blockIdx.y * 32;
    #pragma unroll
    for (int i = threadIdx.y; i < 32; i += 8)
        t[i][threadIdx.x] = in[(size_t)(by + i) * cols + bx + threadIdx.x];
    __syncthreads();
    #pragma unroll
    for (int i = threadIdx.y; i < 32; i += 8)
        out[(size_t)(bx + i) * rows + by + threadIdx.x] = __float2half_rn(t[threadIdx.x][i]);
}

// ---------------------------------------------------------------------------
// fp16 flash attention (causal), mbarrier producer/consumer pipeline.
// grid: (T/128, B*NH), block 256 (8 warps), warp = 16 query rows.
// Warp 0 produces K tiles, warp 1 produces V tiles into a 4-stage ring;
// all warps consume at their own pace (no per-tile __syncthreads).
//   full[s]:  count 64 (producer lanes, via cp.async.mbarrier.arrive.noinc)
//   empty[s]: count 8  (one arrive per warp after consuming the tile)
// ---------------------------------------------------------------------------
#define PADH 72
#define FA_S 4
#define FA_KSTG (64 * PADH * 2)                 // 9216 B per K (or V) stage
#define OFF_K   128
#define OFF_V   (OFF_K + FA_S * FA_KSTG)        // 36992
#define OFF_P   (OFF_V + FA_S * FA_KSTG)        // 73856
#define FA_SMEM (OFF_P + 128 * PADH * 2)        // 92288 B

__global__ __launch_bounds__(256, 2) void flash_attn_h(
    const __half* __restrict__ qkv, __half* __restrict__ ao)
{
    extern __shared__ char smf[];
    __half* Ph = (__half*)(smf + OFF_P);
    const uint32_t sb   = smem_u32(smf);
    const uint32_t ksb  = sb + OFF_K;
    const uint32_t vsb  = sb + OFF_V;
    const uint32_t mbF  = sb;          // full[0..3]  at +0,8,16,24
    const uint32_t mbE  = sb + 32;     // empty[0..3] at +32..56

    const int qb2  = (gridDim.x - 1) - blockIdx.x;  // heavy blocks first
    const int bh   = blockIdx.y;
    const int b    = bh >> 4;
    const int h    = bh & 15;
    const int tid  = threadIdx.x;
    const int lane = tid & 31;
    const int wid  = tid >> 5;
    const int g    = lane >> 2;
    const int tg   = lane & 3;
    const int r0   = wid * 16;
    const int qRowBase = qb2 * 128 + r0;
    const size_t rowbase = (size_t)(b * TT);
    const int lastT = 2 * qb2 + 1;

    if (tid == 0) {
        #pragma unroll
        for (int s = 0; s < FA_S; s++) {
            MBAR_INIT(mbF + 8 * s, 64);
            MBAR_INIT(mbE + 8 * s, 8);
        }
    }
    __syncthreads();

    // Producer source base: warp 0 -> K, warp 1 -> V
    const bool isProd = (wid < 2);
    const __half* psrc = qkv + rowbase * NQKV + DM + (size_t)wid * DM + h * DH;
    const uint32_t pbase = (wid == 0) ? ksb : vsb;

    // prologue: produce tiles 0..min(FA_S-1, lastT)
    if (isProd) {
        #pragma unroll
        for (int pt = 0; pt < FA_S; pt++) {
            if (pt <= lastT) {
                const __half* src = psrc + (size_t)(pt * 64) * NQKV;
                const uint32_t dstb = pbase + (uint32_t)pt * FA_KSTG;
                #pragma unroll
                for (int i = 0; i < 16; i++) {
                    int f = lane + i * 32;
                    int row = f >> 3;
                    int col = (f & 7) * 8;
                    CP16(dstb + (uint32_t)(row * PADH + col) * 2, src + (size_t)row * NQKV + col);
                }
                CP_MBAR_ARR(mbF + 8 * pt);
            }
        }
    }

    // Q fragments (x 0.125, exact in fp16)
    uint32_t qa[4][4];
    {
        const __half* qp = qkv + (rowbase + (size_t)qRowBase) * NQKV + h * DH;
        const __half2 sc = __floats2half2_rn(0.125f, 0.125f);
        #pragma unroll
        for (int kc = 0; kc < 4; kc++) {
            #pragma unroll
            for (int e = 0; e < 4; e++) {
                int dr = (e & 1) * 8;
                int dc = (e >> 1) * 8;
                __half2 v = *(const __half2*)(qp + (size_t)(g + dr) * NQKV + kc * 16 + dc + 2 * tg);
                v = __hmul2(v, sc);
                qa[kc][e] = *(const uint32_t*)&v;
            }
        }
    }

    float O[8][4];
    #pragma unroll
    for (int nc = 0; nc < 8; nc++)
        #pragma unroll
        for (int e = 0; e < 4; e++) O[nc][e] = 0.f;
    float m0 = -1e30f, m1 = -1e30f, l0 = 0.f, l1 = 0.f;

    const int vrow = lane & 15;

    for (int kb = 0; kb <= lastT; kb++) {
        const int s = kb & (FA_S - 1);

        // producers: refill stage (kb-1)%FA_S with tile kb+FA_S-1
        if (isProd && kb >= 1) {
            const int pt = kb + FA_S - 1;
            if (pt <= lastT) {
                const int ps = pt & (FA_S - 1);
                MBAR_WAIT(mbE + 8 * ps, (uint32_t)(((pt >> 2) - 1) & 1));
                const __half* src = psrc + (size_t)(pt * 64) * NQKV;
                const uint32_t dstb = pbase + (uint32_t)ps * FA_KSTG;
                #pragma unroll
                for (int i = 0; i < 16; i++) {
                    int f = lane + i * 32;
                    int row = f >> 3;
                    int col = (f & 7) * 8;
                    CP16(dstb + (uint32_t)(row * PADH + col) * 2, src + (size_t)row * NQKV + col);
                }
                CP_MBAR_ARR(mbF + 8 * ps);
            }
        }

        // consume tile kb
        MBAR_WAIT(mbF + 8 * s, (uint32_t)((kb >> 2) & 1));

        const int iloc = qRowBase - kb * 64;
        if (iloc > -16) {
            const __half* Ks = (const __half*)(smf + OFF_K) + (size_t)s * (64 * PADH);
            const uint32_t vbase = vsb + (uint32_t)s * FA_KSTG + (uint32_t)(vrow * PADH) * 2;

            // ---- S = (Q*scale) K^T ----
            float Sc[8][4];
            #pragma unroll
            for (int nc = 0; nc < 8; nc++)
                #pragma unroll
                for (int e = 0; e < 4; e++) Sc[nc][e] = 0.f;

            #pragma unroll
            for (int kc = 0; kc < 4; kc++) {
                #pragma unroll
                for (int nc = 0; nc < 8; nc++) {
                    uint32_t b0 = *(const uint32_t*)&Ks[(nc * 8 + g) * PADH + kc * 16 + 2 * tg];
                    uint32_t b1 = *(const uint32_t*)&Ks[(nc * 8 + g) * PADH + kc * 16 + 8 + 2 * tg];
                    mma16h(Sc[nc], qa[kc], b0, b1);
                }
            }

            // ---- causal mask ----
            if (iloc < 63) {
                const int i0 = iloc + g, i1 = iloc + g + 8;
                #pragma unroll
                for (int nc = 0; nc < 8; nc++) {
                    int j = nc * 8 + 2 * tg;
                    if (j     > i0) Sc[nc][0] = -1e30f;
                    if (j + 1 > i0) Sc[nc][1] = -1e30f;
                    if (j     > i1) Sc[nc][2] = -1e30f;
                    if (j + 1 > i1) Sc[nc][3] = -1e30f;
                }
            }

            // ---- online softmax ----
            float rx0 = -1e30f, rx1 = -1e30f;
            #pragma unroll
            for (int nc = 0; nc < 8; nc++) {
                rx0 = fmaxf(rx0, fmaxf(Sc[nc][0], Sc[nc][1]));
                rx1 = fmaxf(rx1, fmaxf(Sc[nc][2], Sc[nc][3]));
            }
            rx0 = fmaxf(rx0, __shfl_xor_sync(0xFFFFFFFF, rx0, 1));
            rx0 = fmaxf(rx0, __shfl_xor_sync(0xFFFFFFFF, rx0, 2));
            rx1 = fmaxf(rx1, __shfl_xor_sync(0xFFFFFFFF, rx1, 1));
            rx1 = fmaxf(rx1, __shfl_xor_sync(0xFFFFFFFF, rx1, 2));

            const float mn0 = fmaxf(m0, rx0);
            const float mn1 = fmaxf(m1, rx1);
            const float a0 = __expf(m0 - mn0);
            const float a1 = __expf(m1 - mn1);
            m0 = mn0; m1 = mn1;

            float s0 = 0.f, s1 = 0.f;
            #pragma unroll
            for (int nc = 0; nc < 8; nc++) {
                __half2 h01 = __floats2half2_rn(__expf(Sc[nc][0] - mn0), __expf(Sc[nc][1] - mn0));
                __half2 h23 = __floats2half2_rn(__expf(Sc[nc][2] - mn1), __expf(Sc[nc][3] - mn1));
                s0 += __low2float(h01) + __high2float(h01);
                s1 += __low2float(h23) + __high2float(h23);
                *(__half2*)&Ph[(r0 + g)     * PADH + nc * 8 + 2 * tg] = h01;
                *(__half2*)&Ph[(r0 + g + 8) * PADH + nc * 8 + 2 * tg] = h23;
            }
            l0 = l0 * a0 + s0;
            l1 = l1 * a1 + s1;

            #pragma unroll
            for (int nc = 0; nc < 8; nc++) {
                O[nc][0] *= a0; O[nc][1] *= a0;
                O[nc][2] *= a1; O[nc][3] *= a1;
            }
            __syncwarp();

            // ---- O += P V (V frags via ldmatrix.trans) ----
            #pragma unroll
            for (int kc = 0; kc < 4; kc++) {
                uint32_t pa[4];
                pa[0] = *(const uint32_t*)&Ph[(r0 + g)     * PADH + kc * 16 + 2 * tg];
                pa[1] = *(const uint32_t*)&Ph[(r0 + g + 8) * PADH + kc * 16 + 2 * tg];
                pa[2] = *(const uint32_t*)&Ph[(r0 + g)     * PADH + kc * 16 + 8 + 2 * tg];
                pa[3] = *(const uint32_t*)&Ph[(r0 + g + 8) * PADH + kc * 16 + 8 + 2 * tg];
                const uint32_t va = vbase + (uint32_t)(kc * 16 * PADH) * 2;
                #pragma unroll
                for (int nc = 0; nc < 8; nc++) {
                    uint32_t b0, b1;
                    ldsm_x2_t(b0, b1, va + (uint32_t)(nc * 8) * 2);
                    mma16h(O[nc], pa, b0, b1);
                }
            }
            __syncwarp();
        }

        // every warp releases the stage (even if it skipped compute)
        if (lane == 0) MBAR_ARRIVE(mbE + 8 * s);
    }

    // ---- final l reduction, normalize, write fp16 ao ----
    l0 += __shfl_xor_sync(0xFFFFFFFF, l0, 1);
    l0 += __shfl_xor_sync(0xFFFFFFFF, l0, 2);
    l1 += __shfl_xor_sync(0xFFFFFFFF, l1, 1);
    l1 += __shfl_xor_sync(0xFFFFFFFF, l1, 2);
    const float inv0 = 1.f / l0;
    const float inv1 = 1.f / l1;
    __half* op0 = ao + (rowbase + (size_t)(qRowBase + g))     * DM + h * DH;
    __half* op1 = ao + (rowbase + (size_t)(qRowBase + g + 8)) * DM + h * DH;
    #pragma unroll
    for (int nc = 0; nc < 8; nc++) {
        *(__half2*)(op0 + nc * 8 + 2 * tg) =
            __floats2half2_rn(O[nc][0] * inv0, O[nc][1] * inv0);
        *(__half2*)(op1 + nc * 8 + 2 * tg) =
            __floats2half2_rn(O[nc][2] * inv1, O[nc][3] * inv1);
    }
}

// ---------------------------------------------------------------------------
extern "C" void kernel_launch(void* const* d_in, const int* in_sizes, int n_in,
                              void* d_out, int out_size)
{
    const float* x    = (const float*)d_in[0];   // [B,T,1024]
    const float* Wqkv = (const float*)d_in[1];   // [1024,3072]
    const float* Wout = (const float*)d_in[2];   // [1024,1024]
    float* out = (float*)d_out;

    __half *qkv, *ao, *xh, *wtq, *wto;
    cudaGetSymbolAddress((void**)&qkv, g_qkv);
    cudaGetSymbolAddress((void**)&ao,  g_ao);
    cudaGetSymbolAddress((void**)&xh,  g_xh);
    cudaGetSymbolAddress((void**)&wtq, g_wtq);
    cudaGetSymbolAddress((void**)&wto, g_wto);

    cudaFuncSetAttribute(gemm_h, cudaFuncAttributeMaxDynamicSharedMemorySize, G_SMEM);
    cudaFuncSetAttribute(flash_attn_h, cudaFuncAttributeMaxDynamicSharedMemorySize, FA_SMEM);

    // Prologue: x -> fp16; weights transposed -> fp16
    f32_to_f16<<<(BT * DM / 4 + 255) / 256, 256>>>((const float4*)x, (__half2*)xh, BT * DM / 4);
    transposeH<<<dim3(NQKV / 32, DM / 32), dim3(32, 8)>>>(Wqkv, wtq, DM, NQKV);
    transposeH<<<dim3(DM / 32, DM / 32), dim3(32, 8)>>>(Wout, wto, DM, DM);

    // 1) QKV projection (fp16 mma, fp16 output)
    gemm_h<<<dim3(NQKV / 128, BT / 128), 256, G_SMEM>>>(xh, wtq, nullptr, qkv, BT, NQKV, DM);

    // 2) Causal flash attention (mbarrier-pipelined, 128-row CTAs)
    flash_attn_h<<<dim3(TT / 128, BB * NH), 256, FA_SMEM>>>(qkv, ao);

    // 3) Output projection (fp16 mma, fp32 output)
    gemm_h<<<dim3(DM / 128, BT / 128), 256, G_SMEM>>>(ao, wto, out, nullptr, BT, DM, DM);
}

// round 15
// speedup vs baseline: 8.0512x; 1.0153x over previous
#include <cuda_runtime.h>
#include <cuda_fp16.h>
#include <math.h>
#include <stdint.h>

// Problem constants
#define BB      4
#define TT      2048
#define DM      1024
#define NH      16
#define DH      64
#define BT      (BB * TT)        // 8192 rows
#define NQKV    (3 * DM)         // 3072

// Scratch (alloc-free rule: __device__ globals)
__device__ __half g_qkv[(size_t)BT * NQKV];  // 50.3 MB (fp16)
__device__ __half g_ao [(size_t)BT * DM];    // 16.8 MB (fp16)
__device__ __half g_xh [(size_t)BT * DM];    // 16.8 MB (x in fp16)
__device__ __half g_wtq[(size_t)NQKV * DM];  //  6.3 MB (Wqkv^T fp16)
__device__ __half g_wto[(size_t)DM * DM];    //  2.1 MB (Wout^T fp16)

// ---------------------------------------------------------------------------
// Helpers
// ---------------------------------------------------------------------------
__device__ __forceinline__ uint32_t smem_u32(const void* p) {
    uint32_t a;
    asm("{ .reg .u64 t; cvta.to.shared.u64 t, %1; cvt.u32.u64 %0, t; }" : "=r"(a) : "l"(p));
    return a;
}

#define CP16(dst, src)  asm volatile("cp.async.cg.shared.global [%0], [%1], 16;" :: "r"(dst), "l"(src))
#define CP_COMMIT()     asm volatile("cp.async.commit_group;")
#define CP_WAIT(n)      asm volatile("cp.async.wait_group %0;" :: "n"(n))

#define MBAR_INIT(a, c) asm volatile("mbarrier.init.shared.b64 [%0], %1;" :: "r"(a), "r"(c) : "memory")
#define MBAR_ARRIVE(a)  asm volatile("mbarrier.arrive.shared::cta.b64 _, [%0];" :: "r"(a) : "memory")
#define CP_MBAR_ARR(a)  asm volatile("cp.async.mbarrier.arrive.noinc.shared::cta.b64 [%0];" :: "r"(a) : "memory")
#define MBAR_WAIT(a, ph) do { \
    uint32_t _m = (a), _p = (ph), _d; \
    asm volatile("{ .reg .pred p; mbarrier.try_wait.parity.acquire.cta.shared::cta.b64 p, [%1], %2; selp.b32 %0,1,0,p; }" \
        : "=r"(_d) : "r"(_m), "r"(_p) : "memory"); \
    if (!_d) { \
        asm volatile("{ .reg .pred P1;\nW%=:\nmbarrier.try_wait.parity.acquire.cta.shared::cta.b64 P1, [%0], %1, 0x989680;\n@P1 bra.uni D%=;\nbra.uni W%=;\nD%=:\n}" \
            :: "r"(_m), "r"(_p) : "memory"); \
    } } while (0)

// m16n8k16 fp16 mma, fp32 accumulate.
__device__ __forceinline__ void mma16h(float* d, const uint32_t* a, uint32_t b0, uint32_t b1) {
    asm volatile(
        "mma.sync.aligned.m16n8k16.row.col.f32.f16.f16.f32 "
        "{%0,%1,%2,%3}, {%4,%5,%6,%7}, {%8,%9}, {%0,%1,%2,%3};"
        : "+f"(d[0]), "+f"(d[1]), "+f"(d[2]), "+f"(d[3])
        : "r"(a[0]), "r"(a[1]), "r"(a[2]), "r"(a[3]), "r"(b0), "r"(b1));
}

__device__ __forceinline__ void ldsm_x4(uint32_t& r0, uint32_t& r1, uint32_t& r2, uint32_t& r3,
                                        uint32_t addr) {
    asm volatile("ldmatrix.sync.aligned.m8n8.x4.shared.b16 {%0,%1,%2,%3}, [%4];"
        : "=r"(r0), "=r"(r1), "=r"(r2), "=r"(r3) : "r"(addr));
}
__device__ __forceinline__ void ldsm_x4_t(uint32_t& r0, uint32_t& r1, uint32_t& r2, uint32_t& r3,
                                          uint32_t addr) {
    asm volatile("ldmatrix.sync.aligned.m8n8.x4.trans.shared.b16 {%0,%1,%2,%3}, [%4];"
        : "=r"(r0), "=r"(r1), "=r"(r2), "=r"(r3) : "r"(addr));
}

// ---------------------------------------------------------------------------
// fp16 tensor-core GEMM (93% of mma.sync issue floor — unchanged from R13)
// ---------------------------------------------------------------------------
#define GPAD  40
#define GASZ  (128 * GPAD * 2)
#define GSTG  (2 * GASZ)
#define G_SMEM (3 * GSTG)

__global__ __launch_bounds__(256, 2) void gemm_h(
    const __half* __restrict__ A, const __half* __restrict__ Bt,
    float* __restrict__ Cf, __half* __restrict__ Ch,
    int M, int N, int K)
{
    extern __shared__ char smem_g[];
    const uint32_t sbase = smem_u32(smem_g);

    const int tid  = threadIdx.x;
    const int lane = tid & 31;
    const int wid  = tid >> 5;
    const int wm   = (wid >> 1) * 32;
    const int wn   = (wid & 1) * 64;
    const int g    = lane >> 2;
    const int tg   = lane & 3;

    const int bx = blockIdx.x, by = blockIdx.y;

    const int lrow = tid >> 1;
    const int colb = (tid & 1) * 16;
    const uint32_t dOff = (uint32_t)(lrow * GPAD + colb) * 2;
    const __half* gA = A  + (size_t)(by * 128) * K;
    const __half* gB = Bt + (size_t)(bx * 128) * K;

    const int mi = lane >> 3, lr = lane & 7;
    const int aRow = lr + ((mi & 1) << 3);
    const int aCol = (mi & 2) << 2;
    const int bRow = lr + ((mi >> 1) << 3);
    const int bCol = (mi & 1) << 3;

    float acc[2][8][4];
    #pragma unroll
    for (int i = 0; i < 2; i++)
        #pragma unroll
        for (int j = 0; j < 8; j++)
            #pragma unroll
            for (int q = 0; q < 4; q++) acc[i][j][q] = 0.f;

    const int NC = K / 32;

    {
        const uint32_t dA0 = sbase + dOff;
        CP16(dA0,              gA + (size_t)lrow * K + colb);
        CP16(dA0 + 16,         gA + (size_t)lrow * K + colb + 8);
        CP16(dA0 + GASZ,       gB + (size_t)lrow * K + colb);
        CP16(dA0 + GASZ + 16,  gB + (size_t)lrow * K + colb + 8);
        CP_COMMIT();
        const uint32_t dA1 = sbase + GSTG + dOff;
        CP16(dA1,              gA + (size_t)lrow * K + 32 + colb);
        CP16(dA1 + 16,         gA + (size_t)lrow * K + 32 + colb + 8);
        CP16(dA1 + GASZ,       gB + (size_t)lrow * K + 32 + colb);
        CP16(dA1 + GASZ + 16,  gB + (size_t)lrow * K + 32 + colb + 8);
        CP_COMMIT();
    }

    for (int c = 0; c < NC; c++) {
        CP_WAIT(1);
        __syncthreads();
        if (c + 2 < NC) {
            const int k0 = (c + 2) * 32;
            const uint32_t dA = sbase + (uint32_t)((c + 2) % 3) * GSTG + dOff;
            CP16(dA,             gA + (size_t)lrow * K + k0 + colb);
            CP16(dA + 16,        gA + (size_t)lrow * K + k0 + colb + 8);
            CP16(dA + GASZ,      gB + (size_t)lrow * K + k0 + colb);
            CP16(dA + GASZ + 16, gB + (size_t)lrow * K + k0 + colb + 8);
        }
        CP_COMMIT();

        const uint32_t aoff = sbase + (uint32_t)(c % 3) * GSTG;
        const uint32_t boff = aoff + GASZ;
        #pragma unroll
        for (int ks = 0; ks < 2; ks++) {
            uint32_t a0[4], a1[4];
            ldsm_x4(a0[0], a0[1], a0[2], a0[3],
                    aoff + (uint32_t)((wm + aRow) * GPAD + ks * 16 + aCol) * 2);
            ldsm_x4(a1[0], a1[1], a1[2], a1[3],
                    aoff + (uint32_t)((wm + 16 + aRow) * GPAD + ks * 16 + aCol) * 2);
            uint32_t bb[8][2];
            #pragma unroll
            for (int ntp = 0; ntp < 4; ntp++) {
                uint32_t r0, r1, r2, r3;
                ldsm_x4(r0, r1, r2, r3,
                        boff + (uint32_t)((wn + ntp * 16 + bRow) * GPAD + ks * 16 + bCol) * 2);
                bb[2 * ntp][0] = r0; bb[2 * ntp][1] = r1;
                bb[2 * ntp + 1][0] = r2; bb[2 * ntp + 1][1] = r3;
            }
            #pragma unroll
            for (int nt = 0; nt < 8; nt++) {
                mma16h(acc[0][nt], a0, bb[nt][0], bb[nt][1]);
                mma16h(acc[1][nt], a1, bb[nt][0], bb[nt][1]);
            }
        }
    }

    #pragma unroll
    for (int mt = 0; mt < 2; mt++) {
        const size_t r0 = (size_t)(by * 128 + wm + mt * 16 + g);
        #pragma unroll
        for (int nt = 0; nt < 8; nt++) {
            const int col = bx * 128 + wn + nt * 8 + 2 * tg;
            if (Ch) {
                *(__half2*)(Ch + r0 * N + col) =
                    __floats2half2_rn(acc[mt][nt][0], acc[mt][nt][1]);
                *(__half2*)(Ch + (r0 + 8) * N + col) =
                    __floats2half2_rn(acc[mt][nt][2], acc[mt][nt][3]);
            } else {
                *(float2*)(Cf + r0 * N + col)       = make_float2(acc[mt][nt][0], acc[mt][nt][1]);
                *(float2*)(Cf + (r0 + 8) * N + col) = make_float2(acc[mt][nt][2], acc[mt][nt][3]);
            }
        }
    }
}

// ---------------------------------------------------------------------------
// Prologue kernels
// ---------------------------------------------------------------------------
__global__ void f32_to_f16(const float4* __restrict__ in, __half2* __restrict__ out, int n4)
{
    int i = blockIdx.x * blockDim.x + threadIdx.x;
    if (i < n4) {
        float4 v = in[i];
        out[2 * i]     = __floats2half2_rn(v.x, v.y);
        out[2 * i + 1] = __floats2half2_rn(v.z, v.w);
    }
}

__global__ void transposeH(const float* __restrict__ in, __half* __restrict__ out,
                           int rows, int cols)
{
    __shared__ float t[32][33];
    const int bx = blockIdx.x * 32, by = blockIdx.y * 32;
    #pragma unroll
    for (int i = threadIdx.y; i < 32; i += 8)
        t[i][threadIdx.x] = in[(size_t)(by + i) * cols + bx + threadIdx.x];
    __syncthreads();
    #pragma unroll
    for (int i = threadIdx.y; i < 32; i += 8)
        out[(size_t)(bx + i) * rows + by + threadIdx.x] = __float2half_rn(t[threadIdx.x][i]);
}

// ---------------------------------------------------------------------------
// fp16 flash attention (causal), mbarrier producer/consumer pipeline.
// grid: (T/128, B*NH), block 256 (8 warps), warp = 16 query rows.
// R15: K/P fragments via ldmatrix.x4, V via ldmatrix.x4.trans, and
// masked 16-key sub-blocks skipped on diagonal tiles (bit-identical math).
// ---------------------------------------------------------------------------
#define PADH 72
#define FA_S 4
#define FA_KSTG (64 * PADH * 2)                 // 9216 B per K (or V) stage
#define OFF_K   128
#define OFF_V   (OFF_K + FA_S * FA_KSTG)        // 36992
#define OFF_P   (OFF_V + FA_S * FA_KSTG)        // 73856
#define FA_SMEM (OFF_P + 128 * PADH * 2)        // 92288 B

__global__ __launch_bounds__(256, 2) void flash_attn_h(
    const __half* __restrict__ qkv, __half* __restrict__ ao)
{
    extern __shared__ char smf[];
    __half* Ph = (__half*)(smf + OFF_P);
    const uint32_t sb   = smem_u32(smf);
    const uint32_t ksb  = sb + OFF_K;
    const uint32_t vsb  = sb + OFF_V;
    const uint32_t phb  = sb + OFF_P;
    const uint32_t mbF  = sb;          // full[0..3]  at +0,8,16,24
    const uint32_t mbE  = sb + 32;     // empty[0..3] at +32..56

    const int qb2  = (gridDim.x - 1) - blockIdx.x;  // heavy blocks first
    const int bh   = blockIdx.y;
    const int b    = bh >> 4;
    const int h    = bh & 15;
    const int tid  = threadIdx.x;
    const int lane = tid & 31;
    const int wid  = tid >> 5;
    const int g    = lane >> 2;
    const int tg   = lane & 3;
    const int r0   = wid * 16;
    const int qRowBase = qb2 * 128 + r0;
    const size_t rowbase = (size_t)(b * TT);
    const int lastT = 2 * qb2 + 1;

    // ldmatrix per-lane offsets (same derivation as gemm_h, proven)
    const int mi = lane >> 3, lr = lane & 7;
    const int aRow = lr + ((mi & 1) << 3);
    const int aCol = (mi & 2) << 2;
    const int bRow = lr + ((mi >> 1) << 3);
    const int bCol = (mi & 1) << 3;

    if (tid == 0) {
        #pragma unroll
        for (int s = 0; s < FA_S; s++) {
            MBAR_INIT(mbF + 8 * s, 64);
            MBAR_INIT(mbE + 8 * s, 8);
        }
    }
    __syncthreads();

    // Producer source base: warp 0 -> K, warp 1 -> V
    const bool isProd = (wid < 2);
    const __half* psrc = qkv + rowbase * NQKV + DM + (size_t)wid * DM + h * DH;
    const uint32_t pbase = (wid == 0) ? ksb : vsb;

    // prologue: produce tiles 0..min(FA_S-1, lastT)
    if (isProd) {
        #pragma unroll
        for (int pt = 0; pt < FA_S; pt++) {
            if (pt <= lastT) {
                const __half* src = psrc + (size_t)(pt * 64) * NQKV;
                const uint32_t dstb = pbase + (uint32_t)pt * FA_KSTG;
                #pragma unroll
                for (int i = 0; i < 16; i++) {
                    int f = lane + i * 32;
                    int row = f >> 3;
                    int col = (f & 7) * 8;
                    CP16(dstb + (uint32_t)(row * PADH + col) * 2, src + (size_t)row * NQKV + col);
                }
                CP_MBAR_ARR(mbF + 8 * pt);
            }
        }
    }

    // Q fragments (x 0.125, exact in fp16)
    uint32_t qa[4][4];
    {
        const __half* qp = qkv + (rowbase + (size_t)qRowBase) * NQKV + h * DH;
        const __half2 sc = __floats2half2_rn(0.125f, 0.125f);
        #pragma unroll
        for (int kc = 0; kc < 4; kc++) {
            #pragma unroll
            for (int e = 0; e < 4; e++) {
                int dr = (e & 1) * 8;
                int dc = (e >> 1) * 8;
                __half2 v = *(const __half2*)(qp + (size_t)(g + dr) * NQKV + kc * 16 + dc + 2 * tg);
                v = __hmul2(v, sc);
                qa[kc][e] = *(const uint32_t*)&v;
            }
        }
    }

    float O[8][4];
    #pragma unroll
    for (int nc = 0; nc < 8; nc++)
        #pragma unroll
        for (int e = 0; e < 4; e++) O[nc][e] = 0.f;
    float m0 = -1e30f, m1 = -1e30f, l0 = 0.f, l1 = 0.f;

    // V ldmatrix.x4.trans per-lane address component:
    // rows = key (lane&15), col-halves = +8 for lanes 16-31 (second matrix pair)
    const uint32_t vLaneOff = (uint32_t)((lane & 15) * PADH + ((lane >> 4) & 1) * 8) * 2;

    for (int kb = 0; kb <= lastT; kb++) {
        const int s = kb & (FA_S - 1);

        // producers: refill stage (kb-1)%FA_S with tile kb+FA_S-1
        if (isProd && kb >= 1) {
            const int pt = kb + FA_S - 1;
            if (pt <= lastT) {
                const int ps = pt & (FA_S - 1);
                MBAR_WAIT(mbE + 8 * ps, (uint32_t)(((pt >> 2) - 1) & 1));
                const __half* src = psrc + (size_t)(pt * 64) * NQKV;
                const uint32_t dstb = pbase + (uint32_t)ps * FA_KSTG;
                #pragma unroll
                for (int i = 0; i < 16; i++) {
                    int f = lane + i * 32;
                    int row = f >> 3;
                    int col = (f & 7) * 8;
                    CP16(dstb + (uint32_t)(row * PADH + col) * 2, src + (size_t)row * NQKV + col);
                }
                CP_MBAR_ARR(mbF + 8 * ps);
            }
        }

        // consume tile kb
        MBAR_WAIT(mbF + 8 * s, (uint32_t)((kb >> 2) & 1));

        const int iloc = qRowBase - kb * 64;
        if (iloc > -16) {
            const uint32_t ksAddr = ksb + (uint32_t)s * FA_KSTG;
            const uint32_t vAddr  = vsb + (uint32_t)s * FA_KSTG + vLaneOff;

            // number of active 16-key chunks (warp-uniform)
            int ntpMax = ((iloc + 15) >> 4) + 1;
            if (ntpMax > 4) ntpMax = 4;

            // ---- S = (Q*scale) K^T : ldmatrix.x4 B-frags, skip masked chunks ----
            float Sc[8][4];
            #pragma unroll
            for (int nc = 0; nc < 8; nc++)
                #pragma unroll
                for (int e = 0; e < 4; e++) Sc[nc][e] = 0.f;

            #pragma unroll
            for (int kc = 0; kc < 4; kc++) {
                #pragma unroll
                for (int ntp = 0; ntp < 4; ntp++) {
                    if (ntp < ntpMax) {
                        uint32_t b0, b1, b2, b3;
                        ldsm_x4(b0, b1, b2, b3,
                                ksAddr + (uint32_t)((ntp * 16 + bRow) * PADH + kc * 16 + bCol) * 2);
                        mma16h(Sc[2 * ntp],     qa[kc], b0, b1);
                        mma16h(Sc[2 * ntp + 1], qa[kc], b2, b3);
                    }
                }
            }

            // ---- causal mask (diagonal-overlapping tiles) ----
            if (iloc < 63) {
                const int i0 = iloc + g, i1 = iloc + g + 8;
                #pragma unroll
                for (int nc = 0; nc < 8; nc++) {
                    int j = nc * 8 + 2 * tg;
                    if (j     > i0) Sc[nc][0] = -1e30f;
                    if (j + 1 > i0) Sc[nc][1] = -1e30f;
                    if (j     > i1) Sc[nc][2] = -1e30f;
                    if (j + 1 > i1) Sc[nc][3] = -1e30f;
                }
            }

            // ---- online softmax ----
            float rx0 = -1e30f, rx1 = -1e30f;
            #pragma unroll
            for (int nc = 0; nc < 8; nc++) {
                rx0 = fmaxf(rx0, fmaxf(Sc[nc][0], Sc[nc][1]));
                rx1 = fmaxf(rx1, fmaxf(Sc[nc][2], Sc[nc][3]));
            }
            rx0 = fmaxf(rx0, __shfl_xor_sync(0xFFFFFFFF, rx0, 1));
            rx0 = fmaxf(rx0, __shfl_xor_sync(0xFFFFFFFF, rx0, 2));
            rx1 = fmaxf(rx1, __shfl_xor_sync(0xFFFFFFFF, rx1, 1));
            rx1 = fmaxf(rx1, __shfl_xor_sync(0xFFFFFFFF, rx1, 2));

            const float mn0 = fmaxf(m0, rx0);
            const float mn1 = fmaxf(m1, rx1);
            const float a0 = __expf(m0 - mn0);
            const float a1 = __expf(m1 - mn1);
            m0 = mn0; m1 = mn1;

            float s0 = 0.f, s1 = 0.f;
            #pragma unroll
            for (int nc = 0; nc < 8; nc++) {
                __half2 h01 = __floats2half2_rn(__expf(Sc[nc][0] - mn0), __expf(Sc[nc][1] - mn0));
                __half2 h23 = __floats2half2_rn(__expf(Sc[nc][2] - mn1), __expf(Sc[nc][3] - mn1));
                s0 += __low2float(h01) + __high2float(h01);
                s1 += __low2float(h23) + __high2float(h23);
                *(__half2*)&Ph[(r0 + g)     * PADH + nc * 8 + 2 * tg] = h01;
                *(__half2*)&Ph[(r0 + g + 8) * PADH + nc * 8 + 2 * tg] = h23;
            }
            l0 = l0 * a0 + s0;
            l1 = l1 * a1 + s1;

            #pragma unroll
            for (int nc = 0; nc < 8; nc++) {
                O[nc][0] *= a0; O[nc][1] *= a0;
                O[nc][2] *= a1; O[nc][3] *= a1;
            }
            __syncwarp();

            // ---- O += P V : P via ldmatrix.x4, V via ldmatrix.x4.trans;
            //      skip key-chunks where P == 0 (masked) ----
            #pragma unroll
            for (int kc = 0; kc < 4; kc++) {
                if (kc < ntpMax) {
                    uint32_t pa[4];
                    ldsm_x4(pa[0], pa[1], pa[2], pa[3],
                            phb + (uint32_t)((r0 + aRow) * PADH + kc * 16 + aCol) * 2);
                    #pragma unroll
                    for (int ncp = 0; ncp < 4; ncp++) {
                        uint32_t b0, b1, b2, b3;
                        ldsm_x4_t(b0, b1, b2, b3,
                                  vAddr + (uint32_t)(kc * 16 * PADH + ncp * 16) * 2);
                        mma16h(O[2 * ncp],     pa, b0, b1);
                        mma16h(O[2 * ncp + 1], pa, b2, b3);
                    }
                }
            }
            __syncwarp();
        }

        // every warp releases the stage (even if it skipped compute)
        if (lane == 0) MBAR_ARRIVE(mbE + 8 * s);
    }

    // ---- final l reduction, normalize, write fp16 ao ----
    l0 += __shfl_xor_sync(0xFFFFFFFF, l0, 1);
    l0 += __shfl_xor_sync(0xFFFFFFFF, l0, 2);
    l1 += __shfl_xor_sync(0xFFFFFFFF, l1, 1);
    l1 += __shfl_xor_sync(0xFFFFFFFF, l1, 2);
    const float inv0 = 1.f / l0;
    const float inv1 = 1.f / l1;
    __half* op0 = ao + (rowbase + (size_t)(qRowBase + g))     * DM + h * DH;
    __half* op1 = ao + (rowbase + (size_t)(qRowBase + g + 8)) * DM + h * DH;
    #pragma unroll
    for (int nc = 0; nc < 8; nc++) {
        *(__half2*)(op0 + nc * 8 + 2 * tg) =
            __floats2half2_rn(O[nc][0] * inv0, O[nc][1] * inv0);
        *(__half2*)(op1 + nc * 8 + 2 * tg) =
            __floats2half2_rn(O[nc][2] * inv1, O[nc][3] * inv1);
    }
}

// ---------------------------------------------------------------------------
extern "C" void kernel_launch(void* const* d_in, const int* in_sizes, int n_in,
                              void* d_out, int out_size)
{
    const float* x    = (const float*)d_in[0];   // [B,T,1024]
    const float* Wqkv = (const float*)d_in[1];   // [1024,3072]
    const float* Wout = (const float*)d_in[2];   // [1024,1024]
    float* out = (float*)d_out;

    __half *qkv, *ao, *xh, *wtq, *wto;
    cudaGetSymbolAddress((void**)&qkv, g_qkv);
    cudaGetSymbolAddress((void**)&ao,  g_ao);
    cudaGetSymbolAddress((void**)&xh,  g_xh);
    cudaGetSymbolAddress((void**)&wtq, g_wtq);
    cudaGetSymbolAddress((void**)&wto, g_wto);

    cudaFuncSetAttribute(gemm_h, cudaFuncAttributeMaxDynamicSharedMemorySize, G_SMEM);
    cudaFuncSetAttribute(flash_attn_h, cudaFuncAttributeMaxDynamicSharedMemorySize, FA_SMEM);

    // Prologue: x -> fp16; weights transposed -> fp16
    f32_to_f16<<<(BT * DM / 4 + 255) / 256, 256>>>((const float4*)x, (__half2*)xh, BT * DM / 4);
    transposeH<<<dim3(NQKV / 32, DM / 32), dim3(32, 8)>>>(Wqkv, wtq, DM, NQKV);
    transposeH<<<dim3(DM / 32, DM / 32), dim3(32, 8)>>>(Wout, wto, DM, DM);

    // 1) QKV projection (fp16 mma, fp16 output)
    gemm_h<<<dim3(NQKV / 128, BT / 128), 256, G_SMEM>>>(xh, wtq, nullptr, qkv, BT, NQKV, DM);

    // 2) Causal flash attention (mbarrier-pipelined, ldmatrix fragments)
    flash_attn_h<<<dim3(TT / 128, BB * NH), 256, FA_SMEM>>>(qkv, ao);

    // 3) Output projection (fp16 mma, fp32 output)
    gemm_h<<<dim3(DM / 128, BT / 128), 256, G_SMEM>>>(ao, wto, out, nullptr, BT, DM, DM);
}

// round 16
// speedup vs baseline: 8.1204x; 1.0086x over previous
#include <cuda_runtime.h>
#include <cuda_fp16.h>
#include <math.h>
#include <stdint.h>

// Problem constants
#define BB      4
#define TT      2048
#define DM      1024
#define NH      16
#define DH      64
#define BT      (BB * TT)        // 8192 rows
#define NQKV    (3 * DM)         // 3072

// Scratch (alloc-free rule: __device__ globals)
__device__ __half g_qkv[(size_t)BT * NQKV];  // 50.3 MB (fp16)
__device__ __half g_ao [(size_t)BT * DM];    // 16.8 MB (fp16)
__device__ __half g_xh [(size_t)BT * DM];    // 16.8 MB (x in fp16)
__device__ __half g_wtq[(size_t)NQKV * DM];  //  6.3 MB (Wqkv^T fp16)
__device__ __half g_wto[(size_t)DM * DM];    //  2.1 MB (Wout^T fp16)

// ---------------------------------------------------------------------------
// Helpers
// ---------------------------------------------------------------------------
__device__ __forceinline__ uint32_t smem_u32(const void* p) {
    uint32_t a;
    asm("{ .reg .u64 t; cvta.to.shared.u64 t, %1; cvt.u32.u64 %0, t; }" : "=r"(a) : "l"(p));
    return a;
}

#define CP16(dst, src)  asm volatile("cp.async.cg.shared.global [%0], [%1], 16;" :: "r"(dst), "l"(src))
#define CP_COMMIT()     asm volatile("cp.async.commit_group;")
#define CP_WAIT(n)      asm volatile("cp.async.wait_group %0;" :: "n"(n))

#define MBAR_INIT(a, c) asm volatile("mbarrier.init.shared.b64 [%0], %1;" :: "r"(a), "r"(c) : "memory")
#define MBAR_ARRIVE(a)  asm volatile("mbarrier.arrive.shared::cta.b64 _, [%0];" :: "r"(a) : "memory")
#define CP_MBAR_ARR(a)  asm volatile("cp.async.mbarrier.arrive.noinc.shared::cta.b64 [%0];" :: "r"(a) : "memory")
#define MBAR_WAIT(a, ph) do { \
    uint32_t _m = (a), _p = (ph), _d; \
    asm volatile("{ .reg .pred p; mbarrier.try_wait.parity.acquire.cta.shared::cta.b64 p, [%1], %2; selp.b32 %0,1,0,p; }" \
        : "=r"(_d) : "r"(_m), "r"(_p) : "memory"); \
    if (!_d) { \
        asm volatile("{ .reg .pred P1;\nW%=:\nmbarrier.try_wait.parity.acquire.cta.shared::cta.b64 P1, [%0], %1, 0x989680;\n@P1 bra.uni D%=;\nbra.uni W%=;\nD%=:\n}" \
            :: "r"(_m), "r"(_p) : "memory"); \
    } } while (0)

// m16n8k16 fp16 mma, fp32 accumulate.
__device__ __forceinline__ void mma16h(float* d, const uint32_t* a, uint32_t b0, uint32_t b1) {
    asm volatile(
        "mma.sync.aligned.m16n8k16.row.col.f32.f16.f16.f32 "
        "{%0,%1,%2,%3}, {%4,%5,%6,%7}, {%8,%9}, {%0,%1,%2,%3};"
        : "+f"(d[0]), "+f"(d[1]), "+f"(d[2]), "+f"(d[3])
        : "r"(a[0]), "r"(a[1]), "r"(a[2]), "r"(a[3]), "r"(b0), "r"(b1));
}

__device__ __forceinline__ void ldsm_x4(uint32_t& r0, uint32_t& r1, uint32_t& r2, uint32_t& r3,
                                        uint32_t addr) {
    asm volatile("ldmatrix.sync.aligned.m8n8.x4.shared.b16 {%0,%1,%2,%3}, [%4];"
        : "=r"(r0), "=r"(r1), "=r"(r2), "=r"(r3) : "r"(addr));
}
__device__ __forceinline__ void ldsm_x4_t(uint32_t& r0, uint32_t& r1, uint32_t& r2, uint32_t& r3,
                                          uint32_t addr) {
    asm volatile("ldmatrix.sync.aligned.m8n8.x4.trans.shared.b16 {%0,%1,%2,%3}, [%4];"
        : "=r"(r0), "=r"(r1), "=r"(r2), "=r"(r3) : "r"(addr));
}

// ---------------------------------------------------------------------------
// fp16 tensor-core GEMM (93% of mma.sync issue floor — unchanged from R13)
// ---------------------------------------------------------------------------
#define GPAD  40
#define GASZ  (128 * GPAD * 2)
#define GSTG  (2 * GASZ)
#define G_SMEM (3 * GSTG)

__global__ __launch_bounds__(256, 2) void gemm_h(
    const __half* __restrict__ A, const __half* __restrict__ Bt,
    float* __restrict__ Cf, __half* __restrict__ Ch,
    int M, int N, int K)
{
    extern __shared__ char smem_g[];
    const uint32_t sbase = smem_u32(smem_g);

    const int tid  = threadIdx.x;
    const int lane = tid & 31;
    const int wid  = tid >> 5;
    const int wm   = (wid >> 1) * 32;
    const int wn   = (wid & 1) * 64;
    const int g    = lane >> 2;
    const int tg   = lane & 3;

    const int bx = blockIdx.x, by = blockIdx.y;

    const int lrow = tid >> 1;
    const int colb = (tid & 1) * 16;
    const uint32_t dOff = (uint32_t)(lrow * GPAD + colb) * 2;
    const __half* gA = A  + (size_t)(by * 128) * K;
    const __half* gB = Bt + (size_t)(bx * 128) * K;

    const int mi = lane >> 3, lr = lane & 7;
    const int aRow = lr + ((mi & 1) << 3);
    const int aCol = (mi & 2) << 2;
    const int bRow = lr + ((mi >> 1) << 3);
    const int bCol = (mi & 1) << 3;

    float acc[2][8][4];
    #pragma unroll
    for (int i = 0; i < 2; i++)
        #pragma unroll
        for (int j = 0; j < 8; j++)
            #pragma unroll
            for (int q = 0; q < 4; q++) acc[i][j][q] = 0.f;

    const int NC = K / 32;

    {
        const uint32_t dA0 = sbase + dOff;
        CP16(dA0,              gA + (size_t)lrow * K + colb);
        CP16(dA0 + 16,         gA + (size_t)lrow * K + colb + 8);
        CP16(dA0 + GASZ,       gB + (size_t)lrow * K + colb);
        CP16(dA0 + GASZ + 16,  gB + (size_t)lrow * K + colb + 8);
        CP_COMMIT();
        const uint32_t dA1 = sbase + GSTG + dOff;
        CP16(dA1,              gA + (size_t)lrow * K + 32 + colb);
        CP16(dA1 + 16,         gA + (size_t)lrow * K + 32 + colb + 8);
        CP16(dA1 + GASZ,       gB + (size_t)lrow * K + 32 + colb);
        CP16(dA1 + GASZ + 16,  gB + (size_t)lrow * K + 32 + colb + 8);
        CP_COMMIT();
    }

    for (int c = 0; c < NC; c++) {
        CP_WAIT(1);
        __syncthreads();
        if (c + 2 < NC) {
            const int k0 = (c + 2) * 32;
            const uint32_t dA = sbase + (uint32_t)((c + 2) % 3) * GSTG + dOff;
            CP16(dA,             gA + (size_t)lrow * K + k0 + colb);
            CP16(dA + 16,        gA + (size_t)lrow * K + k0 + colb + 8);
            CP16(dA + GASZ,      gB + (size_t)lrow * K + k0 + colb);
            CP16(dA + GASZ + 16, gB + (size_t)lrow * K + k0 + colb + 8);
        }
        CP_COMMIT();

        const uint32_t aoff = sbase + (uint32_t)(c % 3) * GSTG;
        const uint32_t boff = aoff + GASZ;
        #pragma unroll
        for (int ks = 0; ks < 2; ks++) {
            uint32_t a0[4], a1[4];
            ldsm_x4(a0[0], a0[1], a0[2], a0[3],
                    aoff + (uint32_t)((wm + aRow) * GPAD + ks * 16 + aCol) * 2);
            ldsm_x4(a1[0], a1[1], a1[2], a1[3],
                    aoff + (uint32_t)((wm + 16 + aRow) * GPAD + ks * 16 + aCol) * 2);
            uint32_t bb[8][2];
            #pragma unroll
            for (int ntp = 0; ntp < 4; ntp++) {
                uint32_t r0, r1, r2, r3;
                ldsm_x4(r0, r1, r2, r3,
                        boff + (uint32_t)((wn + ntp * 16 + bRow) * GPAD + ks * 16 + bCol) * 2);
                bb[2 * ntp][0] = r0; bb[2 * ntp][1] = r1;
                bb[2 * ntp + 1][0] = r2; bb[2 * ntp + 1][1] = r3;
            }
            #pragma unroll
            for (int nt = 0; nt < 8; nt++) {
                mma16h(acc[0][nt], a0, bb[nt][0], bb[nt][1]);
                mma16h(acc[1][nt], a1, bb[nt][0], bb[nt][1]);
            }
        }
    }

    #pragma unroll
    for (int mt = 0; mt < 2; mt++) {
        const size_t r0 = (size_t)(by * 128 + wm + mt * 16 + g);
        #pragma unroll
        for (int nt = 0; nt < 8; nt++) {
            const int col = bx * 128 + wn + nt * 8 + 2 * tg;
            if (Ch) {
                *(__half2*)(Ch + r0 * N + col) =
                    __floats2half2_rn(acc[mt][nt][0], acc[mt][nt][1]);
                *(__half2*)(Ch + (r0 + 8) * N + col) =
                    __floats2half2_rn(acc[mt][nt][2], acc[mt][nt][3]);
            } else {
                *(float2*)(Cf + r0 * N + col)       = make_float2(acc[mt][nt][0], acc[mt][nt][1]);
                *(float2*)(Cf + (r0 + 8) * N + col) = make_float2(acc[mt][nt][2], acc[mt][nt][3]);
            }
        }
    }
}

// ---------------------------------------------------------------------------
// Prologue kernels
// ---------------------------------------------------------------------------
__global__ void f32_to_f16(const float4* __restrict__ in, __half2* __restrict__ out, int n4)
{
    int i = blockIdx.x * blockDim.x + threadIdx.x;
    if (i < n4) {
        float4 v = in[i];
        out[2 * i]     = __floats2half2_rn(v.x, v.y);
        out[2 * i + 1] = __floats2half2_rn(v.z, v.w);
    }
}

__global__ void transposeH(const float* __restrict__ in, __half* __restrict__ out,
                           int rows, int cols)
{
    __shared__ float t[32][33];
    const int bx = blockIdx.x * 32, by = blockIdx.y * 32;
    #pragma unroll
    for (int i = threadIdx.y; i < 32; i += 8)
        t[i][threadIdx.x] = in[(size_t)(by + i) * cols + bx + threadIdx.x];
    __syncthreads();
    #pragma unroll
    for (int i = threadIdx.y; i < 32; i += 8)
        out[(size_t)(bx + i) * rows + by + threadIdx.x] = __float2half_rn(t[threadIdx.x][i]);
}

// ---------------------------------------------------------------------------
// fp16 flash attention (causal), mbarrier producer/consumer pipeline.
// grid: (T/128, B*NH), block 256 (8 warps), warp = 16 query rows.
// R16: P fragments built directly in registers (A-frag == C-frag layout for
// m16n8k16), no smem round-trip; O-rescale skipped when max unchanged.
// ---------------------------------------------------------------------------
#define PADH 72
#define FA_S 4
#define FA_KSTG (64 * PADH * 2)                 // 9216 B per K (or V) stage
#define OFF_K   128
#define OFF_V   (OFF_K + FA_S * FA_KSTG)        // 36992
#define FA_SMEM (OFF_V + FA_S * FA_KSTG)        // 73856 B

__global__ __launch_bounds__(256, 2) void flash_attn_h(
    const __half* __restrict__ qkv, __half* __restrict__ ao)
{
    extern __shared__ char smf[];
    const uint32_t sb   = smem_u32(smf);
    const uint32_t ksb  = sb + OFF_K;
    const uint32_t vsb  = sb + OFF_V;
    const uint32_t mbF  = sb;          // full[0..3]  at +0,8,16,24
    const uint32_t mbE  = sb + 32;     // empty[0..3] at +32..56

    const int qb2  = (gridDim.x - 1) - blockIdx.x;  // heavy blocks first
    const int bh   = blockIdx.y;
    const int b    = bh >> 4;
    const int h    = bh & 15;
    const int tid  = threadIdx.x;
    const int lane = tid & 31;
    const int wid  = tid >> 5;
    const int g    = lane >> 2;
    const int tg   = lane & 3;
    const int r0   = wid * 16;
    const int qRowBase = qb2 * 128 + r0;
    const size_t rowbase = (size_t)(b * TT);
    const int lastT = 2 * qb2 + 1;

    // ldmatrix B-fragment per-lane offsets (K tiles)
    const int mi = lane >> 3, lr = lane & 7;
    const int bRow = lr + ((mi >> 1) << 3);
    const int bCol = (mi & 1) << 3;

    if (tid == 0) {
        #pragma unroll
        for (int s = 0; s < FA_S; s++) {
            MBAR_INIT(mbF + 8 * s, 64);
            MBAR_INIT(mbE + 8 * s, 8);
        }
    }
    __syncthreads();

    // Producer source base: warp 0 -> K, warp 1 -> V
    const bool isProd = (wid < 2);
    const __half* psrc = qkv + rowbase * NQKV + DM + (size_t)wid * DM + h * DH;
    const uint32_t pbase = (wid == 0) ? ksb : vsb;

    // prologue: produce tiles 0..min(FA_S-1, lastT)
    if (isProd) {
        #pragma unroll
        for (int pt = 0; pt < FA_S; pt++) {
            if (pt <= lastT) {
                const __half* src = psrc + (size_t)(pt * 64) * NQKV;
                const uint32_t dstb = pbase + (uint32_t)pt * FA_KSTG;
                #pragma unroll
                for (int i = 0; i < 16; i++) {
                    int f = lane + i * 32;
                    int row = f >> 3;
                    int col = (f & 7) * 8;
                    CP16(dstb + (uint32_t)(row * PADH + col) * 2, src + (size_t)row * NQKV + col);
                }
                CP_MBAR_ARR(mbF + 8 * pt);
            }
        }
    }

    // Q fragments (x 0.125, exact in fp16)
    uint32_t qa[4][4];
    {
        const __half* qp = qkv + (rowbase + (size_t)qRowBase) * NQKV + h * DH;
        const __half2 sc = __floats2half2_rn(0.125f, 0.125f);
        #pragma unroll
        for (int kc = 0; kc < 4; kc++) {
            #pragma unroll
            for (int e = 0; e < 4; e++) {
                int dr = (e & 1) * 8;
                int dc = (e >> 1) * 8;
                __half2 v = *(const __half2*)(qp + (size_t)(g + dr) * NQKV + kc * 16 + dc + 2 * tg);
                v = __hmul2(v, sc);
                qa[kc][e] = *(const uint32_t*)&v;
            }
        }
    }

    float O[8][4];
    #pragma unroll
    for (int nc = 0; nc < 8; nc++)
        #pragma unroll
        for (int e = 0; e < 4; e++) O[nc][e] = 0.f;
    float m0 = -1e30f, m1 = -1e30f, l0 = 0.f, l1 = 0.f;

    // V ldmatrix.x4.trans per-lane address component
    const uint32_t vLaneOff = (uint32_t)((lane & 15) * PADH + ((lane >> 4) & 1) * 8) * 2;

    for (int kb = 0; kb <= lastT; kb++) {
        const int s = kb & (FA_S - 1);

        // producers: refill stage with tile kb+FA_S-1
        if (isProd && kb >= 1) {
            const int pt = kb + FA_S - 1;
            if (pt <= lastT) {
                const int ps = pt & (FA_S - 1);
                MBAR_WAIT(mbE + 8 * ps, (uint32_t)(((pt >> 2) - 1) & 1));
                const __half* src = psrc + (size_t)(pt * 64) * NQKV;
                const uint32_t dstb = pbase + (uint32_t)ps * FA_KSTG;
                #pragma unroll
                for (int i = 0; i < 16; i++) {
                    int f = lane + i * 32;
                    int row = f >> 3;
                    int col = (f & 7) * 8;
                    CP16(dstb + (uint32_t)(row * PADH + col) * 2, src + (size_t)row * NQKV + col);
                }
                CP_MBAR_ARR(mbF + 8 * ps);
            }
        }

        // consume tile kb
        MBAR_WAIT(mbF + 8 * s, (uint32_t)((kb >> 2) & 1));

        const int iloc = qRowBase - kb * 64;
        if (iloc > -16) {
            const uint32_t ksAddr = ksb + (uint32_t)s * FA_KSTG;
            const uint32_t vAddr  = vsb + (uint32_t)s * FA_KSTG + vLaneOff;

            // number of active 16-key chunks (warp-uniform)
            int ntpMax = ((iloc + 15) >> 4) + 1;
            if (ntpMax > 4) ntpMax = 4;

            // ---- S = (Q*scale) K^T ----
            float Sc[8][4];
            #pragma unroll
            for (int nc = 0; nc < 8; nc++)
                #pragma unroll
                for (int e = 0; e < 4; e++) Sc[nc][e] = 0.f;

            #pragma unroll
            for (int kc = 0; kc < 4; kc++) {
                #pragma unroll
                for (int ntp = 0; ntp < 4; ntp++) {
                    if (ntp < ntpMax) {
                        uint32_t b0, b1, b2, b3;
                        ldsm_x4(b0, b1, b2, b3,
                                ksAddr + (uint32_t)((ntp * 16 + bRow) * PADH + kc * 16 + bCol) * 2);
                        mma16h(Sc[2 * ntp],     qa[kc], b0, b1);
                        mma16h(Sc[2 * ntp + 1], qa[kc], b2, b3);
                    }
                }
            }

            // ---- causal mask (diagonal-overlapping tiles) ----
            if (iloc < 63) {
                const int i0 = iloc + g, i1 = iloc + g + 8;
                #pragma unroll
                for (int nc = 0; nc < 8; nc++) {
                    int j = nc * 8 + 2 * tg;
                    if (j     > i0) Sc[nc][0] = -1e30f;
                    if (j + 1 > i0) Sc[nc][1] = -1e30f;
                    if (j     > i1) Sc[nc][2] = -1e30f;
                    if (j + 1 > i1) Sc[nc][3] = -1e30f;
                }
            }

            // ---- online softmax ----
            float rx0 = -1e30f, rx1 = -1e30f;
            #pragma unroll
            for (int nc = 0; nc < 8; nc++) {
                rx0 = fmaxf(rx0, fmaxf(Sc[nc][0], Sc[nc][1]));
                rx1 = fmaxf(rx1, fmaxf(Sc[nc][2], Sc[nc][3]));
            }
            rx0 = fmaxf(rx0, __shfl_xor_sync(0xFFFFFFFF, rx0, 1));
            rx0 = fmaxf(rx0, __shfl_xor_sync(0xFFFFFFFF, rx0, 2));
            rx1 = fmaxf(rx1, __shfl_xor_sync(0xFFFFFFFF, rx1, 1));
            rx1 = fmaxf(rx1, __shfl_xor_sync(0xFFFFFFFF, rx1, 2));

            const float mn0 = fmaxf(m0, rx0);
            const float mn1 = fmaxf(m1, rx1);
            const float a0 = __expf(m0 - mn0);
            const float a1 = __expf(m1 - mn1);
            m0 = mn0; m1 = mn1;

            // exp -> fp16 P kept in registers (A-frag == C-frag layout)
            uint32_t p01[8], p23[8];
            float s0 = 0.f, s1 = 0.f;
            #pragma unroll
            for (int nc = 0; nc < 8; nc++) {
                __half2 h01 = __floats2half2_rn(__expf(Sc[nc][0] - mn0), __expf(Sc[nc][1] - mn0));
                __half2 h23 = __floats2half2_rn(__expf(Sc[nc][2] - mn1), __expf(Sc[nc][3] - mn1));
                s0 += __low2float(h01) + __high2float(h01);
                s1 += __low2float(h23) + __high2float(h23);
                p01[nc] = *(const uint32_t*)&h01;
                p23[nc] = *(const uint32_t*)&h23;
            }
            l0 = l0 * a0 + s0;
            l1 = l1 * a1 + s1;

            // skip O-rescale when max unchanged (x1.0 is an fp32 identity)
            if (!__all_sync(0xFFFFFFFF, (a0 == 1.f) && (a1 == 1.f))) {
                #pragma unroll
                for (int nc = 0; nc < 8; nc++) {
                    O[nc][0] *= a0; O[nc][1] *= a0;
                    O[nc][2] *= a1; O[nc][3] *= a1;
                }
            }

            // ---- O += P V : P frags from registers, V via ldmatrix.x4.trans ----
            #pragma unroll
            for (int kc = 0; kc < 4; kc++) {
                if (kc < ntpMax) {
                    uint32_t pa[4];
                    pa[0] = p01[2 * kc];
                    pa[1] = p23[2 * kc];
                    pa[2] = p01[2 * kc + 1];
                    pa[3] = p23[2 * kc + 1];
                    #pragma unroll
                    for (int ncp = 0; ncp < 4; ncp++) {
                        uint32_t b0, b1, b2, b3;
                        ldsm_x4_t(b0, b1, b2, b3,
                                  vAddr + (uint32_t)(kc * 16 * PADH + ncp * 16) * 2);
                        mma16h(O[2 * ncp],     pa, b0, b1);
                        mma16h(O[2 * ncp + 1], pa, b2, b3);
                    }
                }
            }
        }

        // every warp releases the stage (even if it skipped compute)
        if (lane == 0) MBAR_ARRIVE(mbE + 8 * s);
    }

    // ---- final l reduction, normalize, write fp16 ao ----
    l0 += __shfl_xor_sync(0xFFFFFFFF, l0, 1);
    l0 += __shfl_xor_sync(0xFFFFFFFF, l0, 2);
    l1 += __shfl_xor_sync(0xFFFFFFFF, l1, 1);
    l1 += __shfl_xor_sync(0xFFFFFFFF, l1, 2);
    const float inv0 = 1.f / l0;
    const float inv1 = 1.f / l1;
    __half* op0 = ao + (rowbase + (size_t)(qRowBase + g))     * DM + h * DH;
    __half* op1 = ao + (rowbase + (size_t)(qRowBase + g + 8)) * DM + h * DH;
    #pragma unroll
    for (int nc = 0; nc < 8; nc++) {
        *(__half2*)(op0 + nc * 8 + 2 * tg) =
            __floats2half2_rn(O[nc][0] * inv0, O[nc][1] * inv0);
        *(__half2*)(op1 + nc * 8 + 2 * tg) =
            __floats2half2_rn(O[nc][2] * inv1, O[nc][3] * inv1);
    }
}

// ---------------------------------------------------------------------------
extern "C" void kernel_launch(void* const* d_in, const int* in_sizes, int n_in,
                              void* d_out, int out_size)
{
    const float* x    = (const float*)d_in[0];   // [B,T,1024]
    const float* Wqkv = (const float*)d_in[1];   // [1024,3072]
    const float* Wout = (const float*)d_in[2];   // [1024,1024]
    float* out = (float*)d_out;

    __half *qkv, *ao, *xh, *wtq, *wto;
    cudaGetSymbolAddress((void**)&qkv, g_qkv);
    cudaGetSymbolAddress((void**)&ao,  g_ao);
    cudaGetSymbolAddress((void**)&xh,  g_xh);
    cudaGetSymbolAddress((void**)&wtq, g_wtq);
    cudaGetSymbolAddress((void**)&wto, g_wto);

    cudaFuncSetAttribute(gemm_h, cudaFuncAttributeMaxDynamicSharedMemorySize, G_SMEM);
    cudaFuncSetAttribute(flash_attn_h, cudaFuncAttributeMaxDynamicSharedMemorySize, FA_SMEM);

    // Prologue: x -> fp16; weights transposed -> fp16
    f32_to_f16<<<(BT * DM / 4 + 255) / 256, 256>>>((const float4*)x, (__half2*)xh, BT * DM / 4);
    transposeH<<<dim3(NQKV / 32, DM / 32), dim3(32, 8)>>>(Wqkv, wtq, DM, NQKV);
    transposeH<<<dim3(DM / 32, DM / 32), dim3(32, 8)>>>(Wout, wto, DM, DM);

    // 1) QKV projection (fp16 mma, fp16 output)
    gemm_h<<<dim3(NQKV / 128, BT / 128), 256, G_SMEM>>>(xh, wtq, nullptr, qkv, BT, NQKV, DM);

    // 2) Causal flash attention (mbarrier-pipelined, register P fragments)
    flash_attn_h<<<dim3(TT / 128, BB * NH), 256, FA_SMEM>>>(qkv, ao);

    // 3) Output projection (fp16 mma, fp32 output)
    gemm_h<<<dim3(DM / 128, BT / 128), 256, G_SMEM>>>(ao, wto, out, nullptr, BT, DM, DM);
}